// round 1
// baseline (speedup 1.0000x reference)
#include <cuda_runtime.h>
#include <math.h>

typedef unsigned long long u64;

#define NPIX  65536   // 256*256
#define BATCH 4
#define CCH   64

// ---------------- scratch (device globals: allocation is forbidden) -----------
__device__ float g_t[(size_t)BATCH * 256 * NPIX];     // 256 MB : t = w_in @ x
__device__ float g_qv[(size_t)BATCH * 128 * NPIX];    // 128 MB : q (0..63), v (64..127)
__device__ float g_sumsq[BATCH * 128];                // per-channel sum of squares (q then v)
__device__ float g_gram[BATCH * 64 * 64];             // raw gram q.v
__device__ float g_M[BATCH * 64 * 64];                // M = w_out @ attn

// ---------------- f32x2 helpers (packed fp32 FMA, sm_100+) -------------------
__device__ __forceinline__ u64 ffma2(u64 a, u64 b, u64 c) {
    u64 d;
    asm("fma.rn.f32x2 %0, %1, %2, %3;" : "=l"(d) : "l"(a), "l"(b), "l"(c));
    return d;
}
__device__ __forceinline__ u64 pack2(float x, float y) {
    u64 d;
    asm("mov.b64 %0, {%1, %2};" : "=l"(d) : "f"(x), "f"(y));
    return d;
}

// ---------------- zero the accumulators --------------------------------------
__global__ void zero_stats() {
    for (int i = threadIdx.x; i < BATCH * 128 + BATCH * 64 * 64; i += blockDim.x) {
        if (i < BATCH * 128) g_sumsq[i] = 0.f;
        else                 g_gram[i - BATCH * 128] = 0.f;
    }
}

// ---------------- K=64 GEMM: Y[b,o,p] = sum_c W[b,o,c] * X[b,c,p] ------------
// block: 256 threads, tile = 64 outputs x 128 pixels. Thread = 4 outputs x 4 pixel-pairs.
// grid: (NPIX/128, O/64, BATCH)
__global__ __launch_bounds__(256) void gemm_k64(
    const float* __restrict__ W, size_t wBatch,
    const float* __restrict__ X, size_t xBatch,
    float* __restrict__ Y, size_t yBatch)
{
    __shared__ u64   xs2[16 * 64];      // 16 ch x 64 pixel-pairs
    __shared__ float ws[16 * 65];       // 16 ch x 64 outputs (pad 65 vs bank conflicts)
    float* xsf = (float*)xs2;

    const int tid = threadIdx.x;
    const int tp = tid & 15;            // pixel-pair group
    const int to = tid >> 4;            // output group
    const int b = blockIdx.z;
    const int pbase = blockIdx.x * 128;
    const int obase = blockIdx.y * 64;

    const float* Wb = W + (size_t)b * wBatch + (size_t)obase * 64;
    const float* Xb = X + (size_t)b * xBatch;
    float*       Yb = Y + (size_t)b * yBatch + (size_t)obase * NPIX;

    u64 acc[4][4];
#pragma unroll
    for (int j = 0; j < 4; ++j)
#pragma unroll
        for (int k = 0; k < 4; ++k) acc[j][k] = 0ULL;

    for (int cc = 0; cc < 64; cc += 16) {
        __syncthreads();
        // stage 16 channels x 128 pixels of X
        for (int e = tid; e < 2048; e += 256) {
            int ch = e >> 7, px = e & 127;
            xsf[ch * 128 + px] = Xb[(size_t)(cc + ch) * NPIX + pbase + px];
        }
        // stage 64 outputs x 16 channels of W, transposed to [c][o]
        for (int e = tid; e < 1024; e += 256) {
            int o = e >> 4, cl = e & 15;
            ws[cl * 65 + o] = Wb[(size_t)o * 64 + cc + cl];
        }
        __syncthreads();
#pragma unroll
        for (int c = 0; c < 16; ++c) {
            const u64* xr = xs2 + c * 64 + tp;
            u64 xv0 = xr[0], xv1 = xr[16], xv2 = xr[32], xv3 = xr[48];
            const float* wr = ws + c * 65 + to;
#pragma unroll
            for (int j = 0; j < 4; ++j) {
                float wv = wr[16 * j];
                u64 w2 = pack2(wv, wv);
                acc[j][0] = ffma2(w2, xv0, acc[j][0]);
                acc[j][1] = ffma2(w2, xv1, acc[j][1]);
                acc[j][2] = ffma2(w2, xv2, acc[j][2]);
                acc[j][3] = ffma2(w2, xv3, acc[j][3]);
            }
        }
    }
#pragma unroll
    for (int j = 0; j < 4; ++j) {
        float* yp = Yb + (size_t)(to + 16 * j) * NPIX + pbase + tp * 2;
#pragma unroll
        for (int k = 0; k < 4; ++k)
            *reinterpret_cast<u64*>(yp + 32 * k) = acc[j][k];
    }
}

// ---------------- depthwise 3x3 conv (SAME, zero pad) + gate -----------------
// qv[b,jj,p] = (w_dw[jj] * t[b,jj, 3x3 nbhd])  *  t[b,128+jj,p]
// grid: (256/4 rows, 128 ch, BATCH), block 256 (one thread per column)
__global__ __launch_bounds__(256) void conv_mul(const float* __restrict__ w_dw)
{
    __shared__ float st[6][258];
    const int col = threadIdx.x;
    const int jj = blockIdx.y, b = blockIdx.z, r0 = blockIdx.x * 4;

    const float* t1 = g_t + ((size_t)b * 256 + jj) * NPIX;
    const float* t2 = g_t + ((size_t)b * 256 + 128 + jj) * NPIX;
    float* outp = g_qv + ((size_t)b * 128 + jj) * NPIX;

    float wd[9];
#pragma unroll
    for (int i = 0; i < 9; ++i) wd[i] = w_dw[jj * 9 + i];

#pragma unroll
    for (int rr = 0; rr < 6; ++rr) {
        int row = r0 - 1 + rr;
        st[rr][col + 1] = (row >= 0 && row < 256) ? t1[row * 256 + col] : 0.f;
    }
    if (col == 0) {
#pragma unroll
        for (int rr = 0; rr < 6; ++rr) { st[rr][0] = 0.f; st[rr][257] = 0.f; }
    }
    __syncthreads();

#pragma unroll
    for (int r = 0; r < 4; ++r) {
        float s = 0.f;
#pragma unroll
        for (int ky = 0; ky < 3; ++ky)
#pragma unroll
            for (int kx = 0; kx < 3; ++kx)
                s += wd[ky * 3 + kx] * st[r + ky][col + kx];
        int p = (r0 + r) * 256 + col;
        outp[p] = s * t2[p];
    }
}

// ---------------- gram + sumsq ------------------------------------------------
// G[b,cq,cv] += sum_p q[cq,p]*v[cv,p]; sumsq accumulated per channel.
// grid: (128 chunk-strides, BATCH), block 256; thread tile 4x4 (cq,cv).
__global__ __launch_bounds__(256) void gram_kernel()
{
    __shared__ float qs[64 * 65];   // [px][ch], pad 65
    __shared__ float vs[64 * 65];
    const int tid = threadIdx.x;
    const int b = blockIdx.y;
    const int tv = tid & 15, tq = tid >> 4;
    const int cqs = tid & 63, pg = tid >> 6;

    const float* qsrc = g_qv + (size_t)b * 128 * NPIX;
    const float* vsrc = qsrc + (size_t)64 * NPIX;

    float acc[4][4];
#pragma unroll
    for (int i = 0; i < 4; ++i)
#pragma unroll
        for (int j = 0; j < 4; ++j) acc[i][j] = 0.f;
    float ssq = 0.f, ssv = 0.f;

    for (int chunk = blockIdx.x; chunk < 1024; chunk += gridDim.x) {
        int pbase = chunk * 64;
        __syncthreads();
        for (int e = tid; e < 4096; e += 256) {
            int ch = e >> 6, px = e & 63;
            qs[px * 65 + ch] = qsrc[(size_t)ch * NPIX + pbase + px];
            vs[px * 65 + ch] = vsrc[(size_t)ch * NPIX + pbase + px];
        }
        __syncthreads();
        // per-channel sum of squares (thread owns channel cqs, 16 pixels)
#pragma unroll 4
        for (int p = pg * 16; p < pg * 16 + 16; ++p) {
            float a = qs[p * 65 + cqs]; ssq += a * a;
            float c = vs[p * 65 + cqs]; ssv += c * c;
        }
        // gram outer products
        for (int p = 0; p < 64; ++p) {
            float qv_[4], vv_[4];
#pragma unroll
            for (int i = 0; i < 4; ++i) qv_[i] = qs[p * 65 + tq * 4 + i];
#pragma unroll
            for (int j = 0; j < 4; ++j) vv_[j] = vs[p * 65 + tv * 4 + j];
#pragma unroll
            for (int i = 0; i < 4; ++i)
#pragma unroll
                for (int j = 0; j < 4; ++j) acc[i][j] += qv_[i] * vv_[j];
        }
    }
    atomicAdd(&g_sumsq[b * 128 + cqs], ssq);
    atomicAdd(&g_sumsq[b * 128 + 64 + cqs], ssv);
#pragma unroll
    for (int i = 0; i < 4; ++i)
#pragma unroll
        for (int j = 0; j < 4; ++j)
            atomicAdd(&g_gram[b * 4096 + (tq * 4 + i) * 64 + tv * 4 + j], acc[i][j]);
}

// ---------------- norms + softmax + M = w_out @ attn (tiny) ------------------
__global__ __launch_bounds__(256) void attn_kernel(
    const float* __restrict__ w_out, const float* __restrict__ temp_p)
{
    __shared__ float attn_s[64 * 65];
    __shared__ float wo_s[64 * 65];
    __shared__ float nrm[128];
    const int tid = threadIdx.x, b = blockIdx.x;

    if (tid < 128) nrm[tid] = fmaxf(sqrtf(g_sumsq[b * 128 + tid]), 1e-12f);
    for (int e = tid; e < 4096; e += 256) {
        int o = e >> 6, c = e & 63;
        wo_s[c * 65 + o] = w_out[e];    // transposed [c][o]
    }
    __syncthreads();

    const float temp = *temp_p;
    if (tid < 64) {
        int c = tid;
        float inq = temp / nrm[c];
        float mx = -1e30f;
        for (int d = 0; d < 64; ++d) {
            float l = g_gram[b * 4096 + c * 64 + d] * (inq / nrm[64 + d]);
            attn_s[c * 65 + d] = l;
            mx = fmaxf(mx, l);
        }
        float sum = 0.f;
        for (int d = 0; d < 64; ++d) {
            float e_ = expf(attn_s[c * 65 + d] - mx);
            attn_s[c * 65 + d] = e_;
            sum += e_;
        }
        float inv = 1.f / sum;
        for (int d = 0; d < 64; ++d) attn_s[c * 65 + d] *= inv;
    }
    __syncthreads();

    const int o = tid & 63, dg = tid >> 6;
    for (int d = dg * 16; d < dg * 16 + 16; ++d) {
        float m = 0.f;
#pragma unroll 8
        for (int c2 = 0; c2 < 64; ++c2) m += wo_s[c2 * 65 + o] * attn_s[c2 * 65 + d];
        g_M[b * 4096 + o * 64 + d] = m;
    }
}

// ---------------- launch ------------------------------------------------------
extern "C" void kernel_launch(void* const* d_in, const int* in_sizes, int n_in,
                              void* d_out, int out_size)
{
    const float* x      = (const float*)d_in[0];
    const float* w_in   = (const float*)d_in[1];
    const float* w_dw   = (const float*)d_in[2];
    const float* w_out  = (const float*)d_in[3];
    const float* temp   = (const float*)d_in[4];
    float* out = (float*)d_out;

    float *t_ptr = nullptr, *qv_ptr = nullptr, *M_ptr = nullptr;
    cudaGetSymbolAddress((void**)&t_ptr,  g_t);
    cudaGetSymbolAddress((void**)&qv_ptr, g_qv);
    cudaGetSymbolAddress((void**)&M_ptr,  g_M);

    zero_stats<<<1, 256>>>();

    // t = w_in @ x   (O=256)
    gemm_k64<<<dim3(NPIX / 128, 4, BATCH), 256>>>(
        w_in, 0, x, (size_t)64 * NPIX, t_ptr, (size_t)256 * NPIX);

    // depthwise conv + gate -> qv
    conv_mul<<<dim3(64, 128, BATCH), 256>>>(w_dw);

    // gram + sumsq
    gram_kernel<<<dim3(128, BATCH), 256>>>();

    // norms, softmax, M = w_out @ attn
    attn_kernel<<<BATCH, 256>>>(w_out, temp);

    // out = M @ v   (O=64, X = v channels)
    gemm_k64<<<dim3(NPIX / 128, 1, BATCH), 256>>>(
        M_ptr, 4096, qv_ptr + (size_t)64 * NPIX, (size_t)128 * NPIX,
        out, (size_t)64 * NPIX);
}

// round 2
// speedup vs baseline: 1.0032x; 1.0032x over previous
#include <cuda_runtime.h>
#include <math.h>

typedef unsigned long long u64;

#define NPIX  65536   // 256*256
#define BATCH 4

// ---------------- scratch (device globals: allocation is forbidden) -----------
__device__ float g_t[(size_t)BATCH * 256 * NPIX];     // 256 MB : t = w_in @ x
__device__ float g_qv[(size_t)BATCH * 128 * NPIX];    // 128 MB : q (0..63), v (64..127)
__device__ float g_sumsq[BATCH * 128];                // per-channel sum of squares (q then v)
__device__ float g_gram[BATCH * 64 * 64];             // raw gram q.v
__device__ float g_M[BATCH * 64 * 64];                // M = w_out @ attn

// ---------------- f32x2 helpers (packed fp32 FMA, sm_100+) -------------------
__device__ __forceinline__ u64 ffma2(u64 a, u64 b, u64 c) {
    u64 d;
    asm("fma.rn.f32x2 %0, %1, %2, %3;" : "=l"(d) : "l"(a), "l"(b), "l"(c));
    return d;
}
__device__ __forceinline__ u64 pack2(float x, float y) {
    u64 d;
    asm("mov.b64 %0, {%1, %2};" : "=l"(d) : "f"(x), "f"(y));
    return d;
}
__device__ __forceinline__ void unpack2(u64 v, float& x, float& y) {
    asm("mov.b64 {%0, %1}, %2;" : "=f"(x), "=f"(y) : "l"(v));
}

// ---------------- zero the accumulators --------------------------------------
__global__ void zero_stats() {
    for (int i = threadIdx.x; i < BATCH * 128 + BATCH * 64 * 64; i += blockDim.x) {
        if (i < BATCH * 128) g_sumsq[i] = 0.f;
        else                 g_gram[i - BATCH * 128] = 0.f;
    }
}

// ---------------- K=64 GEMM: Y[b,o,p] = sum_c W[b,o,c] * X[b,c,p] ------------
// block 256 threads; tile = 64 outputs x 512 pixels (256 pixel-pairs).
// thread = 8 outputs x 8 pixel-pairs (u64 accum, f32x2 FMA).
// grid: (NPIX/512, O/64, BATCH)
__global__ __launch_bounds__(256) void gemm_k64(
    const float* __restrict__ W, size_t wBatch,
    const float* __restrict__ X, size_t xBatch,
    float* __restrict__ Y, size_t yBatch)
{
    __shared__ u64 xs2[16 * 256];   // 16 ch x 256 pixel-pairs (32 KB)
    __shared__ u64 ws2[16 * 64];    // 16 ch x 64 outputs, (w,w) packed (8 KB)
    float* xsf = (float*)xs2;

    const int tid = threadIdx.x;
    const int tp = tid & 31;         // pixel-pair group (8 pairs, stride 32)
    const int to = tid >> 5;         // output group (8 outputs)
    const int b = blockIdx.z;
    const int pbase = blockIdx.x * 512;
    const int obase = blockIdx.y * 64;

    const float* Wb = W + (size_t)b * wBatch + (size_t)obase * 64;
    const float* Xb = X + (size_t)b * xBatch;
    float*       Yb = Y + (size_t)b * yBatch + (size_t)obase * NPIX;

    u64 acc[8][8];
#pragma unroll
    for (int j = 0; j < 8; ++j)
#pragma unroll
        for (int k = 0; k < 8; ++k) acc[j][k] = 0ULL;

    for (int cc = 0; cc < 64; cc += 16) {
        __syncthreads();
        // stage 16 channels x 512 pixels of X (coalesced)
#pragma unroll
        for (int e = 0; e < 8192; e += 256) {
            int i = e + tid;
            int ch = i >> 9, px = i & 511;
            xsf[ch * 512 + px] = Xb[(size_t)(cc + ch) * NPIX + pbase + px];
        }
        // stage 64 outputs x 16 channels of W, packed (w,w), layout [c][o]
#pragma unroll
        for (int e = 0; e < 1024; e += 256) {
            int i = e + tid;
            int o = i >> 4, cl = i & 15;
            float wv = Wb[(size_t)o * 64 + cc + cl];
            ws2[cl * 64 + o] = pack2(wv, wv);
        }
        __syncthreads();
#pragma unroll
        for (int c = 0; c < 16; ++c) {
            u64 xv[8];
            const u64* xr = xs2 + c * 256 + tp;
#pragma unroll
            for (int k = 0; k < 8; ++k) xv[k] = xr[32 * k];
            const u64* wr = ws2 + c * 64 + to * 8;
#pragma unroll
            for (int j = 0; j < 8; ++j) {
                u64 w2 = wr[j];
#pragma unroll
                for (int k = 0; k < 8; ++k)
                    acc[j][k] = ffma2(w2, xv[k], acc[j][k]);
            }
        }
    }
#pragma unroll
    for (int j = 0; j < 8; ++j) {
        float* yp = Yb + (size_t)(to * 8 + j) * NPIX + pbase + tp * 2;
#pragma unroll
        for (int k = 0; k < 8; ++k)
            *reinterpret_cast<u64*>(yp + 64 * k) = acc[j][k];
    }
}

// ---------------- depthwise 3x3 conv (SAME, zero pad) + gate -----------------
// qv[b,jj,p] = (w_dw[jj] * t[b,jj, 3x3 nbhd]) * t[b,128+jj,p]
// grid: (256/16 rows, 128 ch, BATCH), block 256 (one thread per column)
__global__ __launch_bounds__(256) void conv_mul(const float* __restrict__ w_dw)
{
    __shared__ float st[18][258];
    const int col = threadIdx.x;
    const int jj = blockIdx.y, b = blockIdx.z, r0 = blockIdx.x * 16;

    const float* t1 = g_t + ((size_t)b * 256 + jj) * NPIX;
    const float* t2 = g_t + ((size_t)b * 256 + 128 + jj) * NPIX;
    float* outp = g_qv + ((size_t)b * 128 + jj) * NPIX;

    float wd[9];
#pragma unroll
    for (int i = 0; i < 9; ++i) wd[i] = w_dw[jj * 9 + i];

#pragma unroll
    for (int rr = 0; rr < 18; ++rr) {
        int row = r0 - 1 + rr;
        st[rr][col + 1] = (row >= 0 && row < 256) ? t1[row * 256 + col] : 0.f;
    }
    if (col == 0) {
#pragma unroll
        for (int rr = 0; rr < 18; ++rr) { st[rr][0] = 0.f; st[rr][257] = 0.f; }
    }
    __syncthreads();

#pragma unroll
    for (int r = 0; r < 16; ++r) {
        float s = 0.f;
#pragma unroll
        for (int ky = 0; ky < 3; ++ky)
#pragma unroll
            for (int kx = 0; kx < 3; ++kx)
                s += wd[ky * 3 + kx] * st[r + ky][col + kx];
        int p = (r0 + r) * 256 + col;
        outp[p] = s * t2[p];
    }
}

// ---------------- gram + sumsq ------------------------------------------------
// G[b,cq,cv] += sum_p q[cq,p]*v[cv,p]; sumsq accumulated per channel.
// 8x8 thread tile over pixel-PAIRS (f32x2); channels mapped ch = t + 8*i so
// per-warp smem addresses land in distinct banks (stride-2 banks, conflict-free).
// grid: (128 chunk-strides, BATCH), block 256.
__global__ __launch_bounds__(256) void gram_kernel()
{
    __shared__ u64 qs2[64 * 33];   // [ch][32 pixel-pairs + pad] (16.9 KB)
    __shared__ u64 vs2[64 * 33];
    float* qsf = (float*)qs2;      // float view: ch*66 + px
    float* vsf = (float*)vs2;

    const int tid = threadIdx.x;
    const int b = blockIdx.y;
    const int pg = tid >> 6;           // pixel group (4): handles pp = pg*8..pg*8+7
    const int r  = tid & 63;
    const int tq = r >> 3;             // q channel base: tq + 8*i
    const int tv = r & 7;              // v channel base: tv + 8*j
    const int cqs = tid & 63;          // sumsq channel
    const int pg2 = tid >> 6;

    const float* qsrc = g_qv + (size_t)b * 128 * NPIX;
    const float* vsrc = qsrc + (size_t)64 * NPIX;

    u64 acc[8][8];
#pragma unroll
    for (int i = 0; i < 8; ++i)
#pragma unroll
        for (int j = 0; j < 8; ++j) acc[i][j] = 0ULL;
    float ssq = 0.f, ssv = 0.f;

    for (int chunk = blockIdx.x; chunk < 1024; chunk += gridDim.x) {
        int pbase = chunk * 64;
        __syncthreads();
#pragma unroll
        for (int e = 0; e < 4096; e += 256) {
            int i = e + tid;
            int ch = i >> 6, px = i & 63;
            qsf[ch * 66 + px] = qsrc[(size_t)ch * NPIX + pbase + px];
            vsf[ch * 66 + px] = vsrc[(size_t)ch * NPIX + pbase + px];
        }
        __syncthreads();
        // per-channel sum of squares (thread owns channel cqs, 16 pixels)
#pragma unroll 4
        for (int p = pg2 * 16; p < pg2 * 16 + 16; ++p) {
            float a = qsf[cqs * 66 + p]; ssq += a * a;
            float c = vsf[cqs * 66 + p]; ssv += c * c;
        }
        // gram outer products over 8 pixel-pairs
#pragma unroll
        for (int s = 0; s < 8; ++s) {
            int pp = pg * 8 + s;
            u64 qv_[8], vv_[8];
#pragma unroll
            for (int i = 0; i < 8; ++i) qv_[i] = qs2[(tq + 8 * i) * 33 + pp];
#pragma unroll
            for (int j = 0; j < 8; ++j) vv_[j] = vs2[(tv + 8 * j) * 33 + pp];
#pragma unroll
            for (int i = 0; i < 8; ++i)
#pragma unroll
                for (int j = 0; j < 8; ++j)
                    acc[i][j] = ffma2(qv_[i], vv_[j], acc[i][j]);
        }
    }
    atomicAdd(&g_sumsq[b * 128 + cqs], ssq);
    atomicAdd(&g_sumsq[b * 128 + 64 + cqs], ssv);
#pragma unroll
    for (int i = 0; i < 8; ++i)
#pragma unroll
        for (int j = 0; j < 8; ++j) {
            float lo, hi;
            unpack2(acc[i][j], lo, hi);
            atomicAdd(&g_gram[b * 4096 + (tq + 8 * i) * 64 + (tv + 8 * j)], lo + hi);
        }
}

// ---------------- norms + softmax + M = w_out @ attn (tiny) ------------------
__global__ __launch_bounds__(256) void attn_kernel(
    const float* __restrict__ w_out, const float* __restrict__ temp_p)
{
    __shared__ float attn_s[64 * 65];
    __shared__ float wo_s[64 * 65];
    __shared__ float nrm[128];
    const int tid = threadIdx.x, b = blockIdx.x;

    if (tid < 128) nrm[tid] = fmaxf(sqrtf(g_sumsq[b * 128 + tid]), 1e-12f);
    for (int e = tid; e < 4096; e += 256) {
        int o = e >> 6, c = e & 63;
        wo_s[c * 65 + o] = w_out[e];    // transposed [c][o]
    }
    __syncthreads();

    const float temp = *temp_p;
    if (tid < 64) {
        int c = tid;
        float inq = temp / nrm[c];
        float mx = -1e30f;
        for (int d = 0; d < 64; ++d) {
            float l = g_gram[b * 4096 + c * 64 + d] * (inq / nrm[64 + d]);
            attn_s[c * 65 + d] = l;
            mx = fmaxf(mx, l);
        }
        float sum = 0.f;
        for (int d = 0; d < 64; ++d) {
            float e_ = expf(attn_s[c * 65 + d] - mx);
            attn_s[c * 65 + d] = e_;
            sum += e_;
        }
        float inv = 1.f / sum;
        for (int d = 0; d < 64; ++d) attn_s[c * 65 + d] *= inv;
    }
    __syncthreads();

    const int o = tid & 63, dg = tid >> 6;
    for (int d = dg * 16; d < dg * 16 + 16; ++d) {
        float m = 0.f;
#pragma unroll 8
        for (int c2 = 0; c2 < 64; ++c2) m += wo_s[c2 * 65 + o] * attn_s[c2 * 65 + d];
        g_M[b * 4096 + o * 64 + d] = m;
    }
}

// ---------------- launch ------------------------------------------------------
extern "C" void kernel_launch(void* const* d_in, const int* in_sizes, int n_in,
                              void* d_out, int out_size)
{
    const float* x      = (const float*)d_in[0];
    const float* w_in   = (const float*)d_in[1];
    const float* w_dw   = (const float*)d_in[2];
    const float* w_out  = (const float*)d_in[3];
    const float* temp   = (const float*)d_in[4];
    float* out = (float*)d_out;

    float *t_ptr = nullptr, *qv_ptr = nullptr, *M_ptr = nullptr;
    cudaGetSymbolAddress((void**)&t_ptr,  g_t);
    cudaGetSymbolAddress((void**)&qv_ptr, g_qv);
    cudaGetSymbolAddress((void**)&M_ptr,  g_M);

    zero_stats<<<1, 256>>>();

    // t = w_in @ x   (O=256)
    gemm_k64<<<dim3(NPIX / 512, 4, BATCH), 256>>>(
        w_in, 0, x, (size_t)64 * NPIX, t_ptr, (size_t)256 * NPIX);

    // depthwise conv + gate -> qv
    conv_mul<<<dim3(16, 128, BATCH), 256>>>(w_dw);

    // gram + sumsq
    gram_kernel<<<dim3(128, BATCH), 256>>>();

    // norms, softmax, M = w_out @ attn
    attn_kernel<<<BATCH, 256>>>(w_out, temp);

    // out = M @ v   (O=64)
    gemm_k64<<<dim3(NPIX / 512, 1, BATCH), 256>>>(
        M_ptr, 4096, qv_ptr + (size_t)64 * NPIX, (size_t)128 * NPIX,
        out, (size_t)64 * NPIX);
}

// round 4
// speedup vs baseline: 1.0702x; 1.0668x over previous
#include <cuda_runtime.h>
#include <math.h>

typedef unsigned long long u64;

#define NPIX  65536   // 256*256
#define BATCH 4

// ---------------- scratch (device globals: allocation is forbidden) -----------
__device__ float g_t[(size_t)BATCH * 256 * NPIX];     // 256 MB : t = w_in @ x
__device__ float g_qv[(size_t)BATCH * 128 * NPIX];    // 128 MB : q (0..63), v (64..127)
__device__ float g_sumsq[BATCH * 128];                // per-channel sum of squares (q then v)
__device__ float g_gram[BATCH * 64 * 64];             // raw gram q.v
__device__ float g_M[BATCH * 64 * 64];                // M = w_out @ attn

// ---------------- f32x2 helpers (packed fp32 FMA, sm_100+) -------------------
__device__ __forceinline__ u64 ffma2(u64 a, u64 b, u64 c) {
    u64 d;
    asm("fma.rn.f32x2 %0, %1, %2, %3;" : "=l"(d) : "l"(a), "l"(b), "l"(c));
    return d;
}
__device__ __forceinline__ u64 pack2(float x, float y) {
    u64 d;
    asm("mov.b64 %0, {%1, %2};" : "=l"(d) : "f"(x), "f"(y));
    return d;
}
__device__ __forceinline__ void unpack2(u64 v, float& x, float& y) {
    asm("mov.b64 {%0, %1}, %2;" : "=f"(x), "=f"(y) : "l"(v));
}

// ---------------- zero the accumulators --------------------------------------
__global__ void zero_stats() {
    for (int i = threadIdx.x; i < BATCH * 128 + BATCH * 64 * 64; i += blockDim.x) {
        if (i < BATCH * 128) g_sumsq[i] = 0.f;
        else                 g_gram[i - BATCH * 128] = 0.f;
    }
}

// ---------------- K=64 GEMM: Y[b,o,p] = sum_c W[b,o,c] * X[b,c,p] ------------
// block 256 threads; tile = 64 outputs x 256 pixels (128 pixel-pairs).
// thread = 8 outputs x 4 pixel-pairs (acc = 32 u64 = 64 regs -> 2 CTAs/SM).
// grid: (NPIX/256, O/64, BATCH)
__global__ __launch_bounds__(256, 2) void gemm_k64(
    const float* __restrict__ W, size_t wBatch,
    const float* __restrict__ X, size_t xBatch,
    float* __restrict__ Y, size_t yBatch)
{
    __shared__ u64 xs2[16 * 128];   // 16 ch x 128 pixel-pairs (16 KB)
    __shared__ u64 ws2[16 * 64];    // 16 ch x 64 outputs, (w,w) packed (8 KB)
    float* xsf = (float*)xs2;

    const int tid = threadIdx.x;
    const int tp = tid & 31;         // pixel-pair: tp + 32*k, k<4
    const int to = tid >> 5;         // output group (8 outputs) -- uniform per warp
    const int b = blockIdx.z;
    const int pbase = blockIdx.x * 256;
    const int obase = blockIdx.y * 64;

    const float* Wb = W + (size_t)b * wBatch + (size_t)obase * 64;
    const float* Xb = X + (size_t)b * xBatch;
    float*       Yb = Y + (size_t)b * yBatch + (size_t)obase * NPIX;

    u64 acc[8][4];
#pragma unroll
    for (int j = 0; j < 8; ++j)
#pragma unroll
        for (int k = 0; k < 4; ++k) acc[j][k] = 0ULL;

    for (int cc = 0; cc < 64; cc += 16) {
        __syncthreads();
        // stage 16 channels x 256 pixels of X as float4 (coalesced, 16B-aligned:
        // row stride 256 floats, pbase multiple of 256)
#pragma unroll
        for (int e = 0; e < 1024; e += 256) {
            int i = e + tid;
            int ch = i >> 6, p4 = i & 63;
            ((float4*)xsf)[ch * 64 + p4] =
                *(const float4*)(Xb + (size_t)(cc + ch) * NPIX + pbase + p4 * 4);
        }
        // stage 64 outputs x 16 channels of W, packed (w,w), layout [c][o]
#pragma unroll
        for (int e = 0; e < 1024; e += 256) {
            int i = e + tid;
            int o = i >> 4, cl = i & 15;
            float wv = Wb[(size_t)o * 64 + cc + cl];
            ws2[cl * 64 + o] = pack2(wv, wv);
        }
        __syncthreads();
#pragma unroll
        for (int c = 0; c < 16; ++c) {
            u64 xv[4];
            const u64* xr = xs2 + c * 128 + tp;
#pragma unroll
            for (int k = 0; k < 4; ++k) xv[k] = xr[32 * k];
            const u64* wr = ws2 + c * 64 + to * 8;   // broadcast within warp
#pragma unroll
            for (int j = 0; j < 8; ++j) {
                u64 w2 = wr[j];
#pragma unroll
                for (int k = 0; k < 4; ++k)
                    acc[j][k] = ffma2(w2, xv[k], acc[j][k]);
            }
        }
    }
#pragma unroll
    for (int j = 0; j < 8; ++j) {
        float* yp = Yb + (size_t)(to * 8 + j) * NPIX + pbase + tp * 2;
#pragma unroll
        for (int k = 0; k < 4; ++k)
            *reinterpret_cast<u64*>(yp + 64 * k) = acc[j][k];   // 8B-aligned
    }
}

// ---------------- depthwise 3x3 conv (SAME, zero pad) + gate -----------------
// qv[b,jj,p] = (w_dw[jj] * t[b,jj, 3x3 nbhd]) * t[b,128+jj,p]
// grid: (256/32 rows, 128 ch, BATCH), block 256 (one thread per column)
__global__ __launch_bounds__(256) void conv_mul(const float* __restrict__ w_dw)
{
    __shared__ float st[34][258];
    const int col = threadIdx.x;
    const int jj = blockIdx.y, b = blockIdx.z, r0 = blockIdx.x * 32;

    const float* t1 = g_t + ((size_t)b * 256 + jj) * NPIX;
    const float* t2 = g_t + ((size_t)b * 256 + 128 + jj) * NPIX;
    float* outp = g_qv + ((size_t)b * 128 + jj) * NPIX;

    float wd[9];
#pragma unroll
    for (int i = 0; i < 9; ++i) wd[i] = w_dw[jj * 9 + i];

#pragma unroll
    for (int rr = 0; rr < 34; ++rr) {
        int row = r0 - 1 + rr;
        st[rr][col + 1] = (row >= 0 && row < 256) ? t1[row * 256 + col] : 0.f;
    }
    if (col == 0) {
#pragma unroll
        for (int rr = 0; rr < 34; ++rr) { st[rr][0] = 0.f; st[rr][257] = 0.f; }
    }
    __syncthreads();

#pragma unroll 4
    for (int r = 0; r < 32; ++r) {
        float s = 0.f;
#pragma unroll
        for (int ky = 0; ky < 3; ++ky)
#pragma unroll
            for (int kx = 0; kx < 3; ++kx)
                s += wd[ky * 3 + kx] * st[r + ky][col + kx];
        int p = (r0 + r) * 256 + col;
        outp[p] = s * t2[p];
    }
}

// ---------------- gram + sumsq ------------------------------------------------
// G[b,cq,cv] += sum_p q[cq,p]*v[cv,p]; sumsq per channel.
// 16x16 thread grid, 4x4 channel tile over pixel-pairs (acc = 16 u64 = 32 regs).
// smem stride 33 u64 (=66 floats): v loads bank-pairs all distinct (tx*2 mod 32),
// q loads broadcast. Staging uses u64 (8B-aligned everywhere; float4 would NOT be).
// grid: (128 chunk-strides, BATCH), block 256.
__global__ __launch_bounds__(256, 3) void gram_kernel()
{
    __shared__ u64 qs2[64 * 33];   // [ch][32 pixel-pairs + pad] (16.9 KB)
    __shared__ u64 vs2[64 * 33];
    float* qsf = (float*)qs2;      // float view: ch*66 + px
    float* vsf = (float*)vs2;

    const int tid = threadIdx.x;
    const int b = blockIdx.y;
    const int tx = tid & 15;           // v channel base: tx + 16*j
    const int ty = tid >> 4;           // q channel base: ty + 16*i
    const int cqs = tid & 63;          // sumsq channel
    const int pg2 = tid >> 6;

    const float* qsrc = g_qv + (size_t)b * 128 * NPIX;
    const float* vsrc = qsrc + (size_t)64 * NPIX;

    u64 acc[4][4];
#pragma unroll
    for (int i = 0; i < 4; ++i)
#pragma unroll
        for (int j = 0; j < 4; ++j) acc[i][j] = 0ULL;
    float ssq = 0.f, ssv = 0.f;

    for (int chunk = blockIdx.x; chunk < 1024; chunk += gridDim.x) {
        int pbase = chunk * 64;
        __syncthreads();
        // stage 64 ch x 32 pixel-pairs as u64 (8B-aligned on both sides)
#pragma unroll
        for (int e = 0; e < 2048; e += 256) {
            int i = e + tid;
            int ch = i >> 5, pp = i & 31;
            qs2[ch * 33 + pp] =
                *(const u64*)(qsrc + (size_t)ch * NPIX + pbase + pp * 2);
            vs2[ch * 33 + pp] =
                *(const u64*)(vsrc + (size_t)ch * NPIX + pbase + pp * 2);
        }
        __syncthreads();
        // per-channel sum of squares (thread owns channel cqs, 16 pixels)
#pragma unroll 4
        for (int p = pg2 * 16; p < pg2 * 16 + 16; ++p) {
            float a = qsf[cqs * 66 + p]; ssq += a * a;
            float c = vsf[cqs * 66 + p]; ssv += c * c;
        }
        // gram outer products over 32 pixel-pairs
#pragma unroll 2
        for (int pp = 0; pp < 32; ++pp) {
            u64 qv_[4], vv_[4];
#pragma unroll
            for (int i = 0; i < 4; ++i) qv_[i] = qs2[(ty + 16 * i) * 33 + pp];
#pragma unroll
            for (int j = 0; j < 4; ++j) vv_[j] = vs2[(tx + 16 * j) * 33 + pp];
#pragma unroll
            for (int i = 0; i < 4; ++i)
#pragma unroll
                for (int j = 0; j < 4; ++j)
                    acc[i][j] = ffma2(qv_[i], vv_[j], acc[i][j]);
        }
    }
    atomicAdd(&g_sumsq[b * 128 + cqs], ssq);
    atomicAdd(&g_sumsq[b * 128 + 64 + cqs], ssv);
#pragma unroll
    for (int i = 0; i < 4; ++i)
#pragma unroll
        for (int j = 0; j < 4; ++j) {
            float lo, hi;
            unpack2(acc[i][j], lo, hi);
            atomicAdd(&g_gram[b * 4096 + (ty + 16 * i) * 64 + (tx + 16 * j)], lo + hi);
        }
}

// ---------------- norms + softmax + M = w_out @ attn (tiny) ------------------
__global__ __launch_bounds__(256) void attn_kernel(
    const float* __restrict__ w_out, const float* __restrict__ temp_p)
{
    __shared__ float attn_s[64 * 65];
    __shared__ float wo_s[64 * 65];
    __shared__ float nrm[128];
    const int tid = threadIdx.x, b = blockIdx.x;

    if (tid < 128) nrm[tid] = fmaxf(sqrtf(g_sumsq[b * 128 + tid]), 1e-12f);
    for (int e = tid; e < 4096; e += 256) {
        int o = e >> 6, c = e & 63;
        wo_s[c * 65 + o] = w_out[e];    // transposed [c][o]
    }
    __syncthreads();

    const float temp = *temp_p;
    if (tid < 64) {
        int c = tid;
        float inq = temp / nrm[c];
        float mx = -1e30f;
        for (int d = 0; d < 64; ++d) {
            float l = g_gram[b * 4096 + c * 64 + d] * (inq / nrm[64 + d]);
            attn_s[c * 65 + d] = l;
            mx = fmaxf(mx, l);
        }
        float sum = 0.f;
        for (int d = 0; d < 64; ++d) {
            float e_ = expf(attn_s[c * 65 + d] - mx);
            attn_s[c * 65 + d] = e_;
            sum += e_;
        }
        float inv = 1.f / sum;
        for (int d = 0; d < 64; ++d) attn_s[c * 65 + d] *= inv;
    }
    __syncthreads();

    const int o = tid & 63, dg = tid >> 6;
    for (int d = dg * 16; d < dg * 16 + 16; ++d) {
        float m = 0.f;
#pragma unroll 8
        for (int c2 = 0; c2 < 64; ++c2) m += wo_s[c2 * 65 + o] * attn_s[c2 * 65 + d];
        g_M[b * 4096 + o * 64 + d] = m;
    }
}

// ---------------- launch ------------------------------------------------------
extern "C" void kernel_launch(void* const* d_in, const int* in_sizes, int n_in,
                              void* d_out, int out_size)
{
    const float* x      = (const float*)d_in[0];
    const float* w_in   = (const float*)d_in[1];
    const float* w_dw   = (const float*)d_in[2];
    const float* w_out  = (const float*)d_in[3];
    const float* temp   = (const float*)d_in[4];
    float* out = (float*)d_out;

    float *t_ptr = nullptr, *qv_ptr = nullptr, *M_ptr = nullptr;
    cudaGetSymbolAddress((void**)&t_ptr,  g_t);
    cudaGetSymbolAddress((void**)&qv_ptr, g_qv);
    cudaGetSymbolAddress((void**)&M_ptr,  g_M);

    zero_stats<<<1, 256>>>();

    // t = w_in @ x   (O=256)
    gemm_k64<<<dim3(NPIX / 256, 4, BATCH), 256>>>(
        w_in, 0, x, (size_t)64 * NPIX, t_ptr, (size_t)256 * NPIX);

    // depthwise conv + gate -> qv
    conv_mul<<<dim3(8, 128, BATCH), 256>>>(w_dw);

    // gram + sumsq
    gram_kernel<<<dim3(128, BATCH), 256>>>();

    // norms, softmax, M = w_out @ attn
    attn_kernel<<<BATCH, 256>>>(w_out, temp);

    // out = M @ v   (O=64)
    gemm_k64<<<dim3(NPIX / 256, 1, BATCH), 256>>>(
        M_ptr, 4096, qv_ptr + (size_t)64 * NPIX, (size_t)128 * NPIX,
        out, (size_t)64 * NPIX);
}

// round 6
// speedup vs baseline: 1.1061x; 1.0335x over previous
#include <cuda_runtime.h>
#include <cuda_bf16.h>
#include <math.h>
#include <stdint.h>

typedef unsigned long long u64;

#define NPIX  65536   // 256*256
#define BATCH 4

// ---------------- scratch (device globals: allocation is forbidden) -----------
__device__ float g_t[(size_t)BATCH * 256 * NPIX];             // 256 MB : t = w_in @ x
__device__ float g_qv[(size_t)BATCH * 128 * NPIX];            // 128 MB : q, v
__device__ __nv_bfloat16 g_x2[(size_t)BATCH * NPIX * 192];    // 100 MB : bf16-split x, [p][192]
__device__ __nv_bfloat16 g_a2[256 * 192];                     // bf16-split w_in, [o][192]
__device__ float g_sumsq[BATCH * 128];
__device__ float g_gram[BATCH * 64 * 64];
__device__ float g_M[BATCH * 64 * 64];

// ---------------- f32x2 helpers ----------------------------------------------
__device__ __forceinline__ u64 ffma2(u64 a, u64 b, u64 c) {
    u64 d;
    asm("fma.rn.f32x2 %0, %1, %2, %3;" : "=l"(d) : "l"(a), "l"(b), "l"(c));
    return d;
}
__device__ __forceinline__ u64 pack2(float x, float y) {
    u64 d;
    asm("mov.b64 %0, {%1, %2};" : "=l"(d) : "f"(x), "f"(y));
    return d;
}
__device__ __forceinline__ void unpack2(u64 v, float& x, float& y) {
    asm("mov.b64 {%0, %1}, %2;" : "=f"(x), "=f"(y) : "l"(v));
}

// ---------------- mma.sync helpers (baseline PTX, valid on sm_103) ------------
__device__ __forceinline__ uint32_t smem_to_u32(const void* p) {
    uint32_t a;
    asm("{ .reg .u64 t; cvta.to.shared.u64 t, %1; cvt.u32.u64 %0, t; }" : "=r"(a) : "l"(p));
    return a;
}
__device__ __forceinline__ void ldsm_x4(uint32_t& r0, uint32_t& r1, uint32_t& r2, uint32_t& r3,
                                        uint32_t addr) {
    asm volatile("ldmatrix.sync.aligned.m8n8.x4.shared.b16 {%0,%1,%2,%3}, [%4];"
        : "=r"(r0), "=r"(r1), "=r"(r2), "=r"(r3) : "r"(addr));
}
__device__ __forceinline__ void mma_bf16(float* d, const uint32_t* a, const uint32_t* b) {
    asm volatile("mma.sync.aligned.m16n8k16.row.col.f32.bf16.bf16.f32 "
        "{%0,%1,%2,%3}, {%4,%5,%6,%7}, {%8,%9}, {%0,%1,%2,%3};"
        : "+f"(d[0]), "+f"(d[1]), "+f"(d[2]), "+f"(d[3])
        : "r"(a[0]), "r"(a[1]), "r"(a[2]), "r"(a[3]), "r"(b[0]), "r"(b[1]));
}

// ---------------- zero the accumulators --------------------------------------
__global__ void zero_stats() {
    for (int i = threadIdx.x; i < BATCH * 128 + BATCH * 64 * 64; i += blockDim.x) {
        if (i < BATCH * 128) g_sumsq[i] = 0.f;
        else                 g_gram[i - BATCH * 128] = 0.f;
    }
}

// ---------------- weight split: w_in[256][64] -> A2[256][192] bf16 -----------
// k = 3c+j : j=0 -> w_hi, j=1 -> w_hi, j=2 -> w_lo
__global__ void wsplit(const float* __restrict__ w_in) {
    for (int i = threadIdx.x + blockIdx.x * blockDim.x; i < 256 * 192; i += blockDim.x * gridDim.x) {
        int o = i / 192, k = i % 192;
        int c = k / 3, j = k % 3;
        float w = w_in[o * 64 + c];
        __nv_bfloat16 hi = __float2bfloat16(w);
        if (j == 2) g_a2[i] = __float2bfloat16(w - __bfloat162float(hi));
        else        g_a2[i] = hi;
    }
}

// ---------------- x split + transpose: x[b][c][p] -> X2[b][p][192] -----------
// k = 3c+j : j=0 -> x_hi, j=1 -> x_lo, j=2 -> x_hi
__global__ __launch_bounds__(256) void split192(const float* __restrict__ x) {
    __shared__ float tile[64][65];
    const int tid = threadIdx.x;
    const int pbase = blockIdx.x * 64, b = blockIdx.y;
    const float* xb = x + (size_t)b * 64 * NPIX;

#pragma unroll
    for (int e = 0; e < 4096; e += 256) {
        int i = e + tid;
        int ch = i >> 6, px = i & 63;
        tile[ch][px] = xb[(size_t)ch * NPIX + pbase + px];
    }
    __syncthreads();

    __nv_bfloat16* out = g_x2 + ((size_t)b * NPIX + pbase) * 192;
#pragma unroll
    for (int e = 0; e < 6144; e += 256) {
        int i = e + tid;
        int p = i / 96, u = i % 96;
        uint32_t w = 0;
#pragma unroll
        for (int h = 0; h < 2; ++h) {
            int k = 2 * u + h;
            int c = k / 3, j = k % 3;
            float xv = tile[c][p];
            __nv_bfloat16 hi = __float2bfloat16(xv);
            __nv_bfloat16 val;
            if (j == 1) val = __float2bfloat16(xv - __bfloat162float(hi));
            else        val = hi;
            unsigned short bits = *(unsigned short*)&val;
            w |= (uint32_t)bits << (16 * h);
        }
        *(uint32_t*)(out + p * 192 + u * 2) = w;
    }
}

// ---------------- tensor-core gemm1 via mma.sync bf16 (K=192 split) ----------
// CTA: M=128 outs x N=128 pixels x K=192 (staged whole). 8 warps = 4(m) x 2(n);
// warp = 32x64. SMEM rows padded to 400B -> ldmatrix conflict-free.
// grid (NPIX/128, 2, BATCH), block 256, dyn smem 102400B (2 CTAs/SM).
#define G1_LDA   100                    // u32 per smem row (96 data + 4 pad)
#define G1_ROWB  400                    // bytes per row
#define G1_SMEM  (2 * 128 * G1_LDA * 4) // 102400
__global__ __launch_bounds__(256, 2) void gemm1_mma() {
    extern __shared__ uint32_t sm[];
    uint32_t* As = sm;                  // [128][100] u32
    uint32_t* Bs = sm + 128 * G1_LDA;

    const int tid = threadIdx.x, wid = tid >> 5, lane = tid & 31;
    const int pbase = blockIdx.x * 128;
    const int obase = blockIdx.y * 128;
    const int b = blockIdx.z;
    const int warpM = wid & 3, warpN = wid >> 2;

    // stage A (outputs x K) and B (pixels x K), coalesced u32
    const uint32_t* Ag = (const uint32_t*)(g_a2 + (size_t)obase * 192);
    const uint32_t* Xg = (const uint32_t*)(g_x2 + ((size_t)b * NPIX + pbase) * 192);
#pragma unroll 4
    for (int i = tid; i < 128 * 96; i += 256) {
        int r = i / 96, u = i % 96;
        As[r * G1_LDA + u] = Ag[r * 96 + u];
    }
#pragma unroll 4
    for (int i = tid; i < 128 * 96; i += 256) {
        int r = i / 96, u = i % 96;
        Bs[r * G1_LDA + u] = Xg[r * 96 + u];
    }
    __syncthreads();

    const uint32_t a_smem = smem_to_u32(As);
    const uint32_t b_smem = smem_to_u32(Bs);
    // ldmatrix lane roles: row = lane&15, k-half = (lane>>4)*8
    const int lrow = lane & 15;
    const int lkh  = (lane >> 4) * 8;

    float acc[2][8][4];
#pragma unroll
    for (int mi = 0; mi < 2; ++mi)
#pragma unroll
        for (int ni = 0; ni < 8; ++ni)
#pragma unroll
            for (int r = 0; r < 4; ++r) acc[mi][ni][r] = 0.f;

#pragma unroll
    for (int ks = 0; ks < 12; ++ks) {
        const int k0 = ks * 16;
        uint32_t a[2][4];
#pragma unroll
        for (int mi = 0; mi < 2; ++mi) {
            uint32_t addr = a_smem + (warpM * 32 + mi * 16 + lrow) * G1_ROWB + (k0 + lkh) * 2;
            ldsm_x4(a[mi][0], a[mi][1], a[mi][2], a[mi][3], addr);
        }
        uint32_t bf[8][2];
#pragma unroll
        for (int nq = 0; nq < 4; ++nq) {
            uint32_t r0, r1, r2, r3;
            uint32_t addr = b_smem + (warpN * 64 + nq * 16 + lrow) * G1_ROWB + (k0 + lkh) * 2;
            ldsm_x4(r0, r1, r2, r3, addr);
            bf[2 * nq][0] = r0;     bf[2 * nq][1] = r2;
            bf[2 * nq + 1][0] = r1; bf[2 * nq + 1][1] = r3;
        }
#pragma unroll
        for (int mi = 0; mi < 2; ++mi)
#pragma unroll
            for (int ni = 0; ni < 8; ++ni)
                mma_bf16(acc[mi][ni], a[mi], bf[ni]);
    }

    // epilogue: write t. thread holds D[g][2T],[g][2T+1],[g+8][2T],[g+8][2T+1]
    const int g = lane >> 2, T = lane & 3;
#pragma unroll
    for (int mi = 0; mi < 2; ++mi) {
        int m = obase + warpM * 32 + mi * 16 + g;
        float* rowp = g_t + ((size_t)b * 256 + m) * NPIX + pbase + warpN * 64 + T * 2;
#pragma unroll
        for (int ni = 0; ni < 8; ++ni) {
            *(u64*)(rowp + ni * 8) = pack2(acc[mi][ni][0], acc[mi][ni][1]);
            *(u64*)(rowp + ni * 8 + (size_t)8 * NPIX) = pack2(acc[mi][ni][2], acc[mi][ni][3]);
        }
    }
}

// ---------------- depthwise 3x3 conv (SAME, zero pad) + gate -----------------
__global__ __launch_bounds__(256) void conv_mul(const float* __restrict__ w_dw)
{
    __shared__ float st[34][258];
    const int col = threadIdx.x;
    const int jj = blockIdx.y, b = blockIdx.z, r0 = blockIdx.x * 32;

    const float* t1 = g_t + ((size_t)b * 256 + jj) * NPIX;
    const float* t2 = g_t + ((size_t)b * 256 + 128 + jj) * NPIX;
    float* outp = g_qv + ((size_t)b * 128 + jj) * NPIX;

    float wd[9];
#pragma unroll
    for (int i = 0; i < 9; ++i) wd[i] = w_dw[jj * 9 + i];

#pragma unroll
    for (int rr = 0; rr < 34; ++rr) {
        int row = r0 - 1 + rr;
        st[rr][col + 1] = (row >= 0 && row < 256) ? t1[row * 256 + col] : 0.f;
    }
    if (col == 0) {
#pragma unroll
        for (int rr = 0; rr < 34; ++rr) { st[rr][0] = 0.f; st[rr][257] = 0.f; }
    }
    __syncthreads();

#pragma unroll 4
    for (int r = 0; r < 32; ++r) {
        float s = 0.f;
#pragma unroll
        for (int ky = 0; ky < 3; ++ky)
#pragma unroll
            for (int kx = 0; kx < 3; ++kx)
                s += wd[ky * 3 + kx] * st[r + ky][col + kx];
        int p = (r0 + r) * 256 + col;
        outp[p] = s * t2[p];
    }
}

// ---------------- gram + sumsq (round-4 version, unchanged) -------------------
__global__ __launch_bounds__(256, 3) void gram_kernel()
{
    __shared__ u64 qs2[64 * 33];
    __shared__ u64 vs2[64 * 33];
    float* qsf = (float*)qs2;
    float* vsf = (float*)vs2;

    const int tid = threadIdx.x;
    const int b = blockIdx.y;
    const int tx = tid & 15;
    const int ty = tid >> 4;
    const int cqs = tid & 63;
    const int pg2 = tid >> 6;

    const float* qsrc = g_qv + (size_t)b * 128 * NPIX;
    const float* vsrc = qsrc + (size_t)64 * NPIX;

    u64 acc[4][4];
#pragma unroll
    for (int i = 0; i < 4; ++i)
#pragma unroll
        for (int j = 0; j < 4; ++j) acc[i][j] = 0ULL;
    float ssq = 0.f, ssv = 0.f;

    for (int chunk = blockIdx.x; chunk < 1024; chunk += gridDim.x) {
        int pbase = chunk * 64;
        __syncthreads();
#pragma unroll
        for (int e = 0; e < 2048; e += 256) {
            int i = e + tid;
            int ch = i >> 5, pp = i & 31;
            qs2[ch * 33 + pp] = *(const u64*)(qsrc + (size_t)ch * NPIX + pbase + pp * 2);
            vs2[ch * 33 + pp] = *(const u64*)(vsrc + (size_t)ch * NPIX + pbase + pp * 2);
        }
        __syncthreads();
#pragma unroll 4
        for (int p = pg2 * 16; p < pg2 * 16 + 16; ++p) {
            float a = qsf[cqs * 66 + p]; ssq += a * a;
            float c = vsf[cqs * 66 + p]; ssv += c * c;
        }
#pragma unroll 2
        for (int pp = 0; pp < 32; ++pp) {
            u64 qv_[4], vv_[4];
#pragma unroll
            for (int i = 0; i < 4; ++i) qv_[i] = qs2[(ty + 16 * i) * 33 + pp];
#pragma unroll
            for (int j = 0; j < 4; ++j) vv_[j] = vs2[(tx + 16 * j) * 33 + pp];
#pragma unroll
            for (int i = 0; i < 4; ++i)
#pragma unroll
                for (int j = 0; j < 4; ++j)
                    acc[i][j] = ffma2(qv_[i], vv_[j], acc[i][j]);
        }
    }
    atomicAdd(&g_sumsq[b * 128 + cqs], ssq);
    atomicAdd(&g_sumsq[b * 128 + 64 + cqs], ssv);
#pragma unroll
    for (int i = 0; i < 4; ++i)
#pragma unroll
        for (int j = 0; j < 4; ++j) {
            float lo, hi;
            unpack2(acc[i][j], lo, hi);
            atomicAdd(&g_gram[b * 4096 + (ty + 16 * i) * 64 + (tx + 16 * j)], lo + hi);
        }
}

// ---------------- norms + softmax + M = w_out @ attn --------------------------
__global__ __launch_bounds__(256) void attn_kernel(
    const float* __restrict__ w_out, const float* __restrict__ temp_p)
{
    __shared__ float attn_s[64 * 65];
    __shared__ float wo_s[64 * 65];
    __shared__ float nrm[128];
    const int tid = threadIdx.x, b = blockIdx.x;

    if (tid < 128) nrm[tid] = fmaxf(sqrtf(g_sumsq[b * 128 + tid]), 1e-12f);
    for (int e = tid; e < 4096; e += 256) {
        int o = e >> 6, c = e & 63;
        wo_s[c * 65 + o] = w_out[e];
    }
    __syncthreads();

    const float temp = *temp_p;
    if (tid < 64) {
        int c = tid;
        float inq = temp / nrm[c];
        float mx = -1e30f;
        for (int d = 0; d < 64; ++d) {
            float l = g_gram[b * 4096 + c * 64 + d] * (inq / nrm[64 + d]);
            attn_s[c * 65 + d] = l;
            mx = fmaxf(mx, l);
        }
        float sum = 0.f;
        for (int d = 0; d < 64; ++d) {
            float e_ = expf(attn_s[c * 65 + d] - mx);
            attn_s[c * 65 + d] = e_;
            sum += e_;
        }
        float inv = 1.f / sum;
        for (int d = 0; d < 64; ++d) attn_s[c * 65 + d] *= inv;
    }
    __syncthreads();

    const int o = tid & 63, dg = tid >> 6;
    for (int d = dg * 16; d < dg * 16 + 16; ++d) {
        float m = 0.f;
#pragma unroll 8
        for (int c2 = 0; c2 < 64; ++c2) m += wo_s[c2 * 65 + o] * attn_s[c2 * 65 + d];
        g_M[b * 4096 + o * 64 + d] = m;
    }
}

// ---------------- scalar K=64 GEMM (for gemm2 only) ---------------------------
__global__ __launch_bounds__(256, 2) void gemm_k64(
    const float* __restrict__ W, size_t wBatch,
    const float* __restrict__ X, size_t xBatch,
    float* __restrict__ Y, size_t yBatch)
{
    __shared__ u64 xs2[16 * 128];
    __shared__ u64 ws2[16 * 64];
    float* xsf = (float*)xs2;

    const int tid = threadIdx.x;
    const int tp = tid & 31;
    const int to = tid >> 5;
    const int b = blockIdx.z;
    const int pbase = blockIdx.x * 256;
    const int obase = blockIdx.y * 64;

    const float* Wb = W + (size_t)b * wBatch + (size_t)obase * 64;
    const float* Xb = X + (size_t)b * xBatch;
    float*       Yb = Y + (size_t)b * yBatch + (size_t)obase * NPIX;

    u64 acc[8][4];
#pragma unroll
    for (int j = 0; j < 8; ++j)
#pragma unroll
        for (int k = 0; k < 4; ++k) acc[j][k] = 0ULL;

    for (int cc = 0; cc < 64; cc += 16) {
        __syncthreads();
#pragma unroll
        for (int e = 0; e < 1024; e += 256) {
            int i = e + tid;
            int ch = i >> 6, p4 = i & 63;
            ((float4*)xsf)[ch * 64 + p4] =
                *(const float4*)(Xb + (size_t)(cc + ch) * NPIX + pbase + p4 * 4);
        }
#pragma unroll
        for (int e = 0; e < 1024; e += 256) {
            int i = e + tid;
            int o = i >> 4, cl = i & 15;
            float wv = Wb[(size_t)o * 64 + cc + cl];
            ws2[cl * 64 + o] = pack2(wv, wv);
        }
        __syncthreads();
#pragma unroll
        for (int c = 0; c < 16; ++c) {
            u64 xv[4];
            const u64* xr = xs2 + c * 128 + tp;
#pragma unroll
            for (int k = 0; k < 4; ++k) xv[k] = xr[32 * k];
            const u64* wr = ws2 + c * 64 + to * 8;
#pragma unroll
            for (int j = 0; j < 8; ++j) {
                u64 w2 = wr[j];
#pragma unroll
                for (int k = 0; k < 4; ++k)
                    acc[j][k] = ffma2(w2, xv[k], acc[j][k]);
            }
        }
    }
#pragma unroll
    for (int j = 0; j < 8; ++j) {
        float* yp = Yb + (size_t)(to * 8 + j) * NPIX + pbase + tp * 2;
#pragma unroll
        for (int k = 0; k < 4; ++k)
            *reinterpret_cast<u64*>(yp + 64 * k) = acc[j][k];
    }
}

// ---------------- launch ------------------------------------------------------
extern "C" void kernel_launch(void* const* d_in, const int* in_sizes, int n_in,
                              void* d_out, int out_size)
{
    const float* x      = (const float*)d_in[0];
    const float* w_in   = (const float*)d_in[1];
    const float* w_dw   = (const float*)d_in[2];
    const float* w_out  = (const float*)d_in[3];
    const float* temp   = (const float*)d_in[4];
    float* out = (float*)d_out;

    float *qv_ptr = nullptr, *M_ptr = nullptr;
    cudaGetSymbolAddress((void**)&qv_ptr, g_qv);
    cudaGetSymbolAddress((void**)&M_ptr,  g_M);

    cudaFuncSetAttribute(gemm1_mma, cudaFuncAttributeMaxDynamicSharedMemorySize, G1_SMEM);

    zero_stats<<<1, 256>>>();
    wsplit<<<64, 256>>>(w_in);
    split192<<<dim3(NPIX / 64, BATCH), 256>>>(x);

    // t = w_in @ x  on tensor cores (bf16-split, K=192, mma.sync)
    gemm1_mma<<<dim3(NPIX / 128, 2, BATCH), 256, G1_SMEM>>>();

    // depthwise conv + gate -> qv
    conv_mul<<<dim3(8, 128, BATCH), 256>>>(w_dw);

    // gram + sumsq
    gram_kernel<<<dim3(128, BATCH), 256>>>();

    // norms, softmax, M = w_out @ attn
    attn_kernel<<<BATCH, 256>>>(w_out, temp);

    // out = M @ v   (scalar f32x2 path)
    gemm_k64<<<dim3(NPIX / 256, 1, BATCH), 256>>>(
        M_ptr, 4096, qv_ptr + (size_t)64 * NPIX, (size_t)128 * NPIX,
        out, (size_t)64 * NPIX);
}

// round 7
// speedup vs baseline: 1.2598x; 1.1389x over previous
#include <cuda_runtime.h>
#include <cuda_bf16.h>
#include <math.h>
#include <stdint.h>

typedef unsigned long long u64;

#define NPIX  65536   // 256*256
#define BATCH 4

// ---------------- scratch (device globals: allocation is forbidden) -----------
__device__ float g_t[(size_t)BATCH * 256 * NPIX];             // 256 MB : t = w_in @ x
__device__ float g_qv[(size_t)BATCH * 128 * NPIX];            // 128 MB : q, v
__device__ __nv_bfloat16 g_x2[(size_t)BATCH * NPIX * 192];    // 100 MB : bf16-split x, [p][192]
__device__ __nv_bfloat16 g_a2[256 * 192];                     // bf16-split w_in, [o][192]
__device__ float g_sumsq[BATCH * 128];
__device__ float g_gram[BATCH * 64 * 64];
__device__ float g_M[BATCH * 64 * 64];

// ---------------- f32x2 helpers ----------------------------------------------
__device__ __forceinline__ u64 ffma2(u64 a, u64 b, u64 c) {
    u64 d;
    asm("fma.rn.f32x2 %0, %1, %2, %3;" : "=l"(d) : "l"(a), "l"(b), "l"(c));
    return d;
}
__device__ __forceinline__ u64 pack2(float x, float y) {
    u64 d;
    asm("mov.b64 %0, {%1, %2};" : "=l"(d) : "f"(x), "f"(y));
    return d;
}
__device__ __forceinline__ void unpack2(u64 v, float& x, float& y) {
    asm("mov.b64 {%0, %1}, %2;" : "=f"(x), "=f"(y) : "l"(v));
}

// ---------------- mma.sync / cp.async helpers (baseline PTX) ------------------
__device__ __forceinline__ uint32_t smem_to_u32(const void* p) {
    uint32_t a;
    asm("{ .reg .u64 t; cvta.to.shared.u64 t, %1; cvt.u32.u64 %0, t; }" : "=r"(a) : "l"(p));
    return a;
}
__device__ __forceinline__ void ldsm_x4(uint32_t& r0, uint32_t& r1, uint32_t& r2, uint32_t& r3,
                                        uint32_t addr) {
    asm volatile("ldmatrix.sync.aligned.m8n8.x4.shared.b16 {%0,%1,%2,%3}, [%4];"
        : "=r"(r0), "=r"(r1), "=r"(r2), "=r"(r3) : "r"(addr));
}
__device__ __forceinline__ void mma_bf16(float* d, const uint32_t* a, const uint32_t* b) {
    asm volatile("mma.sync.aligned.m16n8k16.row.col.f32.bf16.bf16.f32 "
        "{%0,%1,%2,%3}, {%4,%5,%6,%7}, {%8,%9}, {%0,%1,%2,%3};"
        : "+f"(d[0]), "+f"(d[1]), "+f"(d[2]), "+f"(d[3])
        : "r"(a[0]), "r"(a[1]), "r"(a[2]), "r"(a[3]), "r"(b[0]), "r"(b[1]));
}
__device__ __forceinline__ void cp16(uint32_t smem_addr, const void* gptr) {
    asm volatile("cp.async.cg.shared.global [%0], [%1], 16;" :: "r"(smem_addr), "l"(gptr));
}
#define CP_COMMIT() asm volatile("cp.async.commit_group;" ::: "memory")
#define CP_WAIT(n)  asm volatile("cp.async.wait_group %0;" :: "n"(n) : "memory")

// ---------------- zero the accumulators --------------------------------------
__global__ void zero_stats() {
    for (int i = threadIdx.x; i < BATCH * 128 + BATCH * 64 * 64; i += blockDim.x) {
        if (i < BATCH * 128) g_sumsq[i] = 0.f;
        else                 g_gram[i - BATCH * 128] = 0.f;
    }
}

// ---------------- weight split: w_in[256][64] -> A2[256][192] bf16 -----------
// k = 3c+j : j=0 -> w_hi, j=1 -> w_hi, j=2 -> w_lo
__global__ void wsplit(const float* __restrict__ w_in) {
    for (int i = threadIdx.x + blockIdx.x * blockDim.x; i < 256 * 192; i += blockDim.x * gridDim.x) {
        int o = i / 192, k = i % 192;
        int c = k / 3, j = k % 3;
        float w = w_in[o * 64 + c];
        __nv_bfloat16 hi = __float2bfloat16(w);
        if (j == 2) g_a2[i] = __float2bfloat16(w - __bfloat162float(hi));
        else        g_a2[i] = hi;
    }
}

// ---------------- x split + transpose: x[b][c][p] -> X2[b][p][192] -----------
// k = 3c+j : j=0 -> x_hi, j=1 -> x_lo, j=2 -> x_hi
__global__ __launch_bounds__(256) void split192(const float* __restrict__ x) {
    __shared__ float tile[64][65];
    const int tid = threadIdx.x;
    const int pbase = blockIdx.x * 64, b = blockIdx.y;
    const float* xb = x + (size_t)b * 64 * NPIX;

#pragma unroll
    for (int e = 0; e < 4096; e += 256) {
        int i = e + tid;
        int ch = i >> 6, px = i & 63;
        tile[ch][px] = xb[(size_t)ch * NPIX + pbase + px];
    }
    __syncthreads();

    __nv_bfloat16* out = g_x2 + ((size_t)b * NPIX + pbase) * 192;
#pragma unroll
    for (int e = 0; e < 6144; e += 256) {
        int i = e + tid;
        int p = i / 96, u = i % 96;
        uint32_t w = 0;
#pragma unroll
        for (int h = 0; h < 2; ++h) {
            int k = 2 * u + h;
            int c = k / 3, j = k % 3;
            float xv = tile[c][p];
            __nv_bfloat16 hi = __float2bfloat16(xv);
            __nv_bfloat16 val;
            if (j == 1) val = __float2bfloat16(xv - __bfloat162float(hi));
            else        val = hi;
            unsigned short bits = *(unsigned short*)&val;
            w |= (uint32_t)bits << (16 * h);
        }
        *(uint32_t*)(out + p * 192 + u * 2) = w;
    }
}

// ---------------- tensor-core gemm1, cp.async double-buffered ----------------
// CTA: M=128 outs x N=128 px x K=192, 4 K-chunks of 48, 2-stage pipeline.
// 8 warps = 4(m) x 2(n); warp tile 32x64. Rows padded to 112B (ldmatrix
// conflict-free: 8-row slab banks = 28r mod 32, all distinct).
// grid (NPIX/128, 2, BATCH), block 256. dyn smem = 2*(14336+14336) = 57344.
#define G1_RB     112                   // bytes per padded row (96 data)
#define G1_ARR    (128 * G1_RB)         // 14336 per array per stage
#define G1_STAGE  (2 * G1_ARR)          // A + B
#define G1_SMEM   (2 * G1_STAGE)        // 57344
__global__ __launch_bounds__(256, 2) void gemm1_mma() {
    extern __shared__ char sm[];
    const int tid = threadIdx.x, wid = tid >> 5, lane = tid & 31;
    const int pbase = blockIdx.x * 128;
    const int obase = blockIdx.y * 128;
    const int b = blockIdx.z;
    const int warpM = wid & 3, warpN = wid >> 2;

    const uint32_t smem_base = smem_to_u32(sm);
    const char* Agl = (const char*)(g_a2 + (size_t)obase * 192);
    const char* Xgl = (const char*)(g_x2 + ((size_t)b * NPIX + pbase) * 192);

    // prefetch helper: thread tid copies 3 slabs of A and 3 of B per chunk.
    // unit u in [0,768): row = u/6, slab = u%6. global row stride 384B.
    auto prefetch = [&](int chunk, int stage) {
        uint32_t abase = smem_base + stage * G1_STAGE;
        uint32_t bbase = abase + G1_ARR;
        int goff = chunk * 96;
#pragma unroll
        for (int e = 0; e < 768; e += 256) {
            int u = e + tid;
            int r = u / 6, s = u % 6;
            cp16(abase + r * G1_RB + s * 16, Agl + r * 384 + goff + s * 16);
        }
#pragma unroll
        for (int e = 0; e < 768; e += 256) {
            int u = e + tid;
            int r = u / 6, s = u % 6;
            cp16(bbase + r * G1_RB + s * 16, Xgl + r * 384 + goff + s * 16);
        }
    };

    const int lrow = lane & 15;
    const int lkh  = (lane >> 4) * 8;

    float acc[2][8][4];
#pragma unroll
    for (int mi = 0; mi < 2; ++mi)
#pragma unroll
        for (int ni = 0; ni < 8; ++ni)
#pragma unroll
            for (int r = 0; r < 4; ++r) acc[mi][ni][r] = 0.f;

    prefetch(0, 0);
    CP_COMMIT();

#pragma unroll
    for (int c = 0; c < 4; ++c) {
        if (c < 3) { prefetch(c + 1, (c + 1) & 1); CP_COMMIT(); }
        if (c < 3) CP_WAIT(1); else CP_WAIT(0);
        __syncthreads();

        uint32_t abase = smem_base + (c & 1) * G1_STAGE;
        uint32_t bbase = abase + G1_ARR;
#pragma unroll
        for (int ksl = 0; ksl < 3; ++ksl) {
            uint32_t a[2][4];
#pragma unroll
            for (int mi = 0; mi < 2; ++mi) {
                uint32_t addr = abase + (warpM * 32 + mi * 16 + lrow) * G1_RB + ksl * 32 + lkh * 2;
                ldsm_x4(a[mi][0], a[mi][1], a[mi][2], a[mi][3], addr);
            }
            uint32_t bf[8][2];
#pragma unroll
            for (int nq = 0; nq < 4; ++nq) {
                uint32_t r0, r1, r2, r3;
                uint32_t addr = bbase + (warpN * 64 + nq * 16 + lrow) * G1_RB + ksl * 32 + lkh * 2;
                ldsm_x4(r0, r1, r2, r3, addr);
                bf[2 * nq][0] = r0;     bf[2 * nq][1] = r2;
                bf[2 * nq + 1][0] = r1; bf[2 * nq + 1][1] = r3;
            }
#pragma unroll
            for (int mi = 0; mi < 2; ++mi)
#pragma unroll
                for (int ni = 0; ni < 8; ++ni)
                    mma_bf16(acc[mi][ni], a[mi], bf[ni]);
        }
        __syncthreads();   // buffer reuse barrier (chunk c+2 prefetch)
    }

    // epilogue: thread holds D rows g, g+8; cols T*2, T*2+1 (+8*ni)
    const int g = lane >> 2, T = lane & 3;
#pragma unroll
    for (int mi = 0; mi < 2; ++mi) {
        int m = obase + warpM * 32 + mi * 16 + g;
        float* rowp = g_t + ((size_t)b * 256 + m) * NPIX + pbase + warpN * 64 + T * 2;
#pragma unroll
        for (int ni = 0; ni < 8; ++ni) {
            *(u64*)(rowp + ni * 8) = pack2(acc[mi][ni][0], acc[mi][ni][1]);
            *(u64*)(rowp + ni * 8 + (size_t)8 * NPIX) = pack2(acc[mi][ni][2], acc[mi][ni][3]);
        }
    }
}

// ---------------- depthwise 3x3 conv (SAME, zero pad) + gate -----------------
__global__ __launch_bounds__(256) void conv_mul(const float* __restrict__ w_dw)
{
    __shared__ float st[34][258];
    const int col = threadIdx.x;
    const int jj = blockIdx.y, b = blockIdx.z, r0 = blockIdx.x * 32;

    const float* t1 = g_t + ((size_t)b * 256 + jj) * NPIX;
    const float* t2 = g_t + ((size_t)b * 256 + 128 + jj) * NPIX;
    float* outp = g_qv + ((size_t)b * 128 + jj) * NPIX;

    float wd[9];
#pragma unroll
    for (int i = 0; i < 9; ++i) wd[i] = w_dw[jj * 9 + i];

#pragma unroll
    for (int rr = 0; rr < 34; ++rr) {
        int row = r0 - 1 + rr;
        st[rr][col + 1] = (row >= 0 && row < 256) ? t1[row * 256 + col] : 0.f;
    }
    if (col == 0) {
#pragma unroll
        for (int rr = 0; rr < 34; ++rr) { st[rr][0] = 0.f; st[rr][257] = 0.f; }
    }
    __syncthreads();

#pragma unroll 4
    for (int r = 0; r < 32; ++r) {
        float s = 0.f;
#pragma unroll
        for (int ky = 0; ky < 3; ++ky)
#pragma unroll
            for (int kx = 0; kx < 3; ++kx)
                s += wd[ky * 3 + kx] * st[r + ky][col + kx];
        int p = (r0 + r) * 256 + col;
        outp[p] = s * t2[p];
    }
}

// ---------------- gram + sumsq (round-4 version, unchanged) -------------------
__global__ __launch_bounds__(256, 3) void gram_kernel()
{
    __shared__ u64 qs2[64 * 33];
    __shared__ u64 vs2[64 * 33];
    float* qsf = (float*)qs2;
    float* vsf = (float*)vs2;

    const int tid = threadIdx.x;
    const int b = blockIdx.y;
    const int tx = tid & 15;
    const int ty = tid >> 4;
    const int cqs = tid & 63;
    const int pg2 = tid >> 6;

    const float* qsrc = g_qv + (size_t)b * 128 * NPIX;
    const float* vsrc = qsrc + (size_t)64 * NPIX;

    u64 acc[4][4];
#pragma unroll
    for (int i = 0; i < 4; ++i)
#pragma unroll
        for (int j = 0; j < 4; ++j) acc[i][j] = 0ULL;
    float ssq = 0.f, ssv = 0.f;

    for (int chunk = blockIdx.x; chunk < 1024; chunk += gridDim.x) {
        int pbase = chunk * 64;
        __syncthreads();
#pragma unroll
        for (int e = 0; e < 2048; e += 256) {
            int i = e + tid;
            int ch = i >> 5, pp = i & 31;
            qs2[ch * 33 + pp] = *(const u64*)(qsrc + (size_t)ch * NPIX + pbase + pp * 2);
            vs2[ch * 33 + pp] = *(const u64*)(vsrc + (size_t)ch * NPIX + pbase + pp * 2);
        }
        __syncthreads();
#pragma unroll 4
        for (int p = pg2 * 16; p < pg2 * 16 + 16; ++p) {
            float a = qsf[cqs * 66 + p]; ssq += a * a;
            float c = vsf[cqs * 66 + p]; ssv += c * c;
        }
#pragma unroll 2
        for (int pp = 0; pp < 32; ++pp) {
            u64 qv_[4], vv_[4];
#pragma unroll
            for (int i = 0; i < 4; ++i) qv_[i] = qs2[(ty + 16 * i) * 33 + pp];
#pragma unroll
            for (int j = 0; j < 4; ++j) vv_[j] = vs2[(tx + 16 * j) * 33 + pp];
#pragma unroll
            for (int i = 0; i < 4; ++i)
#pragma unroll
                for (int j = 0; j < 4; ++j)
                    acc[i][j] = ffma2(qv_[i], vv_[j], acc[i][j]);
        }
    }
    atomicAdd(&g_sumsq[b * 128 + cqs], ssq);
    atomicAdd(&g_sumsq[b * 128 + 64 + cqs], ssv);
#pragma unroll
    for (int i = 0; i < 4; ++i)
#pragma unroll
        for (int j = 0; j < 4; ++j) {
            float lo, hi;
            unpack2(acc[i][j], lo, hi);
            atomicAdd(&g_gram[b * 4096 + (ty + 16 * i) * 64 + (tx + 16 * j)], lo + hi);
        }
}

// ---------------- norms + softmax + M = w_out @ attn --------------------------
__global__ __launch_bounds__(256) void attn_kernel(
    const float* __restrict__ w_out, const float* __restrict__ temp_p)
{
    __shared__ float attn_s[64 * 65];
    __shared__ float wo_s[64 * 65];
    __shared__ float nrm[128];
    const int tid = threadIdx.x, b = blockIdx.x;

    if (tid < 128) nrm[tid] = fmaxf(sqrtf(g_sumsq[b * 128 + tid]), 1e-12f);
    for (int e = tid; e < 4096; e += 256) {
        int o = e >> 6, c = e & 63;
        wo_s[c * 65 + o] = w_out[e];
    }
    __syncthreads();

    const float temp = *temp_p;
    if (tid < 64) {
        int c = tid;
        float inq = temp / nrm[c];
        float mx = -1e30f;
        for (int d = 0; d < 64; ++d) {
            float l = g_gram[b * 4096 + c * 64 + d] * (inq / nrm[64 + d]);
            attn_s[c * 65 + d] = l;
            mx = fmaxf(mx, l);
        }
        float sum = 0.f;
        for (int d = 0; d < 64; ++d) {
            float e_ = expf(attn_s[c * 65 + d] - mx);
            attn_s[c * 65 + d] = e_;
            sum += e_;
        }
        float inv = 1.f / sum;
        for (int d = 0; d < 64; ++d) attn_s[c * 65 + d] *= inv;
    }
    __syncthreads();

    const int o = tid & 63, dg = tid >> 6;
    for (int d = dg * 16; d < dg * 16 + 16; ++d) {
        float m = 0.f;
#pragma unroll 8
        for (int c2 = 0; c2 < 64; ++c2) m += wo_s[c2 * 65 + o] * attn_s[c2 * 65 + d];
        g_M[b * 4096 + o * 64 + d] = m;
    }
}

// ---------------- scalar K=64 GEMM (for gemm2 only) ---------------------------
__global__ __launch_bounds__(256, 2) void gemm_k64(
    const float* __restrict__ W, size_t wBatch,
    const float* __restrict__ X, size_t xBatch,
    float* __restrict__ Y, size_t yBatch)
{
    __shared__ u64 xs2[16 * 128];
    __shared__ u64 ws2[16 * 64];
    float* xsf = (float*)xs2;

    const int tid = threadIdx.x;
    const int tp = tid & 31;
    const int to = tid >> 5;
    const int b = blockIdx.z;
    const int pbase = blockIdx.x * 256;
    const int obase = blockIdx.y * 64;

    const float* Wb = W + (size_t)b * wBatch + (size_t)obase * 64;
    const float* Xb = X + (size_t)b * xBatch;
    float*       Yb = Y + (size_t)b * yBatch + (size_t)obase * NPIX;

    u64 acc[8][4];
#pragma unroll
    for (int j = 0; j < 8; ++j)
#pragma unroll
        for (int k = 0; k < 4; ++k) acc[j][k] = 0ULL;

    for (int cc = 0; cc < 64; cc += 16) {
        __syncthreads();
#pragma unroll
        for (int e = 0; e < 1024; e += 256) {
            int i = e + tid;
            int ch = i >> 6, p4 = i & 63;
            ((float4*)xsf)[ch * 64 + p4] =
                *(const float4*)(Xb + (size_t)(cc + ch) * NPIX + pbase + p4 * 4);
        }
#pragma unroll
        for (int e = 0; e < 1024; e += 256) {
            int i = e + tid;
            int o = i >> 4, cl = i & 15;
            float wv = Wb[(size_t)o * 64 + cc + cl];
            ws2[cl * 64 + o] = pack2(wv, wv);
        }
        __syncthreads();
#pragma unroll
        for (int c = 0; c < 16; ++c) {
            u64 xv[4];
            const u64* xr = xs2 + c * 128 + tp;
#pragma unroll
            for (int k = 0; k < 4; ++k) xv[k] = xr[32 * k];
            const u64* wr = ws2 + c * 64 + to * 8;
#pragma unroll
            for (int j = 0; j < 8; ++j) {
                u64 w2 = wr[j];
#pragma unroll
                for (int k = 0; k < 4; ++k)
                    acc[j][k] = ffma2(w2, xv[k], acc[j][k]);
            }
        }
    }
#pragma unroll
    for (int j = 0; j < 8; ++j) {
        float* yp = Yb + (size_t)(to * 8 + j) * NPIX + pbase + tp * 2;
#pragma unroll
        for (int k = 0; k < 4; ++k)
            *reinterpret_cast<u64*>(yp + 64 * k) = acc[j][k];
    }
}

// ---------------- launch ------------------------------------------------------
extern "C" void kernel_launch(void* const* d_in, const int* in_sizes, int n_in,
                              void* d_out, int out_size)
{
    const float* x      = (const float*)d_in[0];
    const float* w_in   = (const float*)d_in[1];
    const float* w_dw   = (const float*)d_in[2];
    const float* w_out  = (const float*)d_in[3];
    const float* temp   = (const float*)d_in[4];
    float* out = (float*)d_out;

    float *qv_ptr = nullptr, *M_ptr = nullptr;
    cudaGetSymbolAddress((void**)&qv_ptr, g_qv);
    cudaGetSymbolAddress((void**)&M_ptr,  g_M);

    cudaFuncSetAttribute(gemm1_mma, cudaFuncAttributeMaxDynamicSharedMemorySize, G1_SMEM);

    zero_stats<<<1, 256>>>();
    wsplit<<<64, 256>>>(w_in);
    split192<<<dim3(NPIX / 64, BATCH), 256>>>(x);

    // t = w_in @ x  on tensor cores (bf16-split, K=192, cp.async pipelined)
    gemm1_mma<<<dim3(NPIX / 128, 2, BATCH), 256, G1_SMEM>>>();

    // depthwise conv + gate -> qv
    conv_mul<<<dim3(8, 128, BATCH), 256>>>(w_dw);

    // gram + sumsq
    gram_kernel<<<dim3(128, BATCH), 256>>>();

    // norms, softmax, M = w_out @ attn
    attn_kernel<<<BATCH, 256>>>(w_out, temp);

    // out = M @ v   (scalar f32x2 path)
    gemm_k64<<<dim3(NPIX / 256, 1, BATCH), 256>>>(
        M_ptr, 4096, qv_ptr + (size_t)64 * NPIX, (size_t)128 * NPIX,
        out, (size_t)64 * NPIX);
}

// round 8
// speedup vs baseline: 1.3163x; 1.0449x over previous
#include <cuda_runtime.h>
#include <cuda_bf16.h>
#include <math.h>
#include <stdint.h>

typedef unsigned long long u64;

#define NPIX  65536   // 256*256
#define BATCH 4

// ---------------- scratch (device globals: allocation is forbidden) -----------
__device__ float g_t[(size_t)BATCH * 256 * NPIX];     // 256 MB : t = w_in @ x
__device__ float g_qv[(size_t)BATCH * 128 * NPIX];    // 128 MB : q, v
__device__ __nv_bfloat16 g_a2[256 * 192];             // bf16-split w_in, [o][192]
__device__ float g_sumsq[BATCH * 128];
__device__ float g_gram[BATCH * 64 * 64];
__device__ float g_M[BATCH * 64 * 64];

// ---------------- f32x2 helpers ----------------------------------------------
__device__ __forceinline__ u64 ffma2(u64 a, u64 b, u64 c) {
    u64 d;
    asm("fma.rn.f32x2 %0, %1, %2, %3;" : "=l"(d) : "l"(a), "l"(b), "l"(c));
    return d;
}
__device__ __forceinline__ u64 pack2(float x, float y) {
    u64 d;
    asm("mov.b64 %0, {%1, %2};" : "=l"(d) : "f"(x), "f"(y));
    return d;
}
__device__ __forceinline__ void unpack2(u64 v, float& x, float& y) {
    asm("mov.b64 {%0, %1}, %2;" : "=f"(x), "=f"(y) : "l"(v));
}

// ---------------- mma.sync / cp.async helpers (baseline PTX) ------------------
__device__ __forceinline__ uint32_t smem_to_u32(const void* p) {
    uint32_t a;
    asm("{ .reg .u64 t; cvta.to.shared.u64 t, %1; cvt.u32.u64 %0, t; }" : "=r"(a) : "l"(p));
    return a;
}
__device__ __forceinline__ void ldsm_x4(uint32_t& r0, uint32_t& r1, uint32_t& r2, uint32_t& r3,
                                        uint32_t addr) {
    asm volatile("ldmatrix.sync.aligned.m8n8.x4.shared.b16 {%0,%1,%2,%3}, [%4];"
        : "=r"(r0), "=r"(r1), "=r"(r2), "=r"(r3) : "r"(addr));
}
__device__ __forceinline__ void mma_bf16(float* d, const uint32_t* a, const uint32_t* b) {
    asm volatile("mma.sync.aligned.m16n8k16.row.col.f32.bf16.bf16.f32 "
        "{%0,%1,%2,%3}, {%4,%5,%6,%7}, {%8,%9}, {%0,%1,%2,%3};"
        : "+f"(d[0]), "+f"(d[1]), "+f"(d[2]), "+f"(d[3])
        : "r"(a[0]), "r"(a[1]), "r"(a[2]), "r"(a[3]), "r"(b[0]), "r"(b[1]));
}
__device__ __forceinline__ void cp16(uint32_t smem_addr, const void* gptr) {
    asm volatile("cp.async.cg.shared.global [%0], [%1], 16;" :: "r"(smem_addr), "l"(gptr));
}
#define CP_COMMIT() asm volatile("cp.async.commit_group;" ::: "memory")
#define CP_WAIT(n)  asm volatile("cp.async.wait_group %0;" :: "n"(n) : "memory")

__device__ __forceinline__ unsigned short bfbits(float v) {
    __nv_bfloat16 h = __float2bfloat16(v);
    return *(unsigned short*)&h;
}
// low 16 = element k (a), high 16 = element k+1 (b)
__device__ __forceinline__ uint32_t bfpair(float a, float b) {
    return (uint32_t)bfbits(a) | ((uint32_t)bfbits(b) << 16);
}

// ---------------- zero the accumulators --------------------------------------
__global__ void zero_stats() {
    for (int i = threadIdx.x; i < BATCH * 128 + BATCH * 64 * 64; i += blockDim.x) {
        if (i < BATCH * 128) g_sumsq[i] = 0.f;
        else                 g_gram[i - BATCH * 128] = 0.f;
    }
}

// ---------------- weight split: w_in[256][64] -> A2[256][192] bf16 -----------
// k = 3c+j : j=0 -> w_hi, j=1 -> w_hi, j=2 -> w_lo
__global__ void wsplit(const float* __restrict__ w_in) {
    for (int i = threadIdx.x + blockIdx.x * blockDim.x; i < 256 * 192; i += blockDim.x * gridDim.x) {
        int o = i / 192, k = i % 192;
        int c = k / 3, j = k % 3;
        float w = w_in[o * 64 + c];
        __nv_bfloat16 hi = __float2bfloat16(w);
        if (j == 2) g_a2[i] = __float2bfloat16(w - __bfloat162float(hi));
        else        g_a2[i] = hi;
    }
}

// ---------------- fused split + tensor-core gemm1 ----------------------------
// t = w_in @ x with bf16-split (K=192 = 3 per channel: hiW*hiX, hiW*loX, loW*hiX).
// CTA: M=256 (ALL outputs) x N=64 px x K=192 in 4 chunks of 48 (16 channels).
// Per chunk: cp.async A-chunk (bf16) + raw x fp32; in-kernel convert builds B.
// 8 warps, warp = 32 rows x 64 px, acc 64 regs. Double buffered.
// Rows padded to 112B -> ldmatrix conflict-free (28r mod 32 distinct).
// grid (NPIX/64, 1, BATCH), block 256.
#define G1_RB      112                        // padded row bytes (96 data)
#define G1_A_ARR   (256 * G1_RB)              // 28672
#define G1_B_ARR   (64 * G1_RB)               // 7168
#define G1_X_RB    272                        // xstage row bytes (64*4=256 data, 16B-aligned pad)
#define G1_X_ARR   (16 * G1_X_RB)             // 4352
#define G1_STAGE   (G1_A_ARR + G1_B_ARR + G1_X_ARR)   // 40192
#define G1_SMEM    (2 * G1_STAGE)             // 80384
__global__ __launch_bounds__(256, 2) void gemm1_fused(const float* __restrict__ x) {
    extern __shared__ char sm[];
    const int tid = threadIdx.x, wid = tid >> 5, lane = tid & 31;
    const int pbase = blockIdx.x * 64;
    const int b = blockIdx.z;
    const int warpM = wid;                    // 8 warps x 32 rows = 256 outs

    const uint32_t smem_base = smem_to_u32(sm);
    const char*  Agl = (const char*)g_a2;                       // [256][192] bf16
    const float* xb  = x + (size_t)b * 64 * NPIX + pbase;

    // stage bases
    auto a_base = [&](int s) { return smem_base + s * G1_STAGE; };
    auto b_base = [&](int s) { return smem_base + s * G1_STAGE + G1_A_ARR; };
    auto x_base = [&](int s) { return smem_base + s * G1_STAGE + G1_A_ARR + G1_B_ARR; };

    // prefetch chunk (A bf16 rows + raw x channels) into stage s
    auto prefetch = [&](int chunk, int s) {
        const int goff = chunk * 96;          // byte offset into 384B A row
        uint32_t ab = a_base(s);
#pragma unroll
        for (int e = 0; e < 1536; e += 256) { // 256 rows x 6 slabs
            int u = e + tid;
            int r = u / 6, sl = u % 6;
            cp16(ab + r * G1_RB + sl * 16, Agl + r * 384 + goff + sl * 16);
        }
        uint32_t xbs = x_base(s);
        {                                     // 16 ch x 16 slabs = 256 units
            int ch = tid >> 4, sl = tid & 15;
            cp16(xbs + ch * G1_X_RB + sl * 16,
                 xb + (size_t)(chunk * 16 + ch) * NPIX + sl * 4);
        }
    };

    const int lrow = lane & 15;
    const int lkh  = (lane >> 4) * 8;

    float acc[2][8][4];
#pragma unroll
    for (int mi = 0; mi < 2; ++mi)
#pragma unroll
        for (int ni = 0; ni < 8; ++ni)
#pragma unroll
            for (int r = 0; r < 4; ++r) acc[mi][ni][r] = 0.f;

    prefetch(0, 0);
    CP_COMMIT();

#pragma unroll
    for (int c = 0; c < 4; ++c) {
        const int s = c & 1;
        if (c < 3) { prefetch(c + 1, s ^ 1); CP_COMMIT(); }
        if (c < 3) CP_WAIT(1); else CP_WAIT(0);
        __syncthreads();

        // convert: build B rows [64 px][48 k] from raw x chunk
        {
            const float* xs = (const float*)(sm + s * G1_STAGE + G1_A_ARR + G1_B_ARR);
            char* Bs = sm + s * G1_STAGE + G1_A_ARR;
#pragma unroll
            for (int e = 0; e < 512; e += 256) {
                int u = e + tid;
                int p = u & 63, cp = u >> 6;           // cp = channel pair 0..7
                float x0 = xs[(2 * cp) * 68 + p];
                float x1 = xs[(2 * cp + 1) * 68 + p];
                float h0 = __bfloat162float(__float2bfloat16(x0));
                float h1 = __bfloat162float(__float2bfloat16(x1));
                float l0 = x0 - h0, l1 = x1 - h1;
                uint32_t* row = (uint32_t*)(Bs + p * G1_RB + cp * 12);
                row[0] = bfpair(h0, l0);   // k=6cp   : xhi(c0), xlo(c0)
                row[1] = bfpair(h0, h1);   // k=6cp+2 : xhi(c0), xhi(c1)
                row[2] = bfpair(l1, h1);   // k=6cp+4 : xlo(c1), xhi(c1)
            }
        }
        __syncthreads();

        // compute 3 k-steps of 16
        uint32_t ab = a_base(s), bb = b_base(s);
#pragma unroll
        for (int ksl = 0; ksl < 3; ++ksl) {
            uint32_t a[2][4];
#pragma unroll
            for (int mi = 0; mi < 2; ++mi) {
                uint32_t addr = ab + (warpM * 32 + mi * 16 + lrow) * G1_RB + ksl * 32 + lkh * 2;
                ldsm_x4(a[mi][0], a[mi][1], a[mi][2], a[mi][3], addr);
            }
            uint32_t bf[8][2];
#pragma unroll
            for (int nq = 0; nq < 4; ++nq) {
                uint32_t r0, r1, r2, r3;
                uint32_t addr = bb + (nq * 16 + lrow) * G1_RB + ksl * 32 + lkh * 2;
                ldsm_x4(r0, r1, r2, r3, addr);
                bf[2 * nq][0] = r0;     bf[2 * nq][1] = r2;
                bf[2 * nq + 1][0] = r1; bf[2 * nq + 1][1] = r3;
            }
#pragma unroll
            for (int mi = 0; mi < 2; ++mi)
#pragma unroll
                for (int ni = 0; ni < 8; ++ni)
                    mma_bf16(acc[mi][ni], a[mi], bf[ni]);
        }
        __syncthreads();   // protect stage reuse by next prefetch/convert
    }

    // epilogue: thread holds D rows g, g+8; cols T*2, T*2+1 (+8*ni)
    const int g = lane >> 2, T = lane & 3;
#pragma unroll
    for (int mi = 0; mi < 2; ++mi) {
        int m = warpM * 32 + mi * 16 + g;
        float* rowp = g_t + ((size_t)b * 256 + m) * NPIX + pbase + T * 2;
#pragma unroll
        for (int ni = 0; ni < 8; ++ni) {
            *(u64*)(rowp + ni * 8) = pack2(acc[mi][ni][0], acc[mi][ni][1]);
            *(u64*)(rowp + ni * 8 + (size_t)8 * NPIX) = pack2(acc[mi][ni][2], acc[mi][ni][3]);
        }
    }
}

// ---------------- depthwise 3x3 conv (SAME, zero pad) + gate -----------------
__global__ __launch_bounds__(256) void conv_mul(const float* __restrict__ w_dw)
{
    __shared__ float st[34][258];
    const int col = threadIdx.x;
    const int jj = blockIdx.y, b = blockIdx.z, r0 = blockIdx.x * 32;

    const float* t1 = g_t + ((size_t)b * 256 + jj) * NPIX;
    const float* t2 = g_t + ((size_t)b * 256 + 128 + jj) * NPIX;
    float* outp = g_qv + ((size_t)b * 128 + jj) * NPIX;

    float wd[9];
#pragma unroll
    for (int i = 0; i < 9; ++i) wd[i] = w_dw[jj * 9 + i];

#pragma unroll
    for (int rr = 0; rr < 34; ++rr) {
        int row = r0 - 1 + rr;
        st[rr][col + 1] = (row >= 0 && row < 256) ? t1[row * 256 + col] : 0.f;
    }
    if (col == 0) {
#pragma unroll
        for (int rr = 0; rr < 34; ++rr) { st[rr][0] = 0.f; st[rr][257] = 0.f; }
    }
    __syncthreads();

#pragma unroll 4
    for (int r = 0; r < 32; ++r) {
        float s = 0.f;
#pragma unroll
        for (int ky = 0; ky < 3; ++ky)
#pragma unroll
            for (int kx = 0; kx < 3; ++kx)
                s += wd[ky * 3 + kx] * st[r + ky][col + kx];
        int p = (r0 + r) * 256 + col;
        outp[p] = s * t2[p];
    }
}

// ---------------- gram + sumsq ------------------------------------------------
__global__ __launch_bounds__(256, 3) void gram_kernel()
{
    __shared__ u64 qs2[64 * 33];
    __shared__ u64 vs2[64 * 33];
    float* qsf = (float*)qs2;
    float* vsf = (float*)vs2;

    const int tid = threadIdx.x;
    const int b = blockIdx.y;
    const int tx = tid & 15;
    const int ty = tid >> 4;
    const int cqs = tid & 63;
    const int pg2 = tid >> 6;

    const float* qsrc = g_qv + (size_t)b * 128 * NPIX;
    const float* vsrc = qsrc + (size_t)64 * NPIX;

    u64 acc[4][4];
#pragma unroll
    for (int i = 0; i < 4; ++i)
#pragma unroll
        for (int j = 0; j < 4; ++j) acc[i][j] = 0ULL;
    float ssq = 0.f, ssv = 0.f;

    for (int chunk = blockIdx.x; chunk < 1024; chunk += gridDim.x) {
        int pbase = chunk * 64;
        __syncthreads();
#pragma unroll
        for (int e = 0; e < 2048; e += 256) {
            int i = e + tid;
            int ch = i >> 5, pp = i & 31;
            qs2[ch * 33 + pp] = *(const u64*)(qsrc + (size_t)ch * NPIX + pbase + pp * 2);
            vs2[ch * 33 + pp] = *(const u64*)(vsrc + (size_t)ch * NPIX + pbase + pp * 2);
        }
        __syncthreads();
#pragma unroll 4
        for (int p = pg2 * 16; p < pg2 * 16 + 16; ++p) {
            float a = qsf[cqs * 66 + p]; ssq += a * a;
            float c = vsf[cqs * 66 + p]; ssv += c * c;
        }
#pragma unroll 2
        for (int pp = 0; pp < 32; ++pp) {
            u64 qv_[4], vv_[4];
#pragma unroll
            for (int i = 0; i < 4; ++i) qv_[i] = qs2[(ty + 16 * i) * 33 + pp];
#pragma unroll
            for (int j = 0; j < 4; ++j) vv_[j] = vs2[(tx + 16 * j) * 33 + pp];
#pragma unroll
            for (int i = 0; i < 4; ++i)
#pragma unroll
                for (int j = 0; j < 4; ++j)
                    acc[i][j] = ffma2(qv_[i], vv_[j], acc[i][j]);
        }
    }
    atomicAdd(&g_sumsq[b * 128 + cqs], ssq);
    atomicAdd(&g_sumsq[b * 128 + 64 + cqs], ssv);
#pragma unroll
    for (int i = 0; i < 4; ++i)
#pragma unroll
        for (int j = 0; j < 4; ++j) {
            float lo, hi;
            unpack2(acc[i][j], lo, hi);
            atomicAdd(&g_gram[b * 4096 + (ty + 16 * i) * 64 + (tx + 16 * j)], lo + hi);
        }
}

// ---------------- norms + softmax + M = w_out @ attn --------------------------
__global__ __launch_bounds__(256) void attn_kernel(
    const float* __restrict__ w_out, const float* __restrict__ temp_p)
{
    __shared__ float attn_s[64 * 65];
    __shared__ float wo_s[64 * 65];
    __shared__ float nrm[128];
    const int tid = threadIdx.x, b = blockIdx.x;

    if (tid < 128) nrm[tid] = fmaxf(sqrtf(g_sumsq[b * 128 + tid]), 1e-12f);
    for (int e = tid; e < 4096; e += 256) {
        int o = e >> 6, c = e & 63;
        wo_s[c * 65 + o] = w_out[e];
    }
    __syncthreads();

    const float temp = *temp_p;
    if (tid < 64) {
        int c = tid;
        float inq = temp / nrm[c];
        float mx = -1e30f;
        for (int d = 0; d < 64; ++d) {
            float l = g_gram[b * 4096 + c * 64 + d] * (inq / nrm[64 + d]);
            attn_s[c * 65 + d] = l;
            mx = fmaxf(mx, l);
        }
        float sum = 0.f;
        for (int d = 0; d < 64; ++d) {
            float e_ = expf(attn_s[c * 65 + d] - mx);
            attn_s[c * 65 + d] = e_;
            sum += e_;
        }
        float inv = 1.f / sum;
        for (int d = 0; d < 64; ++d) attn_s[c * 65 + d] *= inv;
    }
    __syncthreads();

    const int o = tid & 63, dg = tid >> 6;
    for (int d = dg * 16; d < dg * 16 + 16; ++d) {
        float m = 0.f;
#pragma unroll 8
        for (int c2 = 0; c2 < 64; ++c2) m += wo_s[c2 * 65 + o] * attn_s[c2 * 65 + d];
        g_M[b * 4096 + o * 64 + d] = m;
    }
}

// ---------------- scalar K=64 GEMM (for gemm2 only) ---------------------------
__global__ __launch_bounds__(256, 2) void gemm_k64(
    const float* __restrict__ W, size_t wBatch,
    const float* __restrict__ X, size_t xBatch,
    float* __restrict__ Y, size_t yBatch)
{
    __shared__ u64 xs2[16 * 128];
    __shared__ u64 ws2[16 * 64];
    float* xsf = (float*)xs2;

    const int tid = threadIdx.x;
    const int tp = tid & 31;
    const int to = tid >> 5;
    const int b = blockIdx.z;
    const int pbase = blockIdx.x * 256;
    const int obase = blockIdx.y * 64;

    const float* Wb = W + (size_t)b * wBatch + (size_t)obase * 64;
    const float* Xb = X + (size_t)b * xBatch;
    float*       Yb = Y + (size_t)b * yBatch + (size_t)obase * NPIX;

    u64 acc[8][4];
#pragma unroll
    for (int j = 0; j < 8; ++j)
#pragma unroll
        for (int k = 0; k < 4; ++k) acc[j][k] = 0ULL;

    for (int cc = 0; cc < 64; cc += 16) {
        __syncthreads();
#pragma unroll
        for (int e = 0; e < 1024; e += 256) {
            int i = e + tid;
            int ch = i >> 6, p4 = i & 63;
            ((float4*)xsf)[ch * 64 + p4] =
                *(const float4*)(Xb + (size_t)(cc + ch) * NPIX + pbase + p4 * 4);
        }
#pragma unroll
        for (int e = 0; e < 1024; e += 256) {
            int i = e + tid;
            int o = i >> 4, cl = i & 15;
            float wv = Wb[(size_t)o * 64 + cc + cl];
            ws2[cl * 64 + o] = pack2(wv, wv);
        }
        __syncthreads();
#pragma unroll
        for (int c = 0; c < 16; ++c) {
            u64 xv[4];
            const u64* xr = xs2 + c * 128 + tp;
#pragma unroll
            for (int k = 0; k < 4; ++k) xv[k] = xr[32 * k];
            const u64* wr = ws2 + c * 64 + to * 8;
#pragma unroll
            for (int j = 0; j < 8; ++j) {
                u64 w2 = wr[j];
#pragma unroll
                for (int k = 0; k < 4; ++k)
                    acc[j][k] = ffma2(w2, xv[k], acc[j][k]);
            }
        }
    }
#pragma unroll
    for (int j = 0; j < 8; ++j) {
        float* yp = Yb + (size_t)(to * 8 + j) * NPIX + pbase + tp * 2;
#pragma unroll
        for (int k = 0; k < 4; ++k)
            *reinterpret_cast<u64*>(yp + 64 * k) = acc[j][k];
    }
}

// ---------------- launch ------------------------------------------------------
extern "C" void kernel_launch(void* const* d_in, const int* in_sizes, int n_in,
                              void* d_out, int out_size)
{
    const float* x      = (const float*)d_in[0];
    const float* w_in   = (const float*)d_in[1];
    const float* w_dw   = (const float*)d_in[2];
    const float* w_out  = (const float*)d_in[3];
    const float* temp   = (const float*)d_in[4];
    float* out = (float*)d_out;

    float *qv_ptr = nullptr, *M_ptr = nullptr;
    cudaGetSymbolAddress((void**)&qv_ptr, g_qv);
    cudaGetSymbolAddress((void**)&M_ptr,  g_M);

    cudaFuncSetAttribute(gemm1_fused, cudaFuncAttributeMaxDynamicSharedMemorySize, G1_SMEM);

    zero_stats<<<1, 256>>>();
    wsplit<<<64, 256>>>(w_in);

    // t = w_in @ x  on tensor cores (fused bf16-split, K=192, cp.async pipelined)
    gemm1_fused<<<dim3(NPIX / 64, 1, BATCH), 256, G1_SMEM>>>(x);

    // depthwise conv + gate -> qv
    conv_mul<<<dim3(8, 128, BATCH), 256>>>(w_dw);

    // gram + sumsq
    gram_kernel<<<dim3(128, BATCH), 256>>>();

    // norms, softmax, M = w_out @ attn
    attn_kernel<<<BATCH, 256>>>(w_out, temp);

    // out = M @ v   (scalar f32x2 path)
    gemm_k64<<<dim3(NPIX / 256, 1, BATCH), 256>>>(
        M_ptr, 4096, qv_ptr + (size_t)64 * NPIX, (size_t)128 * NPIX,
        out, (size_t)64 * NPIX);
}

// round 9
// speedup vs baseline: 1.4934x; 1.1345x over previous
#include <cuda_runtime.h>
#include <cuda_bf16.h>
#include <math.h>
#include <stdint.h>

typedef unsigned long long u64;

#define NPIX  65536   // 256*256
#define BATCH 4

// ---------------- scratch (device globals: allocation is forbidden) -----------
__device__ float g_t[(size_t)BATCH * 256 * NPIX];     // 256 MB : t = w_in @ x
__device__ float g_qv[(size_t)BATCH * 128 * NPIX];    // 128 MB : q, v
__device__ __nv_bfloat16 g_a2[256 * 192];             // bf16-split w_in, [o][192]
__device__ float g_sumsq[BATCH * 128];
__device__ float g_gram[BATCH * 64 * 64];
__device__ float g_M[BATCH * 64 * 64];

// ---------------- f32x2 helpers ----------------------------------------------
__device__ __forceinline__ u64 ffma2(u64 a, u64 b, u64 c) {
    u64 d;
    asm("fma.rn.f32x2 %0, %1, %2, %3;" : "=l"(d) : "l"(a), "l"(b), "l"(c));
    return d;
}
__device__ __forceinline__ u64 pack2(float x, float y) {
    u64 d;
    asm("mov.b64 %0, {%1, %2};" : "=l"(d) : "f"(x), "f"(y));
    return d;
}

// ---------------- mma.sync / cp.async helpers (baseline PTX) ------------------
__device__ __forceinline__ uint32_t smem_to_u32(const void* p) {
    uint32_t a;
    asm("{ .reg .u64 t; cvta.to.shared.u64 t, %1; cvt.u32.u64 %0, t; }" : "=r"(a) : "l"(p));
    return a;
}
__device__ __forceinline__ void ldsm_x4(uint32_t& r0, uint32_t& r1, uint32_t& r2, uint32_t& r3,
                                        uint32_t addr) {
    asm volatile("ldmatrix.sync.aligned.m8n8.x4.shared.b16 {%0,%1,%2,%3}, [%4];"
        : "=r"(r0), "=r"(r1), "=r"(r2), "=r"(r3) : "r"(addr));
}
__device__ __forceinline__ void mma_bf16(float* d, const uint32_t* a, const uint32_t* b) {
    asm volatile("mma.sync.aligned.m16n8k16.row.col.f32.bf16.bf16.f32 "
        "{%0,%1,%2,%3}, {%4,%5,%6,%7}, {%8,%9}, {%0,%1,%2,%3};"
        : "+f"(d[0]), "+f"(d[1]), "+f"(d[2]), "+f"(d[3])
        : "r"(a[0]), "r"(a[1]), "r"(a[2]), "r"(a[3]), "r"(b[0]), "r"(b[1]));
}
__device__ __forceinline__ void cp16(uint32_t smem_addr, const void* gptr) {
    asm volatile("cp.async.cg.shared.global [%0], [%1], 16;" :: "r"(smem_addr), "l"(gptr));
}
#define CP_COMMIT() asm volatile("cp.async.commit_group;" ::: "memory")
#define CP_WAIT(n)  asm volatile("cp.async.wait_group %0;" :: "n"(n) : "memory")

__device__ __forceinline__ unsigned short bfbits(float v) {
    __nv_bfloat16 h = __float2bfloat16(v);
    return *(unsigned short*)&h;
}
__device__ __forceinline__ uint32_t bfpair(float a, float b) {
    return (uint32_t)bfbits(a) | ((uint32_t)bfbits(b) << 16);
}

// ---------------- zero the accumulators --------------------------------------
__global__ void zero_stats() {
    for (int i = threadIdx.x; i < BATCH * 128 + BATCH * 64 * 64; i += blockDim.x) {
        if (i < BATCH * 128) g_sumsq[i] = 0.f;
        else                 g_gram[i - BATCH * 128] = 0.f;
    }
}

// ---------------- weight split: w_in[256][64] -> A2[256][192] bf16 -----------
__global__ void wsplit(const float* __restrict__ w_in) {
    for (int i = threadIdx.x + blockIdx.x * blockDim.x; i < 256 * 192; i += blockDim.x * gridDim.x) {
        int o = i / 192, k = i % 192;
        int c = k / 3, j = k % 3;
        float w = w_in[o * 64 + c];
        __nv_bfloat16 hi = __float2bfloat16(w);
        if (j == 2) g_a2[i] = __float2bfloat16(w - __bfloat162float(hi));
        else        g_a2[i] = hi;
    }
}

// ---------------- fused split + tensor-core gemm1 (unchanged, round 8) -------
#define G1_RB      112
#define G1_A_ARR   (256 * G1_RB)
#define G1_B_ARR   (64 * G1_RB)
#define G1_X_RB    272
#define G1_X_ARR   (16 * G1_X_RB)
#define G1_STAGE   (G1_A_ARR + G1_B_ARR + G1_X_ARR)
#define G1_SMEM    (2 * G1_STAGE)
__global__ __launch_bounds__(256, 2) void gemm1_fused(const float* __restrict__ x) {
    extern __shared__ char sm[];
    const int tid = threadIdx.x, wid = tid >> 5, lane = tid & 31;
    const int pbase = blockIdx.x * 64;
    const int b = blockIdx.z;
    const int warpM = wid;

    const uint32_t smem_base = smem_to_u32(sm);
    const char*  Agl = (const char*)g_a2;
    const float* xb  = x + (size_t)b * 64 * NPIX + pbase;

    auto a_base = [&](int s) { return smem_base + s * G1_STAGE; };
    auto b_base = [&](int s) { return smem_base + s * G1_STAGE + G1_A_ARR; };
    auto x_base = [&](int s) { return smem_base + s * G1_STAGE + G1_A_ARR + G1_B_ARR; };

    auto prefetch = [&](int chunk, int s) {
        const int goff = chunk * 96;
        uint32_t ab = a_base(s);
#pragma unroll
        for (int e = 0; e < 1536; e += 256) {
            int u = e + tid;
            int r = u / 6, sl = u % 6;
            cp16(ab + r * G1_RB + sl * 16, Agl + r * 384 + goff + sl * 16);
        }
        uint32_t xbs = x_base(s);
        {
            int ch = tid >> 4, sl = tid & 15;
            cp16(xbs + ch * G1_X_RB + sl * 16,
                 xb + (size_t)(chunk * 16 + ch) * NPIX + sl * 4);
        }
    };

    const int lrow = lane & 15;
    const int lkh  = (lane >> 4) * 8;

    float acc[2][8][4];
#pragma unroll
    for (int mi = 0; mi < 2; ++mi)
#pragma unroll
        for (int ni = 0; ni < 8; ++ni)
#pragma unroll
            for (int r = 0; r < 4; ++r) acc[mi][ni][r] = 0.f;

    prefetch(0, 0);
    CP_COMMIT();

#pragma unroll
    for (int c = 0; c < 4; ++c) {
        const int s = c & 1;
        if (c < 3) { prefetch(c + 1, s ^ 1); CP_COMMIT(); }
        if (c < 3) CP_WAIT(1); else CP_WAIT(0);
        __syncthreads();

        {
            const float* xs = (const float*)(sm + s * G1_STAGE + G1_A_ARR + G1_B_ARR);
            char* Bs = sm + s * G1_STAGE + G1_A_ARR;
#pragma unroll
            for (int e = 0; e < 512; e += 256) {
                int u = e + tid;
                int p = u & 63, cp = u >> 6;
                float x0 = xs[(2 * cp) * 68 + p];
                float x1 = xs[(2 * cp + 1) * 68 + p];
                float h0 = __bfloat162float(__float2bfloat16(x0));
                float h1 = __bfloat162float(__float2bfloat16(x1));
                float l0 = x0 - h0, l1 = x1 - h1;
                uint32_t* row = (uint32_t*)(Bs + p * G1_RB + cp * 12);
                row[0] = bfpair(h0, l0);
                row[1] = bfpair(h0, h1);
                row[2] = bfpair(l1, h1);
            }
        }
        __syncthreads();

        uint32_t ab = a_base(s), bb = b_base(s);
#pragma unroll
        for (int ksl = 0; ksl < 3; ++ksl) {
            uint32_t a[2][4];
#pragma unroll
            for (int mi = 0; mi < 2; ++mi) {
                uint32_t addr = ab + (warpM * 32 + mi * 16 + lrow) * G1_RB + ksl * 32 + lkh * 2;
                ldsm_x4(a[mi][0], a[mi][1], a[mi][2], a[mi][3], addr);
            }
            uint32_t bf[8][2];
#pragma unroll
            for (int nq = 0; nq < 4; ++nq) {
                uint32_t r0, r1, r2, r3;
                uint32_t addr = bb + (nq * 16 + lrow) * G1_RB + ksl * 32 + lkh * 2;
                ldsm_x4(r0, r1, r2, r3, addr);
                bf[2 * nq][0] = r0;     bf[2 * nq][1] = r2;
                bf[2 * nq + 1][0] = r1; bf[2 * nq + 1][1] = r3;
            }
#pragma unroll
            for (int mi = 0; mi < 2; ++mi)
#pragma unroll
                for (int ni = 0; ni < 8; ++ni)
                    mma_bf16(acc[mi][ni], a[mi], bf[ni]);
        }
        __syncthreads();
    }

    const int g = lane >> 2, T = lane & 3;
#pragma unroll
    for (int mi = 0; mi < 2; ++mi) {
        int m = warpM * 32 + mi * 16 + g;
        float* rowp = g_t + ((size_t)b * 256 + m) * NPIX + pbase + T * 2;
#pragma unroll
        for (int ni = 0; ni < 8; ++ni) {
            *(u64*)(rowp + ni * 8) = pack2(acc[mi][ni][0], acc[mi][ni][1]);
            *(u64*)(rowp + ni * 8 + (size_t)8 * NPIX) = pack2(acc[mi][ni][2], acc[mi][ni][3]);
        }
    }
}

// ---------------- depthwise 3x3 conv + gate, float4 ---------------------------
// grid (8, 128, BATCH), block 256. Thread = 4 cols x 8 rows.
__global__ __launch_bounds__(256) void conv_mul(const float* __restrict__ w_dw)
{
    __shared__ float st[34][264];   // data at cols [4..259], halo [3] and [260]
    const int tid = threadIdx.x;
    const int jj = blockIdx.y, b = blockIdx.z, r0 = blockIdx.x * 32;

    const float* t1 = g_t + ((size_t)b * 256 + jj) * NPIX;
    const float* t2 = g_t + ((size_t)b * 256 + 128 + jj) * NPIX;
    float* outp = g_qv + ((size_t)b * 128 + jj) * NPIX;

    float wd[9];
#pragma unroll
    for (int i = 0; i < 9; ++i) wd[i] = w_dw[jj * 9 + i];

    // stage 34 rows x 256 cols as float4
#pragma unroll
    for (int e = 0; e < 2176; e += 256) {
        int u = e + tid;
        if (u < 2176) {
            int rr = u >> 6, q4 = u & 63;
            int row = r0 - 1 + rr;
            float4 v = make_float4(0.f, 0.f, 0.f, 0.f);
            if (row >= 0 && row < 256)
                v = *(const float4*)(t1 + row * 256 + q4 * 4);
            *(float4*)&st[rr][4 + q4 * 4] = v;
        }
    }
    if (tid < 34) { st[tid][3] = 0.f; st[tid][260] = 0.f; }
    __syncthreads();

    const int ty = tid >> 6, tc = tid & 63;
    const int c0 = tc * 4;
#pragma unroll
    for (int r = ty * 8; r < ty * 8 + 8; ++r) {
        float s0 = 0.f, s1 = 0.f, s2 = 0.f, s3 = 0.f;
#pragma unroll
        for (int ky = 0; ky < 3; ++ky) {
            const float* rowp = &st[r + ky][4 + c0];
            float4 m = *(const float4*)rowp;
            float left = rowp[-1], right = rowp[4];
            float w0 = wd[ky * 3 + 0], w1 = wd[ky * 3 + 1], w2 = wd[ky * 3 + 2];
            s0 += w0 * left + w1 * m.x + w2 * m.y;
            s1 += w0 * m.x  + w1 * m.y + w2 * m.z;
            s2 += w0 * m.y  + w1 * m.z + w2 * m.w;
            s3 += w0 * m.z  + w1 * m.w + w2 * right;
        }
        int p = (r0 + r) * 256 + c0;
        float4 g4 = *(const float4*)(t2 + p);
        float4 o = make_float4(s0 * g4.x, s1 * g4.y, s2 * g4.z, s3 * g4.w);
        *(float4*)(outp + p) = o;
    }
}

// ---------------- tensor-core gram + sumsq ------------------------------------
// G[cq,cv] = sum_p q*v via bf16-split: per pixel 3 K-slots, A=q:(hi,hi,lo),
// B=v:(hi,lo,hi). CTA = 64x64 output, chunks of 32 px (K=96), double-buffered
// cp.async raw fp32 staging + in-kernel convert; sumsq from raw during convert.
// 8 warps = 4(m:16 q-ch) x 2(n:32 v-ch). grid (128, BATCH).
#define GR_RB     208                  // bf16 row bytes (192 data, 52 u32)
#define GR_XRB    144                  // raw fp32 row bytes (128 data = 36 fl)
#define GR_A_OFF  0
#define GR_B_OFF  13312                // 64*208
#define GR_Q_OFF  26624
#define GR_V_OFF  35840                // + 64*144
#define GR_STAGE  45056
#define GR_SMEM   (2 * GR_STAGE)       // 90112
#define GR_CHUNKS 16                   // (NPIX/32)/128
__global__ __launch_bounds__(256, 2) void gram_mma()
{
    extern __shared__ char sm[];
    const int tid = threadIdx.x, wid = tid >> 5, lane = tid & 31;
    const int b = blockIdx.y;
    const int warpM = wid & 3, warpN = wid >> 2;

    const uint32_t smem_base = smem_to_u32(sm);
    const float* qsrc = g_qv + (size_t)b * 128 * NPIX;
    const float* vsrc = qsrc + (size_t)64 * NPIX;
    const int cbase = blockIdx.x * GR_CHUNKS;

    auto prefetch = [&](int ci, int s) {
        int pbase = (cbase + ci) * 32;
        uint32_t qb = smem_base + s * GR_STAGE + GR_Q_OFF;
        uint32_t vb = smem_base + s * GR_STAGE + GR_V_OFF;
#pragma unroll
        for (int e = 0; e < 512; e += 256) {
            int u = e + tid;
            int ch = u >> 3, sl = u & 7;
            cp16(qb + ch * GR_XRB + sl * 16, qsrc + (size_t)ch * NPIX + pbase + sl * 4);
        }
#pragma unroll
        for (int e = 0; e < 512; e += 256) {
            int u = e + tid;
            int ch = u >> 3, sl = u & 7;
            cp16(vb + ch * GR_XRB + sl * 16, vsrc + (size_t)ch * NPIX + pbase + sl * 4);
        }
    };

    const int lrow = lane & 15;
    const int lkh  = (lane >> 4) * 8;

    float acc[4][4];
#pragma unroll
    for (int ni = 0; ni < 4; ++ni)
#pragma unroll
        for (int r = 0; r < 4; ++r) acc[ni][r] = 0.f;
    float ssq = 0.f, ssv = 0.f;

    // convert mapping: ch = tid>>2, pixel pairs (tid&3)*4 .. +4 (8 px)
    const int cch = tid >> 2;
    const int ppr = (tid & 3) * 4;

    prefetch(0, 0);
    CP_COMMIT();

    for (int c = 0; c < GR_CHUNKS; ++c) {
        const int s = c & 1;
        if (c < GR_CHUNKS - 1) { prefetch(c + 1, s ^ 1); CP_COMMIT(); }
        if (c < GR_CHUNKS - 1) CP_WAIT(1); else CP_WAIT(0);
        __syncthreads();

        // convert raw -> Aq / Bv (and sumsq)
        {
            const float* rq = (const float*)(sm + s * GR_STAGE + GR_Q_OFF) + cch * 36;
            const float* rv = (const float*)(sm + s * GR_STAGE + GR_V_OFF) + cch * 36;
            uint32_t* aq = (uint32_t*)(sm + s * GR_STAGE + GR_A_OFF + cch * GR_RB) + ppr * 3;
            uint32_t* bv = (uint32_t*)(sm + s * GR_STAGE + GR_B_OFF + cch * GR_RB) + ppr * 3;
#pragma unroll
            for (int pr = 0; pr < 4; ++pr) {
                float q0 = rq[ppr * 2 + pr * 2], q1 = rq[ppr * 2 + pr * 2 + 1];
                float v0 = rv[ppr * 2 + pr * 2], v1 = rv[ppr * 2 + pr * 2 + 1];
                ssq += q0 * q0 + q1 * q1;
                ssv += v0 * v0 + v1 * v1;
                float qh0 = __bfloat162float(__float2bfloat16(q0));
                float qh1 = __bfloat162float(__float2bfloat16(q1));
                float vh0 = __bfloat162float(__float2bfloat16(v0));
                float vh1 = __bfloat162float(__float2bfloat16(v1));
                float ql0 = q0 - qh0, ql1 = q1 - qh1;
                float vl0 = v0 - vh0, vl1 = v1 - vh1;
                aq[pr * 3 + 0] = bfpair(qh0, qh0);
                aq[pr * 3 + 1] = bfpair(ql0, qh1);
                aq[pr * 3 + 2] = bfpair(qh1, ql1);
                bv[pr * 3 + 0] = bfpair(vh0, vl0);
                bv[pr * 3 + 1] = bfpair(vh0, vh1);
                bv[pr * 3 + 2] = bfpair(vl1, vh1);
            }
        }
        __syncthreads();

        // compute: 6 k-steps of 16
        uint32_t ab = smem_base + s * GR_STAGE + GR_A_OFF;
        uint32_t bb = smem_base + s * GR_STAGE + GR_B_OFF;
#pragma unroll
        for (int ks = 0; ks < 6; ++ks) {
            uint32_t a[4];
            {
                uint32_t addr = ab + (warpM * 16 + lrow) * GR_RB + ks * 32 + lkh * 2;
                ldsm_x4(a[0], a[1], a[2], a[3], addr);
            }
            uint32_t bf[4][2];
#pragma unroll
            for (int nq = 0; nq < 2; ++nq) {
                uint32_t r0, r1, r2, r3;
                uint32_t addr = bb + (warpN * 32 + nq * 16 + lrow) * GR_RB + ks * 32 + lkh * 2;
                ldsm_x4(r0, r1, r2, r3, addr);
                bf[2 * nq][0] = r0;     bf[2 * nq][1] = r2;
                bf[2 * nq + 1][0] = r1; bf[2 * nq + 1][1] = r3;
            }
#pragma unroll
            for (int ni = 0; ni < 4; ++ni)
                mma_bf16(acc[ni], a, bf[ni]);
        }
        __syncthreads();
    }

    atomicAdd(&g_sumsq[b * 128 + cch], ssq);
    atomicAdd(&g_sumsq[b * 128 + 64 + cch], ssv);

    const int g = lane >> 2, T = lane & 3;
    float* Gb = g_gram + b * 4096;
#pragma unroll
    for (int ni = 0; ni < 4; ++ni) {
        int n = warpN * 32 + ni * 8 + T * 2;
        int m = warpM * 16 + g;
        atomicAdd(&Gb[m * 64 + n],           acc[ni][0]);
        atomicAdd(&Gb[m * 64 + n + 1],       acc[ni][1]);
        atomicAdd(&Gb[(m + 8) * 64 + n],     acc[ni][2]);
        atomicAdd(&Gb[(m + 8) * 64 + n + 1], acc[ni][3]);
    }
}

// ---------------- norms + softmax + M = w_out @ attn --------------------------
__global__ __launch_bounds__(256) void attn_kernel(
    const float* __restrict__ w_out, const float* __restrict__ temp_p)
{
    __shared__ float attn_s[64 * 65];
    __shared__ float wo_s[64 * 65];
    __shared__ float nrm[128];
    const int tid = threadIdx.x, b = blockIdx.x;

    if (tid < 128) nrm[tid] = fmaxf(sqrtf(g_sumsq[b * 128 + tid]), 1e-12f);
    for (int e = tid; e < 4096; e += 256) {
        int o = e >> 6, c = e & 63;
        wo_s[c * 65 + o] = w_out[e];
    }
    __syncthreads();

    const float temp = *temp_p;
    if (tid < 64) {
        int c = tid;
        float inq = temp / nrm[c];
        float mx = -1e30f;
        for (int d = 0; d < 64; ++d) {
            float l = g_gram[b * 4096 + c * 64 + d] * (inq / nrm[64 + d]);
            attn_s[c * 65 + d] = l;
            mx = fmaxf(mx, l);
        }
        float sum = 0.f;
        for (int d = 0; d < 64; ++d) {
            float e_ = expf(attn_s[c * 65 + d] - mx);
            attn_s[c * 65 + d] = e_;
            sum += e_;
        }
        float inv = 1.f / sum;
        for (int d = 0; d < 64; ++d) attn_s[c * 65 + d] *= inv;
    }
    __syncthreads();

    const int o = tid & 63, dg = tid >> 6;
    for (int d = dg * 16; d < dg * 16 + 16; ++d) {
        float m = 0.f;
#pragma unroll 8
        for (int c2 = 0; c2 < 64; ++c2) m += wo_s[c2 * 65 + o] * attn_s[c2 * 65 + d];
        g_M[b * 4096 + o * 64 + d] = m;
    }
}

// ---------------- scalar K=64 GEMM (for gemm2 only) ---------------------------
__global__ __launch_bounds__(256, 2) void gemm_k64(
    const float* __restrict__ W, size_t wBatch,
    const float* __restrict__ X, size_t xBatch,
    float* __restrict__ Y, size_t yBatch)
{
    __shared__ u64 xs2[16 * 128];
    __shared__ u64 ws2[16 * 64];
    float* xsf = (float*)xs2;

    const int tid = threadIdx.x;
    const int tp = tid & 31;
    const int to = tid >> 5;
    const int b = blockIdx.z;
    const int pbase = blockIdx.x * 256;
    const int obase = blockIdx.y * 64;

    const float* Wb = W + (size_t)b * wBatch + (size_t)obase * 64;
    const float* Xb = X + (size_t)b * xBatch;
    float*       Yb = Y + (size_t)b * yBatch + (size_t)obase * NPIX;

    u64 acc[8][4];
#pragma unroll
    for (int j = 0; j < 8; ++j)
#pragma unroll
        for (int k = 0; k < 4; ++k) acc[j][k] = 0ULL;

    for (int cc = 0; cc < 64; cc += 16) {
        __syncthreads();
#pragma unroll
        for (int e = 0; e < 1024; e += 256) {
            int i = e + tid;
            int ch = i >> 6, p4 = i & 63;
            ((float4*)xsf)[ch * 64 + p4] =
                *(const float4*)(Xb + (size_t)(cc + ch) * NPIX + pbase + p4 * 4);
        }
#pragma unroll
        for (int e = 0; e < 1024; e += 256) {
            int i = e + tid;
            int o = i >> 4, cl = i & 15;
            float wv = Wb[(size_t)o * 64 + cc + cl];
            ws2[cl * 64 + o] = pack2(wv, wv);
        }
        __syncthreads();
#pragma unroll
        for (int c = 0; c < 16; ++c) {
            u64 xv[4];
            const u64* xr = xs2 + c * 128 + tp;
#pragma unroll
            for (int k = 0; k < 4; ++k) xv[k] = xr[32 * k];
            const u64* wr = ws2 + c * 64 + to * 8;
#pragma unroll
            for (int j = 0; j < 8; ++j) {
                u64 w2 = wr[j];
#pragma unroll
                for (int k = 0; k < 4; ++k)
                    acc[j][k] = ffma2(w2, xv[k], acc[j][k]);
            }
        }
    }
#pragma unroll
    for (int j = 0; j < 8; ++j) {
        float* yp = Yb + (size_t)(to * 8 + j) * NPIX + pbase + tp * 2;
#pragma unroll
        for (int k = 0; k < 4; ++k)
            *reinterpret_cast<u64*>(yp + 64 * k) = acc[j][k];
    }
}

// ---------------- launch ------------------------------------------------------
extern "C" void kernel_launch(void* const* d_in, const int* in_sizes, int n_in,
                              void* d_out, int out_size)
{
    const float* x      = (const float*)d_in[0];
    const float* w_in   = (const float*)d_in[1];
    const float* w_dw   = (const float*)d_in[2];
    const float* w_out  = (const float*)d_in[3];
    const float* temp   = (const float*)d_in[4];
    float* out = (float*)d_out;

    float *qv_ptr = nullptr, *M_ptr = nullptr;
    cudaGetSymbolAddress((void**)&qv_ptr, g_qv);
    cudaGetSymbolAddress((void**)&M_ptr,  g_M);

    cudaFuncSetAttribute(gemm1_fused, cudaFuncAttributeMaxDynamicSharedMemorySize, G1_SMEM);
    cudaFuncSetAttribute(gram_mma,    cudaFuncAttributeMaxDynamicSharedMemorySize, GR_SMEM);

    zero_stats<<<1, 256>>>();
    wsplit<<<64, 256>>>(w_in);

    // t = w_in @ x  (tensor cores, fused bf16-split)
    gemm1_fused<<<dim3(NPIX / 64, 1, BATCH), 256, G1_SMEM>>>(x);

    // depthwise conv + gate -> qv (float4)
    conv_mul<<<dim3(8, 128, BATCH), 256>>>(w_dw);

    // gram + sumsq (tensor cores)
    gram_mma<<<dim3(128, BATCH), 256, GR_SMEM>>>();

    // norms, softmax, M = w_out @ attn
    attn_kernel<<<BATCH, 256>>>(w_out, temp);

    // out = M @ v   (scalar f32x2 path)
    gemm_k64<<<dim3(NPIX / 256, 1, BATCH), 256>>>(
        M_ptr, 4096, qv_ptr + (size_t)64 * NPIX, (size_t)128 * NPIX,
        out, (size_t)64 * NPIX);
}

// round 10
// speedup vs baseline: 1.4944x; 1.0007x over previous
#include <cuda_runtime.h>
#include <cuda_bf16.h>
#include <math.h>
#include <stdint.h>

typedef unsigned long long u64;

#define NPIX  65536   // 256*256
#define BATCH 4

// ---------------- scratch (device globals: allocation is forbidden) -----------
__device__ float g_t[(size_t)BATCH * 256 * NPIX];     // 256 MB : t = w_in @ x
__device__ float g_qv[(size_t)BATCH * 128 * NPIX];    // 128 MB : q, v
__device__ __nv_bfloat16 g_a2[256 * 192];             // bf16-split w_in, [o][192]
__device__ __nv_bfloat16 g_M2[BATCH * 64 * 192];      // bf16-split M = w_out@attn
__device__ float g_sumsq[BATCH * 128];
__device__ float g_gram[BATCH * 64 * 64];

// ---------------- helpers -----------------------------------------------------
__device__ __forceinline__ u64 pack2(float x, float y) {
    u64 d;
    asm("mov.b64 %0, {%1, %2};" : "=l"(d) : "f"(x), "f"(y));
    return d;
}
__device__ __forceinline__ uint32_t smem_to_u32(const void* p) {
    uint32_t a;
    asm("{ .reg .u64 t; cvta.to.shared.u64 t, %1; cvt.u32.u64 %0, t; }" : "=r"(a) : "l"(p));
    return a;
}
__device__ __forceinline__ void ldsm_x4(uint32_t& r0, uint32_t& r1, uint32_t& r2, uint32_t& r3,
                                        uint32_t addr) {
    asm volatile("ldmatrix.sync.aligned.m8n8.x4.shared.b16 {%0,%1,%2,%3}, [%4];"
        : "=r"(r0), "=r"(r1), "=r"(r2), "=r"(r3) : "r"(addr));
}
__device__ __forceinline__ void mma_bf16(float* d, const uint32_t* a, const uint32_t* b) {
    asm volatile("mma.sync.aligned.m16n8k16.row.col.f32.bf16.bf16.f32 "
        "{%0,%1,%2,%3}, {%4,%5,%6,%7}, {%8,%9}, {%0,%1,%2,%3};"
        : "+f"(d[0]), "+f"(d[1]), "+f"(d[2]), "+f"(d[3])
        : "r"(a[0]), "r"(a[1]), "r"(a[2]), "r"(a[3]), "r"(b[0]), "r"(b[1]));
}
__device__ __forceinline__ void cp16(uint32_t smem_addr, const void* gptr) {
    asm volatile("cp.async.cg.shared.global [%0], [%1], 16;" :: "r"(smem_addr), "l"(gptr));
}
#define CP_COMMIT() asm volatile("cp.async.commit_group;" ::: "memory")
#define CP_WAIT(n)  asm volatile("cp.async.wait_group %0;" :: "n"(n) : "memory")

__device__ __forceinline__ unsigned short bfbits(float v) {
    __nv_bfloat16 h = __float2bfloat16(v);
    return *(unsigned short*)&h;
}
__device__ __forceinline__ uint32_t bfpair(float a, float b) {
    return (uint32_t)bfbits(a) | ((uint32_t)bfbits(b) << 16);
}

// ---------------- zero the accumulators --------------------------------------
__global__ void zero_stats() {
    for (int i = threadIdx.x; i < BATCH * 128 + BATCH * 64 * 64; i += blockDim.x) {
        if (i < BATCH * 128) g_sumsq[i] = 0.f;
        else                 g_gram[i - BATCH * 128] = 0.f;
    }
}

// ---------------- weight split: w_in[256][64] -> A2[256][192] bf16 -----------
__global__ void wsplit(const float* __restrict__ w_in) {
    for (int i = threadIdx.x + blockIdx.x * blockDim.x; i < 256 * 192; i += blockDim.x * gridDim.x) {
        int o = i / 192, k = i % 192;
        int c = k / 3, j = k % 3;
        float w = w_in[o * 64 + c];
        __nv_bfloat16 hi = __float2bfloat16(w);
        if (j == 2) g_a2[i] = __float2bfloat16(w - __bfloat162float(hi));
        else        g_a2[i] = hi;
    }
}

// ---------------- fused split + tensor-core gemm1 (round-8, proven) ----------
#define G1_RB      112
#define G1_A_ARR   (256 * G1_RB)
#define G1_B_ARR   (64 * G1_RB)
#define G1_X_RB    272
#define G1_X_ARR   (16 * G1_X_RB)
#define G1_STAGE   (G1_A_ARR + G1_B_ARR + G1_X_ARR)
#define G1_SMEM    (2 * G1_STAGE)
__global__ __launch_bounds__(256, 2) void gemm1_fused(const float* __restrict__ x) {
    extern __shared__ char sm[];
    const int tid = threadIdx.x, wid = tid >> 5, lane = tid & 31;
    const int pbase = blockIdx.x * 64;
    const int b = blockIdx.z;
    const int warpM = wid;

    const uint32_t smem_base = smem_to_u32(sm);
    const char*  Agl = (const char*)g_a2;
    const float* xb  = x + (size_t)b * 64 * NPIX + pbase;

    auto a_base = [&](int s) { return smem_base + s * G1_STAGE; };
    auto b_base = [&](int s) { return smem_base + s * G1_STAGE + G1_A_ARR; };
    auto x_base = [&](int s) { return smem_base + s * G1_STAGE + G1_A_ARR + G1_B_ARR; };

    auto prefetch = [&](int chunk, int s) {
        const int goff = chunk * 96;
        uint32_t ab = a_base(s);
#pragma unroll
        for (int e = 0; e < 1536; e += 256) {
            int u = e + tid;
            int r = u / 6, sl = u % 6;
            cp16(ab + r * G1_RB + sl * 16, Agl + r * 384 + goff + sl * 16);
        }
        uint32_t xbs = x_base(s);
        {
            int ch = tid >> 4, sl = tid & 15;
            cp16(xbs + ch * G1_X_RB + sl * 16,
                 xb + (size_t)(chunk * 16 + ch) * NPIX + sl * 4);
        }
    };

    const int lrow = lane & 15;
    const int lkh  = (lane >> 4) * 8;

    float acc[2][8][4];
#pragma unroll
    for (int mi = 0; mi < 2; ++mi)
#pragma unroll
        for (int ni = 0; ni < 8; ++ni)
#pragma unroll
            for (int r = 0; r < 4; ++r) acc[mi][ni][r] = 0.f;

    prefetch(0, 0);
    CP_COMMIT();

#pragma unroll
    for (int c = 0; c < 4; ++c) {
        const int s = c & 1;
        if (c < 3) { prefetch(c + 1, s ^ 1); CP_COMMIT(); }
        if (c < 3) CP_WAIT(1); else CP_WAIT(0);
        __syncthreads();

        {
            const float* xs = (const float*)(sm + s * G1_STAGE + G1_A_ARR + G1_B_ARR);
            char* Bs = sm + s * G1_STAGE + G1_A_ARR;
#pragma unroll
            for (int e = 0; e < 512; e += 256) {
                int u = e + tid;
                int p = u & 63, cp = u >> 6;
                float x0 = xs[(2 * cp) * 68 + p];
                float x1 = xs[(2 * cp + 1) * 68 + p];
                float h0 = __bfloat162float(__float2bfloat16(x0));
                float h1 = __bfloat162float(__float2bfloat16(x1));
                float l0 = x0 - h0, l1 = x1 - h1;
                uint32_t* row = (uint32_t*)(Bs + p * G1_RB + cp * 12);
                row[0] = bfpair(h0, l0);
                row[1] = bfpair(h0, h1);
                row[2] = bfpair(l1, h1);
            }
        }
        __syncthreads();

        uint32_t ab = a_base(s), bb = b_base(s);
#pragma unroll
        for (int ksl = 0; ksl < 3; ++ksl) {
            uint32_t a[2][4];
#pragma unroll
            for (int mi = 0; mi < 2; ++mi) {
                uint32_t addr = ab + (warpM * 32 + mi * 16 + lrow) * G1_RB + ksl * 32 + lkh * 2;
                ldsm_x4(a[mi][0], a[mi][1], a[mi][2], a[mi][3], addr);
            }
            uint32_t bf[8][2];
#pragma unroll
            for (int nq = 0; nq < 4; ++nq) {
                uint32_t r0, r1, r2, r3;
                uint32_t addr = bb + (nq * 16 + lrow) * G1_RB + ksl * 32 + lkh * 2;
                ldsm_x4(r0, r1, r2, r3, addr);
                bf[2 * nq][0] = r0;     bf[2 * nq][1] = r2;
                bf[2 * nq + 1][0] = r1; bf[2 * nq + 1][1] = r3;
            }
#pragma unroll
            for (int mi = 0; mi < 2; ++mi)
#pragma unroll
                for (int ni = 0; ni < 8; ++ni)
                    mma_bf16(acc[mi][ni], a[mi], bf[ni]);
        }
        __syncthreads();
    }

    const int g = lane >> 2, T = lane & 3;
#pragma unroll
    for (int mi = 0; mi < 2; ++mi) {
        int m = warpM * 32 + mi * 16 + g;
        float* rowp = g_t + ((size_t)b * 256 + m) * NPIX + pbase + T * 2;
#pragma unroll
        for (int ni = 0; ni < 8; ++ni) {
            *(u64*)(rowp + ni * 8) = pack2(acc[mi][ni][0], acc[mi][ni][1]);
            *(u64*)(rowp + ni * 8 + (size_t)8 * NPIX) = pack2(acc[mi][ni][2], acc[mi][ni][3]);
        }
    }
}

// ---------------- depthwise 3x3 conv + gate, float4, 3 CTAs/SM ----------------
__global__ __launch_bounds__(256, 3) void conv_mul(const float* __restrict__ w_dw)
{
    __shared__ float st[34][264];
    const int tid = threadIdx.x;
    const int jj = blockIdx.y, b = blockIdx.z, r0 = blockIdx.x * 32;

    const float* t1 = g_t + ((size_t)b * 256 + jj) * NPIX;
    const float* t2 = g_t + ((size_t)b * 256 + 128 + jj) * NPIX;
    float* outp = g_qv + ((size_t)b * 128 + jj) * NPIX;

    float wd[9];
#pragma unroll
    for (int i = 0; i < 9; ++i) wd[i] = w_dw[jj * 9 + i];

#pragma unroll
    for (int e = 0; e < 2176; e += 256) {
        int u = e + tid;
        if (u < 2176) {
            int rr = u >> 6, q4 = u & 63;
            int row = r0 - 1 + rr;
            float4 v = make_float4(0.f, 0.f, 0.f, 0.f);
            if (row >= 0 && row < 256)
                v = *(const float4*)(t1 + row * 256 + q4 * 4);
            *(float4*)&st[rr][4 + q4 * 4] = v;
        }
    }
    if (tid < 34) { st[tid][3] = 0.f; st[tid][260] = 0.f; }
    __syncthreads();

    const int ty = tid >> 6, tc = tid & 63;
    const int c0 = tc * 4;
#pragma unroll
    for (int r = ty * 8; r < ty * 8 + 8; ++r) {
        float s0 = 0.f, s1 = 0.f, s2 = 0.f, s3 = 0.f;
#pragma unroll
        for (int ky = 0; ky < 3; ++ky) {
            const float* rowp = &st[r + ky][4 + c0];
            float4 m = *(const float4*)rowp;
            float left = rowp[-1], right = rowp[4];
            float w0 = wd[ky * 3 + 0], w1 = wd[ky * 3 + 1], w2 = wd[ky * 3 + 2];
            s0 += w0 * left + w1 * m.x + w2 * m.y;
            s1 += w0 * m.x  + w1 * m.y + w2 * m.z;
            s2 += w0 * m.y  + w1 * m.z + w2 * m.w;
            s3 += w0 * m.z  + w1 * m.w + w2 * right;
        }
        int p = (r0 + r) * 256 + c0;
        float4 g4 = *(const float4*)(t2 + p);
        float4 o = make_float4(s0 * g4.x, s1 * g4.y, s2 * g4.z, s3 * g4.w);
        *(float4*)(outp + p) = o;
    }
}

// ---------------- tensor-core gram + sumsq (round-9, proven) ------------------
#define GR_RB     208
#define GR_XRB    144
#define GR_A_OFF  0
#define GR_B_OFF  13312
#define GR_Q_OFF  26624
#define GR_V_OFF  35840
#define GR_STAGE  45056
#define GR_SMEM   (2 * GR_STAGE)
#define GR_CHUNKS 16
__global__ __launch_bounds__(256, 2) void gram_mma()
{
    extern __shared__ char sm[];
    const int tid = threadIdx.x, wid = tid >> 5, lane = tid & 31;
    const int b = blockIdx.y;
    const int warpM = wid & 3, warpN = wid >> 2;

    const uint32_t smem_base = smem_to_u32(sm);
    const float* qsrc = g_qv + (size_t)b * 128 * NPIX;
    const float* vsrc = qsrc + (size_t)64 * NPIX;
    const int cbase = blockIdx.x * GR_CHUNKS;

    auto prefetch = [&](int ci, int s) {
        int pbase = (cbase + ci) * 32;
        uint32_t qb = smem_base + s * GR_STAGE + GR_Q_OFF;
        uint32_t vb = smem_base + s * GR_STAGE + GR_V_OFF;
#pragma unroll
        for (int e = 0; e < 512; e += 256) {
            int u = e + tid;
            int ch = u >> 3, sl = u & 7;
            cp16(qb + ch * GR_XRB + sl * 16, qsrc + (size_t)ch * NPIX + pbase + sl * 4);
        }
#pragma unroll
        for (int e = 0; e < 512; e += 256) {
            int u = e + tid;
            int ch = u >> 3, sl = u & 7;
            cp16(vb + ch * GR_XRB + sl * 16, vsrc + (size_t)ch * NPIX + pbase + sl * 4);
        }
    };

    const int lrow = lane & 15;
    const int lkh  = (lane >> 4) * 8;

    float acc[4][4];
#pragma unroll
    for (int ni = 0; ni < 4; ++ni)
#pragma unroll
        for (int r = 0; r < 4; ++r) acc[ni][r] = 0.f;
    float ssq = 0.f, ssv = 0.f;

    const int cch = tid >> 2;
    const int ppr = (tid & 3) * 4;

    prefetch(0, 0);
    CP_COMMIT();

    for (int c = 0; c < GR_CHUNKS; ++c) {
        const int s = c & 1;
        if (c < GR_CHUNKS - 1) { prefetch(c + 1, s ^ 1); CP_COMMIT(); }
        if (c < GR_CHUNKS - 1) CP_WAIT(1); else CP_WAIT(0);
        __syncthreads();

        {
            const float* rq = (const float*)(sm + s * GR_STAGE + GR_Q_OFF) + cch * 36;
            const float* rv = (const float*)(sm + s * GR_STAGE + GR_V_OFF) + cch * 36;
            uint32_t* aq = (uint32_t*)(sm + s * GR_STAGE + GR_A_OFF + cch * GR_RB) + ppr * 3;
            uint32_t* bv = (uint32_t*)(sm + s * GR_STAGE + GR_B_OFF + cch * GR_RB) + ppr * 3;
#pragma unroll
            for (int pr = 0; pr < 4; ++pr) {
                float q0 = rq[ppr * 2 + pr * 2], q1 = rq[ppr * 2 + pr * 2 + 1];
                float v0 = rv[ppr * 2 + pr * 2], v1 = rv[ppr * 2 + pr * 2 + 1];
                ssq += q0 * q0 + q1 * q1;
                ssv += v0 * v0 + v1 * v1;
                float qh0 = __bfloat162float(__float2bfloat16(q0));
                float qh1 = __bfloat162float(__float2bfloat16(q1));
                float vh0 = __bfloat162float(__float2bfloat16(v0));
                float vh1 = __bfloat162float(__float2bfloat16(v1));
                float ql0 = q0 - qh0, ql1 = q1 - qh1;
                float vl0 = v0 - vh0, vl1 = v1 - vh1;
                aq[pr * 3 + 0] = bfpair(qh0, qh0);
                aq[pr * 3 + 1] = bfpair(ql0, qh1);
                aq[pr * 3 + 2] = bfpair(qh1, ql1);
                bv[pr * 3 + 0] = bfpair(vh0, vl0);
                bv[pr * 3 + 1] = bfpair(vh0, vh1);
                bv[pr * 3 + 2] = bfpair(vl1, vh1);
            }
        }
        __syncthreads();

        uint32_t ab = smem_base + s * GR_STAGE + GR_A_OFF;
        uint32_t bb = smem_base + s * GR_STAGE + GR_B_OFF;
#pragma unroll
        for (int ks = 0; ks < 6; ++ks) {
            uint32_t a[4];
            {
                uint32_t addr = ab + (warpM * 16 + lrow) * GR_RB + ks * 32 + lkh * 2;
                ldsm_x4(a[0], a[1], a[2], a[3], addr);
            }
            uint32_t bf[4][2];
#pragma unroll
            for (int nq = 0; nq < 2; ++nq) {
                uint32_t r0, r1, r2, r3;
                uint32_t addr = bb + (warpN * 32 + nq * 16 + lrow) * GR_RB + ks * 32 + lkh * 2;
                ldsm_x4(r0, r1, r2, r3, addr);
                bf[2 * nq][0] = r0;     bf[2 * nq][1] = r2;
                bf[2 * nq + 1][0] = r1; bf[2 * nq + 1][1] = r3;
            }
#pragma unroll
            for (int ni = 0; ni < 4; ++ni)
                mma_bf16(acc[ni], a, bf[ni]);
        }
        __syncthreads();
    }

    atomicAdd(&g_sumsq[b * 128 + cch], ssq);
    atomicAdd(&g_sumsq[b * 128 + 64 + cch], ssv);

    const int g = lane >> 2, T = lane & 3;
    float* Gb = g_gram + b * 4096;
#pragma unroll
    for (int ni = 0; ni < 4; ++ni) {
        int n = warpN * 32 + ni * 8 + T * 2;
        int m = warpM * 16 + g;
        atomicAdd(&Gb[m * 64 + n],           acc[ni][0]);
        atomicAdd(&Gb[m * 64 + n + 1],       acc[ni][1]);
        atomicAdd(&Gb[(m + 8) * 64 + n],     acc[ni][2]);
        atomicAdd(&Gb[(m + 8) * 64 + n + 1], acc[ni][3]);
    }
}

// ---------------- norms + softmax + M = w_out @ attn (writes split M) --------
__global__ __launch_bounds__(256) void attn_kernel(
    const float* __restrict__ w_out, const float* __restrict__ temp_p)
{
    __shared__ float attn_s[64 * 65];
    __shared__ float wo_s[64 * 65];
    __shared__ float nrm[128];
    const int tid = threadIdx.x, b = blockIdx.x;

    if (tid < 128) nrm[tid] = fmaxf(sqrtf(g_sumsq[b * 128 + tid]), 1e-12f);
    for (int e = tid; e < 4096; e += 256) {
        int o = e >> 6, c = e & 63;
        wo_s[c * 65 + o] = w_out[e];
    }
    __syncthreads();

    const float temp = *temp_p;
    if (tid < 64) {
        int c = tid;
        float inq = temp / nrm[c];
        float mx = -1e30f;
        for (int d = 0; d < 64; ++d) {
            float l = g_gram[b * 4096 + c * 64 + d] * (inq / nrm[64 + d]);
            attn_s[c * 65 + d] = l;
            mx = fmaxf(mx, l);
        }
        float sum = 0.f;
        for (int d = 0; d < 64; ++d) {
            float e_ = expf(attn_s[c * 65 + d] - mx);
            attn_s[c * 65 + d] = e_;
            sum += e_;
        }
        float inv = 1.f / sum;
        for (int d = 0; d < 64; ++d) attn_s[c * 65 + d] *= inv;
    }
    __syncthreads();

    const int o = tid & 63, dg = tid >> 6;
    for (int d = dg * 16; d < dg * 16 + 16; ++d) {
        float m = 0.f;
#pragma unroll 8
        for (int c2 = 0; c2 < 64; ++c2) m += wo_s[c2 * 65 + o] * attn_s[c2 * 65 + d];
        // bf16-split write for tensor-core gemm2: A slots (hi, hi, lo)
        __nv_bfloat16 hi = __float2bfloat16(m);
        __nv_bfloat16 lo = __float2bfloat16(m - __bfloat162float(hi));
        __nv_bfloat16* dst = g_M2 + ((size_t)b * 64 + o) * 192 + 3 * d;
        dst[0] = hi; dst[1] = hi; dst[2] = lo;
    }
}

// ---------------- tensor-core gemm2: out = M @ v (fused split) ----------------
// CTA: M=64 outs x N=128 px x K=192 (4 chunks of 48 = 16 channels).
// A (split M, 64x192 bf16) staged once; raw v chunks double-buffered + converted.
// 8 warps = 2(m:32) x 4(n:32 px). grid (NPIX/128, BATCH).
#define G2_A_RB   400
#define G2_A_ARR  (64 * G2_A_RB)           // 25600
#define G2_B_RB   112
#define G2_B_ARR  (128 * G2_B_RB)          // 14336
#define G2_X_RB   528
#define G2_X_ARR  (16 * G2_X_RB)           // 8448
#define G2_STAGE  (G2_B_ARR + G2_X_ARR)    // 22784
#define G2_SMEM   (G2_A_ARR + 2 * G2_STAGE)  // 71168
__global__ __launch_bounds__(256, 2) void gemm2_mma(float* __restrict__ out)
{
    extern __shared__ char sm[];
    const int tid = threadIdx.x, wid = tid >> 5, lane = tid & 31;
    const int pbase = blockIdx.x * 128;
    const int b = blockIdx.y;
    const int warpM = wid & 1, warpN = wid >> 1;

    const uint32_t smem_base = smem_to_u32(sm);
    const char*  Agl = (const char*)(g_M2 + (size_t)b * 64 * 192);
    const float* vb  = g_qv + (size_t)b * 128 * NPIX + (size_t)64 * NPIX + pbase;

    auto b_base = [&](int s) { return smem_base + G2_A_ARR + s * G2_STAGE; };
    auto x_base = [&](int s) { return smem_base + G2_A_ARR + s * G2_STAGE + G2_B_ARR; };

    // stage A whole (64 rows x 384B = 1536 16B units)
#pragma unroll
    for (int e = 0; e < 1536; e += 256) {
        int u = e + tid;
        int r = u / 24, sl = u % 24;
        cp16(smem_base + r * G2_A_RB + sl * 16, Agl + r * 384 + sl * 16);
    }
    // prefetch chunk 0 raw v (16 ch x 32 slabs = 512 units)
    auto prefetch = [&](int chunk, int s) {
        uint32_t xbs = x_base(s);
#pragma unroll
        for (int e = 0; e < 512; e += 256) {
            int u = e + tid;
            int ch = u >> 5, sl = u & 31;
            cp16(xbs + ch * G2_X_RB + sl * 16,
                 vb + (size_t)(chunk * 16 + ch) * NPIX + sl * 4);
        }
    };
    prefetch(0, 0);
    CP_COMMIT();

    const int lrow = lane & 15;
    const int lkh  = (lane >> 4) * 8;

    float acc[2][4][4];
#pragma unroll
    for (int mi = 0; mi < 2; ++mi)
#pragma unroll
        for (int ni = 0; ni < 4; ++ni)
#pragma unroll
            for (int r = 0; r < 4; ++r) acc[mi][ni][r] = 0.f;

#pragma unroll
    for (int c = 0; c < 4; ++c) {
        const int s = c & 1;
        if (c < 3) { prefetch(c + 1, s ^ 1); CP_COMMIT(); }
        if (c < 3) CP_WAIT(1); else CP_WAIT(0);
        __syncthreads();

        // convert raw v -> B slots (hi, lo, hi): 8 ch-pairs x 128 px = 1024 units
        {
            const float* xs = (const float*)(sm + G2_A_ARR + s * G2_STAGE + G2_B_ARR);
            char* Bs = sm + G2_A_ARR + s * G2_STAGE;
#pragma unroll
            for (int e = 0; e < 1024; e += 256) {
                int u = e + tid;
                int p = u & 127, cp = u >> 7;
                float x0 = xs[(2 * cp) * 132 + p];
                float x1 = xs[(2 * cp + 1) * 132 + p];
                float h0 = __bfloat162float(__float2bfloat16(x0));
                float h1 = __bfloat162float(__float2bfloat16(x1));
                float l0 = x0 - h0, l1 = x1 - h1;
                uint32_t* row = (uint32_t*)(Bs + p * G2_B_RB + cp * 12);
                row[0] = bfpair(h0, l0);
                row[1] = bfpair(h0, h1);
                row[2] = bfpair(l1, h1);
            }
        }
        __syncthreads();

        uint32_t bb = b_base(s);
#pragma unroll
        for (int ksl = 0; ksl < 3; ++ksl) {
            uint32_t a[2][4];
#pragma unroll
            for (int mi = 0; mi < 2; ++mi) {
                uint32_t addr = smem_base + (warpM * 32 + mi * 16 + lrow) * G2_A_RB
                              + c * 96 + ksl * 32 + lkh * 2;
                ldsm_x4(a[mi][0], a[mi][1], a[mi][2], a[mi][3], addr);
            }
            uint32_t bf[4][2];
#pragma unroll
            for (int nq = 0; nq < 2; ++nq) {
                uint32_t r0, r1, r2, r3;
                uint32_t addr = bb + (warpN * 32 + nq * 16 + lrow) * G2_B_RB + ksl * 32 + lkh * 2;
                ldsm_x4(r0, r1, r2, r3, addr);
                bf[2 * nq][0] = r0;     bf[2 * nq][1] = r2;
                bf[2 * nq + 1][0] = r1; bf[2 * nq + 1][1] = r3;
            }
#pragma unroll
            for (int mi = 0; mi < 2; ++mi)
#pragma unroll
                for (int ni = 0; ni < 4; ++ni)
                    mma_bf16(acc[mi][ni], a[mi], bf[ni]);
        }
        __syncthreads();
    }

    const int g = lane >> 2, T = lane & 3;
#pragma unroll
    for (int mi = 0; mi < 2; ++mi) {
        int o = warpM * 32 + mi * 16 + g;
        float* rowp = out + ((size_t)b * 64 + o) * NPIX + pbase + warpN * 32 + T * 2;
#pragma unroll
        for (int ni = 0; ni < 4; ++ni) {
            *(u64*)(rowp + ni * 8) = pack2(acc[mi][ni][0], acc[mi][ni][1]);
            *(u64*)(rowp + ni * 8 + (size_t)8 * NPIX) = pack2(acc[mi][ni][2], acc[mi][ni][3]);
        }
    }
}

// ---------------- launch ------------------------------------------------------
extern "C" void kernel_launch(void* const* d_in, const int* in_sizes, int n_in,
                              void* d_out, int out_size)
{
    const float* x      = (const float*)d_in[0];
    const float* w_in   = (const float*)d_in[1];
    const float* w_dw   = (const float*)d_in[2];
    const float* w_out  = (const float*)d_in[3];
    const float* temp   = (const float*)d_in[4];
    float* out = (float*)d_out;

    cudaFuncSetAttribute(gemm1_fused, cudaFuncAttributeMaxDynamicSharedMemorySize, G1_SMEM);
    cudaFuncSetAttribute(gram_mma,    cudaFuncAttributeMaxDynamicSharedMemorySize, GR_SMEM);
    cudaFuncSetAttribute(gemm2_mma,   cudaFuncAttributeMaxDynamicSharedMemorySize, G2_SMEM);

    zero_stats<<<1, 256>>>();
    wsplit<<<64, 256>>>(w_in);

    // t = w_in @ x  (tensor cores, fused bf16-split)
    gemm1_fused<<<dim3(NPIX / 64, 1, BATCH), 256, G1_SMEM>>>(x);

    // depthwise conv + gate -> qv (float4)
    conv_mul<<<dim3(8, 128, BATCH), 256>>>(w_dw);

    // gram + sumsq (tensor cores)
    gram_mma<<<dim3(128, BATCH), 256, GR_SMEM>>>();

    // norms, softmax, M = w_out @ attn (+ bf16-split M)
    attn_kernel<<<BATCH, 256>>>(w_out, temp);

    // out = M @ v (tensor cores, fused split)
    gemm2_mma<<<dim3(NPIX / 128, BATCH), 256, G2_SMEM>>>(out);
}

// round 11
// speedup vs baseline: 1.5592x; 1.0433x over previous
#include <cuda_runtime.h>
#include <cuda_bf16.h>
#include <math.h>
#include <stdint.h>

typedef unsigned long long u64;

#define NPIX  65536   // 256*256
#define BATCH 4

// ---------------- scratch (device globals: allocation is forbidden) -----------
__device__ float g_t[(size_t)BATCH * 256 * NPIX];     // 256 MB : t = w_in @ x
__device__ float g_qv[(size_t)BATCH * 128 * NPIX];    // 128 MB : q, v
__device__ __nv_bfloat16 g_a2[256 * 192];             // bf16-split w_in, [o][192]
__device__ __nv_bfloat16 g_M2[BATCH * 64 * 192];      // bf16-split M = w_out@attn
__device__ float g_sumsq[BATCH * 128];
__device__ float g_gram[BATCH * 64 * 64];

// ---------------- helpers -----------------------------------------------------
__device__ __forceinline__ u64 pack2(float x, float y) {
    u64 d;
    asm("mov.b64 %0, {%1, %2};" : "=l"(d) : "f"(x), "f"(y));
    return d;
}
__device__ __forceinline__ uint32_t smem_to_u32(const void* p) {
    uint32_t a;
    asm("{ .reg .u64 t; cvta.to.shared.u64 t, %1; cvt.u32.u64 %0, t; }" : "=r"(a) : "l"(p));
    return a;
}
__device__ __forceinline__ void ldsm_x4(uint32_t& r0, uint32_t& r1, uint32_t& r2, uint32_t& r3,
                                        uint32_t addr) {
    asm volatile("ldmatrix.sync.aligned.m8n8.x4.shared.b16 {%0,%1,%2,%3}, [%4];"
        : "=r"(r0), "=r"(r1), "=r"(r2), "=r"(r3) : "r"(addr));
}
__device__ __forceinline__ void mma_bf16(float* d, const uint32_t* a, const uint32_t* b) {
    asm volatile("mma.sync.aligned.m16n8k16.row.col.f32.bf16.bf16.f32 "
        "{%0,%1,%2,%3}, {%4,%5,%6,%7}, {%8,%9}, {%0,%1,%2,%3};"
        : "+f"(d[0]), "+f"(d[1]), "+f"(d[2]), "+f"(d[3])
        : "r"(a[0]), "r"(a[1]), "r"(a[2]), "r"(a[3]), "r"(b[0]), "r"(b[1]));
}
__device__ __forceinline__ void cp16(uint32_t smem_addr, const void* gptr) {
    asm volatile("cp.async.cg.shared.global [%0], [%1], 16;" :: "r"(smem_addr), "l"(gptr));
}
#define CP_COMMIT() asm volatile("cp.async.commit_group;" ::: "memory")
#define CP_WAIT(n)  asm volatile("cp.async.wait_group %0;" :: "n"(n) : "memory")

__device__ __forceinline__ unsigned short bfbits(float v) {
    __nv_bfloat16 h = __float2bfloat16(v);
    return *(unsigned short*)&h;
}
__device__ __forceinline__ uint32_t bfpair(float a, float b) {
    return (uint32_t)bfbits(a) | ((uint32_t)bfbits(b) << 16);
}

// ---------------- weight split + zero stats (merged) --------------------------
__global__ void wsplit(const float* __restrict__ w_in) {
    const int gi = threadIdx.x + blockIdx.x * blockDim.x;
    const int gs = blockDim.x * gridDim.x;
    for (int i = gi; i < 256 * 192; i += gs) {
        int o = i / 192, k = i % 192;
        int c = k / 3, j = k % 3;
        float w = w_in[o * 64 + c];
        __nv_bfloat16 hi = __float2bfloat16(w);
        if (j == 2) g_a2[i] = __float2bfloat16(w - __bfloat162float(hi));
        else        g_a2[i] = hi;
    }
    for (int i = gi; i < BATCH * 128 + BATCH * 64 * 64; i += gs) {
        if (i < BATCH * 128) g_sumsq[i] = 0.f;
        else                 g_gram[i - BATCH * 128] = 0.f;
    }
}

// ---------------- fused split + tensor-core gemm1 (round-8, proven) ----------
#define G1_RB      112
#define G1_A_ARR   (256 * G1_RB)
#define G1_B_ARR   (64 * G1_RB)
#define G1_X_RB    272
#define G1_X_ARR   (16 * G1_X_RB)
#define G1_STAGE   (G1_A_ARR + G1_B_ARR + G1_X_ARR)
#define G1_SMEM    (2 * G1_STAGE)
__global__ __launch_bounds__(256, 2) void gemm1_fused(const float* __restrict__ x) {
    extern __shared__ char sm[];
    const int tid = threadIdx.x, wid = tid >> 5, lane = tid & 31;
    const int pbase = blockIdx.x * 64;
    const int b = blockIdx.z;
    const int warpM = wid;

    const uint32_t smem_base = smem_to_u32(sm);
    const char*  Agl = (const char*)g_a2;
    const float* xb  = x + (size_t)b * 64 * NPIX + pbase;

    auto a_base = [&](int s) { return smem_base + s * G1_STAGE; };
    auto b_base = [&](int s) { return smem_base + s * G1_STAGE + G1_A_ARR; };
    auto x_base = [&](int s) { return smem_base + s * G1_STAGE + G1_A_ARR + G1_B_ARR; };

    auto prefetch = [&](int chunk, int s) {
        const int goff = chunk * 96;
        uint32_t ab = a_base(s);
#pragma unroll
        for (int e = 0; e < 1536; e += 256) {
            int u = e + tid;
            int r = u / 6, sl = u % 6;
            cp16(ab + r * G1_RB + sl * 16, Agl + r * 384 + goff + sl * 16);
        }
        uint32_t xbs = x_base(s);
        {
            int ch = tid >> 4, sl = tid & 15;
            cp16(xbs + ch * G1_X_RB + sl * 16,
                 xb + (size_t)(chunk * 16 + ch) * NPIX + sl * 4);
        }
    };

    const int lrow = lane & 15;
    const int lkh  = (lane >> 4) * 8;

    float acc[2][8][4];
#pragma unroll
    for (int mi = 0; mi < 2; ++mi)
#pragma unroll
        for (int ni = 0; ni < 8; ++ni)
#pragma unroll
            for (int r = 0; r < 4; ++r) acc[mi][ni][r] = 0.f;

    prefetch(0, 0);
    CP_COMMIT();

#pragma unroll
    for (int c = 0; c < 4; ++c) {
        const int s = c & 1;
        if (c < 3) { prefetch(c + 1, s ^ 1); CP_COMMIT(); }
        if (c < 3) CP_WAIT(1); else CP_WAIT(0);
        __syncthreads();

        {
            const float* xs = (const float*)(sm + s * G1_STAGE + G1_A_ARR + G1_B_ARR);
            char* Bs = sm + s * G1_STAGE + G1_A_ARR;
#pragma unroll
            for (int e = 0; e < 512; e += 256) {
                int u = e + tid;
                int p = u & 63, cp = u >> 6;
                float x0 = xs[(2 * cp) * 68 + p];
                float x1 = xs[(2 * cp + 1) * 68 + p];
                float h0 = __bfloat162float(__float2bfloat16(x0));
                float h1 = __bfloat162float(__float2bfloat16(x1));
                float l0 = x0 - h0, l1 = x1 - h1;
                uint32_t* row = (uint32_t*)(Bs + p * G1_RB + cp * 12);
                row[0] = bfpair(h0, l0);
                row[1] = bfpair(h0, h1);
                row[2] = bfpair(l1, h1);
            }
        }
        __syncthreads();

        uint32_t ab = a_base(s), bb = b_base(s);
#pragma unroll
        for (int ksl = 0; ksl < 3; ++ksl) {
            uint32_t a[2][4];
#pragma unroll
            for (int mi = 0; mi < 2; ++mi) {
                uint32_t addr = ab + (warpM * 32 + mi * 16 + lrow) * G1_RB + ksl * 32 + lkh * 2;
                ldsm_x4(a[mi][0], a[mi][1], a[mi][2], a[mi][3], addr);
            }
            uint32_t bf[8][2];
#pragma unroll
            for (int nq = 0; nq < 4; ++nq) {
                uint32_t r0, r1, r2, r3;
                uint32_t addr = bb + (nq * 16 + lrow) * G1_RB + ksl * 32 + lkh * 2;
                ldsm_x4(r0, r1, r2, r3, addr);
                bf[2 * nq][0] = r0;     bf[2 * nq][1] = r2;
                bf[2 * nq + 1][0] = r1; bf[2 * nq + 1][1] = r3;
            }
#pragma unroll
            for (int mi = 0; mi < 2; ++mi)
#pragma unroll
                for (int ni = 0; ni < 8; ++ni)
                    mma_bf16(acc[mi][ni], a[mi], bf[ni]);
        }
        __syncthreads();
    }

    const int g = lane >> 2, T = lane & 3;
#pragma unroll
    for (int mi = 0; mi < 2; ++mi) {
        int m = warpM * 32 + mi * 16 + g;
        float* rowp = g_t + ((size_t)b * 256 + m) * NPIX + pbase + T * 2;
#pragma unroll
        for (int ni = 0; ni < 8; ++ni) {
            *(u64*)(rowp + ni * 8) = pack2(acc[mi][ni][0], acc[mi][ni][1]);
            *(u64*)(rowp + ni * 8 + (size_t)8 * NPIX) = pack2(acc[mi][ni][2], acc[mi][ni][3]);
        }
    }
}

// ---------------- depthwise 3x3 conv + gate, float4 (round-9 exact) ----------
__global__ __launch_bounds__(256) void conv_mul(const float* __restrict__ w_dw)
{
    __shared__ float st[34][264];
    const int tid = threadIdx.x;
    const int jj = blockIdx.y, b = blockIdx.z, r0 = blockIdx.x * 32;

    const float* t1 = g_t + ((size_t)b * 256 + jj) * NPIX;
    const float* t2 = g_t + ((size_t)b * 256 + 128 + jj) * NPIX;
    float* outp = g_qv + ((size_t)b * 128 + jj) * NPIX;

    float wd[9];
#pragma unroll
    for (int i = 0; i < 9; ++i) wd[i] = w_dw[jj * 9 + i];

#pragma unroll
    for (int e = 0; e < 2176; e += 256) {
        int u = e + tid;
        if (u < 2176) {
            int rr = u >> 6, q4 = u & 63;
            int row = r0 - 1 + rr;
            float4 v = make_float4(0.f, 0.f, 0.f, 0.f);
            if (row >= 0 && row < 256)
                v = *(const float4*)(t1 + row * 256 + q4 * 4);
            *(float4*)&st[rr][4 + q4 * 4] = v;
        }
    }
    if (tid < 34) { st[tid][3] = 0.f; st[tid][260] = 0.f; }
    __syncthreads();

    const int ty = tid >> 6, tc = tid & 63;
    const int c0 = tc * 4;
#pragma unroll
    for (int r = ty * 8; r < ty * 8 + 8; ++r) {
        float s0 = 0.f, s1 = 0.f, s2 = 0.f, s3 = 0.f;
#pragma unroll
        for (int ky = 0; ky < 3; ++ky) {
            const float* rowp = &st[r + ky][4 + c0];
            float4 m = *(const float4*)rowp;
            float left = rowp[-1], right = rowp[4];
            float w0 = wd[ky * 3 + 0], w1 = wd[ky * 3 + 1], w2 = wd[ky * 3 + 2];
            s0 += w0 * left + w1 * m.x + w2 * m.y;
            s1 += w0 * m.x  + w1 * m.y + w2 * m.z;
            s2 += w0 * m.y  + w1 * m.z + w2 * m.w;
            s3 += w0 * m.z  + w1 * m.w + w2 * right;
        }
        int p = (r0 + r) * 256 + c0;
        float4 g4 = *(const float4*)(t2 + p);
        float4 o = make_float4(s0 * g4.x, s1 * g4.y, s2 * g4.z, s3 * g4.w);
        *(float4*)(outp + p) = o;
    }
}

// ---------------- tensor-core gram + sumsq (grid-stride, 2 full waves) --------
#define GR_RB     208
#define GR_XRB    144
#define GR_A_OFF  0
#define GR_B_OFF  13312
#define GR_Q_OFF  26624
#define GR_V_OFF  35840
#define GR_STAGE  45056
#define GR_SMEM   (2 * GR_STAGE)
#define GR_NCHUNK 2048                 // NPIX / 32
__global__ __launch_bounds__(256, 2) void gram_mma()
{
    extern __shared__ char sm[];
    const int tid = threadIdx.x, wid = tid >> 5, lane = tid & 31;
    const int b = blockIdx.y;
    const int warpM = wid & 3, warpN = wid >> 2;

    const uint32_t smem_base = smem_to_u32(sm);
    const float* qsrc = g_qv + (size_t)b * 128 * NPIX;
    const float* vsrc = qsrc + (size_t)64 * NPIX;

    auto prefetch = [&](int ci, int s) {
        int pbase = ci * 32;
        uint32_t qb = smem_base + s * GR_STAGE + GR_Q_OFF;
        uint32_t vb = smem_base + s * GR_STAGE + GR_V_OFF;
#pragma unroll
        for (int e = 0; e < 512; e += 256) {
            int u = e + tid;
            int ch = u >> 3, sl = u & 7;
            cp16(qb + ch * GR_XRB + sl * 16, qsrc + (size_t)ch * NPIX + pbase + sl * 4);
        }
#pragma unroll
        for (int e = 0; e < 512; e += 256) {
            int u = e + tid;
            int ch = u >> 3, sl = u & 7;
            cp16(vb + ch * GR_XRB + sl * 16, vsrc + (size_t)ch * NPIX + pbase + sl * 4);
        }
    };

    const int lrow = lane & 15;
    const int lkh  = (lane >> 4) * 8;

    float acc[4][4];
#pragma unroll
    for (int ni = 0; ni < 4; ++ni)
#pragma unroll
        for (int r = 0; r < 4; ++r) acc[ni][r] = 0.f;
    float ssq = 0.f, ssv = 0.f;

    const int cch = tid >> 2;
    const int ppr = (tid & 3) * 4;

    int ci = blockIdx.x;
    int s = 0;
    prefetch(ci, 0);
    CP_COMMIT();

    while (ci < GR_NCHUNK) {
        const int nci = ci + gridDim.x;
        const bool more = nci < GR_NCHUNK;
        if (more) { prefetch(nci, s ^ 1); CP_COMMIT(); CP_WAIT(1); }
        else      { CP_WAIT(0); }
        __syncthreads();

        {
            const float* rq = (const float*)(sm + s * GR_STAGE + GR_Q_OFF) + cch * 36;
            const float* rv = (const float*)(sm + s * GR_STAGE + GR_V_OFF) + cch * 36;
            uint32_t* aq = (uint32_t*)(sm + s * GR_STAGE + GR_A_OFF + cch * GR_RB) + ppr * 3;
            uint32_t* bv = (uint32_t*)(sm + s * GR_STAGE + GR_B_OFF + cch * GR_RB) + ppr * 3;
#pragma unroll
            for (int pr = 0; pr < 4; ++pr) {
                float q0 = rq[ppr * 2 + pr * 2], q1 = rq[ppr * 2 + pr * 2 + 1];
                float v0 = rv[ppr * 2 + pr * 2], v1 = rv[ppr * 2 + pr * 2 + 1];
                ssq += q0 * q0 + q1 * q1;
                ssv += v0 * v0 + v1 * v1;
                float qh0 = __bfloat162float(__float2bfloat16(q0));
                float qh1 = __bfloat162float(__float2bfloat16(q1));
                float vh0 = __bfloat162float(__float2bfloat16(v0));
                float vh1 = __bfloat162float(__float2bfloat16(v1));
                float ql0 = q0 - qh0, ql1 = q1 - qh1;
                float vl0 = v0 - vh0, vl1 = v1 - vh1;
                aq[pr * 3 + 0] = bfpair(qh0, qh0);
                aq[pr * 3 + 1] = bfpair(ql0, qh1);
                aq[pr * 3 + 2] = bfpair(qh1, ql1);
                bv[pr * 3 + 0] = bfpair(vh0, vl0);
                bv[pr * 3 + 1] = bfpair(vh0, vh1);
                bv[pr * 3 + 2] = bfpair(vl1, vh1);
            }
        }
        __syncthreads();

        uint32_t ab = smem_base + s * GR_STAGE + GR_A_OFF;
        uint32_t bb = smem_base + s * GR_STAGE + GR_B_OFF;
#pragma unroll
        for (int ks = 0; ks < 6; ++ks) {
            uint32_t a[4];
            {
                uint32_t addr = ab + (warpM * 16 + lrow) * GR_RB + ks * 32 + lkh * 2;
                ldsm_x4(a[0], a[1], a[2], a[3], addr);
            }
            uint32_t bf[4][2];
#pragma unroll
            for (int nq = 0; nq < 2; ++nq) {
                uint32_t r0, r1, r2, r3;
                uint32_t addr = bb + (warpN * 32 + nq * 16 + lrow) * GR_RB + ks * 32 + lkh * 2;
                ldsm_x4(r0, r1, r2, r3, addr);
                bf[2 * nq][0] = r0;     bf[2 * nq][1] = r2;
                bf[2 * nq + 1][0] = r1; bf[2 * nq + 1][1] = r3;
            }
#pragma unroll
            for (int ni = 0; ni < 4; ++ni)
                mma_bf16(acc[ni], a, bf[ni]);
        }
        __syncthreads();
        ci = nci;
        s ^= 1;
    }

    atomicAdd(&g_sumsq[b * 128 + cch], ssq);
    atomicAdd(&g_sumsq[b * 128 + 64 + cch], ssv);

    const int g = lane >> 2, T = lane & 3;
    float* Gb = g_gram + b * 4096;
#pragma unroll
    for (int ni = 0; ni < 4; ++ni) {
        int n = warpN * 32 + ni * 8 + T * 2;
        int m = warpM * 16 + g;
        atomicAdd(&Gb[m * 64 + n],           acc[ni][0]);
        atomicAdd(&Gb[m * 64 + n + 1],       acc[ni][1]);
        atomicAdd(&Gb[(m + 8) * 64 + n],     acc[ni][2]);
        atomicAdd(&Gb[(m + 8) * 64 + n + 1], acc[ni][3]);
    }
}

// ---------------- norms + softmax + M = w_out @ attn (writes split M) --------
__global__ __launch_bounds__(256) void attn_kernel(
    const float* __restrict__ w_out, const float* __restrict__ temp_p)
{
    __shared__ float attn_s[64 * 65];
    __shared__ float wo_s[64 * 65];
    __shared__ float nrm[128];
    const int tid = threadIdx.x, b = blockIdx.x;

    if (tid < 128) nrm[tid] = fmaxf(sqrtf(g_sumsq[b * 128 + tid]), 1e-12f);
    for (int e = tid; e < 4096; e += 256) {
        int o = e >> 6, c = e & 63;
        wo_s[c * 65 + o] = w_out[e];
    }
    __syncthreads();

    const float temp = *temp_p;
    if (tid < 64) {
        int c = tid;
        float inq = temp / nrm[c];
        float mx = -1e30f;
        for (int d = 0; d < 64; ++d) {
            float l = g_gram[b * 4096 + c * 64 + d] * (inq / nrm[64 + d]);
            attn_s[c * 65 + d] = l;
            mx = fmaxf(mx, l);
        }
        float sum = 0.f;
        for (int d = 0; d < 64; ++d) {
            float e_ = expf(attn_s[c * 65 + d] - mx);
            attn_s[c * 65 + d] = e_;
            sum += e_;
        }
        float inv = 1.f / sum;
        for (int d = 0; d < 64; ++d) attn_s[c * 65 + d] *= inv;
    }
    __syncthreads();

    const int o = tid & 63, dg = tid >> 6;
    for (int d = dg * 16; d < dg * 16 + 16; ++d) {
        float m = 0.f;
#pragma unroll 8
        for (int c2 = 0; c2 < 64; ++c2) m += wo_s[c2 * 65 + o] * attn_s[c2 * 65 + d];
        __nv_bfloat16 hi = __float2bfloat16(m);
        __nv_bfloat16 lo = __float2bfloat16(m - __bfloat162float(hi));
        __nv_bfloat16* dst = g_M2 + ((size_t)b * 64 + o) * 192 + 3 * d;
        dst[0] = hi; dst[1] = hi; dst[2] = lo;
    }
}

// ---------------- tensor-core gemm2: out = M @ v (fused split, round-10) -----
#define G2_A_RB   400
#define G2_A_ARR  (64 * G2_A_RB)
#define G2_B_RB   112
#define G2_B_ARR  (128 * G2_B_RB)
#define G2_X_RB   528
#define G2_X_ARR  (16 * G2_X_RB)
#define G2_STAGE  (G2_B_ARR + G2_X_ARR)
#define G2_SMEM   (G2_A_ARR + 2 * G2_STAGE)
__global__ __launch_bounds__(256, 2) void gemm2_mma(float* __restrict__ out)
{
    extern __shared__ char sm[];
    const int tid = threadIdx.x, wid = tid >> 5, lane = tid & 31;
    const int pbase = blockIdx.x * 128;
    const int b = blockIdx.y;
    const int warpM = wid & 1, warpN = wid >> 1;

    const uint32_t smem_base = smem_to_u32(sm);
    const char*  Agl = (const char*)(g_M2 + (size_t)b * 64 * 192);
    const float* vb  = g_qv + (size_t)b * 128 * NPIX + (size_t)64 * NPIX + pbase;

    auto b_base = [&](int s) { return smem_base + G2_A_ARR + s * G2_STAGE; };
    auto x_base = [&](int s) { return smem_base + G2_A_ARR + s * G2_STAGE + G2_B_ARR; };

#pragma unroll
    for (int e = 0; e < 1536; e += 256) {
        int u = e + tid;
        int r = u / 24, sl = u % 24;
        cp16(smem_base + r * G2_A_RB + sl * 16, Agl + r * 384 + sl * 16);
    }
    auto prefetch = [&](int chunk, int s) {
        uint32_t xbs = x_base(s);
#pragma unroll
        for (int e = 0; e < 512; e += 256) {
            int u = e + tid;
            int ch = u >> 5, sl = u & 31;
            cp16(xbs + ch * G2_X_RB + sl * 16,
                 vb + (size_t)(chunk * 16 + ch) * NPIX + sl * 4);
        }
    };
    prefetch(0, 0);
    CP_COMMIT();

    const int lrow = lane & 15;
    const int lkh  = (lane >> 4) * 8;

    float acc[2][4][4];
#pragma unroll
    for (int mi = 0; mi < 2; ++mi)
#pragma unroll
        for (int ni = 0; ni < 4; ++ni)
#pragma unroll
            for (int r = 0; r < 4; ++r) acc[mi][ni][r] = 0.f;

#pragma unroll
    for (int c = 0; c < 4; ++c) {
        const int s = c & 1;
        if (c < 3) { prefetch(c + 1, s ^ 1); CP_COMMIT(); }
        if (c < 3) CP_WAIT(1); else CP_WAIT(0);
        __syncthreads();

        {
            const float* xs = (const float*)(sm + G2_A_ARR + s * G2_STAGE + G2_B_ARR);
            char* Bs = sm + G2_A_ARR + s * G2_STAGE;
#pragma unroll
            for (int e = 0; e < 1024; e += 256) {
                int u = e + tid;
                int p = u & 127, cp = u >> 7;
                float x0 = xs[(2 * cp) * 132 + p];
                float x1 = xs[(2 * cp + 1) * 132 + p];
                float h0 = __bfloat162float(__float2bfloat16(x0));
                float h1 = __bfloat162float(__float2bfloat16(x1));
                float l0 = x0 - h0, l1 = x1 - h1;
                uint32_t* row = (uint32_t*)(Bs + p * G2_B_RB + cp * 12);
                row[0] = bfpair(h0, l0);
                row[1] = bfpair(h0, h1);
                row[2] = bfpair(l1, h1);
            }
        }
        __syncthreads();

        uint32_t bb = b_base(s);
#pragma unroll
        for (int ksl = 0; ksl < 3; ++ksl) {
            uint32_t a[2][4];
#pragma unroll
            for (int mi = 0; mi < 2; ++mi) {
                uint32_t addr = smem_base + (warpM * 32 + mi * 16 + lrow) * G2_A_RB
                              + c * 96 + ksl * 32 + lkh * 2;
                ldsm_x4(a[mi][0], a[mi][1], a[mi][2], a[mi][3], addr);
            }
            uint32_t bf[4][2];
#pragma unroll
            for (int nq = 0; nq < 2; ++nq) {
                uint32_t r0, r1, r2, r3;
                uint32_t addr = bb + (warpN * 32 + nq * 16 + lrow) * G2_B_RB + ksl * 32 + lkh * 2;
                ldsm_x4(r0, r1, r2, r3, addr);
                bf[2 * nq][0] = r0;     bf[2 * nq][1] = r2;
                bf[2 * nq + 1][0] = r1; bf[2 * nq + 1][1] = r3;
            }
#pragma unroll
            for (int mi = 0; mi < 2; ++mi)
#pragma unroll
                for (int ni = 0; ni < 4; ++ni)
                    mma_bf16(acc[mi][ni], a[mi], bf[ni]);
        }
        __syncthreads();
    }

    const int g = lane >> 2, T = lane & 3;
#pragma unroll
    for (int mi = 0; mi < 2; ++mi) {
        int o = warpM * 32 + mi * 16 + g;
        float* rowp = out + ((size_t)b * 64 + o) * NPIX + pbase + warpN * 32 + T * 2;
#pragma unroll
        for (int ni = 0; ni < 4; ++ni) {
            *(u64*)(rowp + ni * 8) = pack2(acc[mi][ni][0], acc[mi][ni][1]);
            *(u64*)(rowp + ni * 8 + (size_t)8 * NPIX) = pack2(acc[mi][ni][2], acc[mi][ni][3]);
        }
    }
}

// ---------------- launch ------------------------------------------------------
extern "C" void kernel_launch(void* const* d_in, const int* in_sizes, int n_in,
                              void* d_out, int out_size)
{
    const float* x      = (const float*)d_in[0];
    const float* w_in   = (const float*)d_in[1];
    const float* w_dw   = (const float*)d_in[2];
    const float* w_out  = (const float*)d_in[3];
    const float* temp   = (const float*)d_in[4];
    float* out = (float*)d_out;

    cudaFuncSetAttribute(gemm1_fused, cudaFuncAttributeMaxDynamicSharedMemorySize, G1_SMEM);
    cudaFuncSetAttribute(gram_mma,    cudaFuncAttributeMaxDynamicSharedMemorySize, GR_SMEM);
    cudaFuncSetAttribute(gemm2_mma,   cudaFuncAttributeMaxDynamicSharedMemorySize, G2_SMEM);

    // weight split + stat zeroing (merged)
    wsplit<<<64, 256>>>(w_in);

    // t = w_in @ x  (tensor cores, fused bf16-split)
    gemm1_fused<<<dim3(NPIX / 64, 1, BATCH), 256, G1_SMEM>>>(x);

    // depthwise conv + gate -> qv (float4, round-9 config)
    conv_mul<<<dim3(8, 128, BATCH), 256>>>(w_dw);

    // gram + sumsq (tensor cores, grid-stride, 2 full waves)
    gram_mma<<<dim3(148, BATCH), 256, GR_SMEM>>>();

    // norms, softmax, M = w_out @ attn (+ bf16-split M)
    attn_kernel<<<BATCH, 256>>>(w_out, temp);

    // out = M @ v (tensor cores, fused split)
    gemm2_mma<<<dim3(NPIX / 128, BATCH), 256, G2_SMEM>>>(out);
}

// round 12
// speedup vs baseline: 1.7687x; 1.1343x over previous
#include <cuda_runtime.h>
#include <cuda_bf16.h>
#include <math.h>
#include <stdint.h>

typedef unsigned long long u64;

#define NPIX  65536   // 256*256
#define BATCH 4

// ---------------- scratch (device globals: allocation is forbidden) -----------
__device__ float g_t[(size_t)BATCH * 256 * NPIX];     // 256 MB : t = w_in @ x
__device__ float g_qv[(size_t)BATCH * 128 * NPIX];    // 128 MB : q, v
__device__ __nv_bfloat16 g_a2[256 * 192];             // bf16-split w_in, [o][192]
__device__ __nv_bfloat16 g_M2[BATCH * 64 * 192];      // bf16-split M = w_out@attn
__device__ float g_sumsq[BATCH * 128];
__device__ float g_gram[BATCH * 64 * 64];

// ---------------- helpers -----------------------------------------------------
__device__ __forceinline__ u64 pack2(float x, float y) {
    u64 d;
    asm("mov.b64 %0, {%1, %2};" : "=l"(d) : "f"(x), "f"(y));
    return d;
}
__device__ __forceinline__ uint32_t smem_to_u32(const void* p) {
    uint32_t a;
    asm("{ .reg .u64 t; cvta.to.shared.u64 t, %1; cvt.u32.u64 %0, t; }" : "=r"(a) : "l"(p));
    return a;
}
__device__ __forceinline__ void ldsm_x4(uint32_t& r0, uint32_t& r1, uint32_t& r2, uint32_t& r3,
                                        uint32_t addr) {
    asm volatile("ldmatrix.sync.aligned.m8n8.x4.shared.b16 {%0,%1,%2,%3}, [%4];"
        : "=r"(r0), "=r"(r1), "=r"(r2), "=r"(r3) : "r"(addr));
}
__device__ __forceinline__ void mma_bf16(float* d, const uint32_t* a, const uint32_t* b) {
    asm volatile("mma.sync.aligned.m16n8k16.row.col.f32.bf16.bf16.f32 "
        "{%0,%1,%2,%3}, {%4,%5,%6,%7}, {%8,%9}, {%0,%1,%2,%3};"
        : "+f"(d[0]), "+f"(d[1]), "+f"(d[2]), "+f"(d[3])
        : "r"(a[0]), "r"(a[1]), "r"(a[2]), "r"(a[3]), "r"(b[0]), "r"(b[1]));
}
__device__ __forceinline__ void cp16(uint32_t smem_addr, const void* gptr) {
    asm volatile("cp.async.cg.shared.global [%0], [%1], 16;" :: "r"(smem_addr), "l"(gptr));
}
#define CP_COMMIT() asm volatile("cp.async.commit_group;" ::: "memory")
#define CP_WAIT(n)  asm volatile("cp.async.wait_group %0;" :: "n"(n) : "memory")

__device__ __forceinline__ unsigned short bfbits(float v) {
    __nv_bfloat16 h = __float2bfloat16(v);
    return *(unsigned short*)&h;
}
__device__ __forceinline__ uint32_t bfpair(float a, float b) {
    return (uint32_t)bfbits(a) | ((uint32_t)bfbits(b) << 16);
}

// ---------------- weight split + zero stats (merged) --------------------------
__global__ void wsplit(const float* __restrict__ w_in) {
    const int gi = threadIdx.x + blockIdx.x * blockDim.x;
    const int gs = blockDim.x * gridDim.x;
    for (int i = gi; i < 256 * 192; i += gs) {
        int o = i / 192, k = i % 192;
        int c = k / 3, j = k % 3;
        float w = w_in[o * 64 + c];
        __nv_bfloat16 hi = __float2bfloat16(w);
        if (j == 2) g_a2[i] = __float2bfloat16(w - __bfloat162float(hi));
        else        g_a2[i] = hi;
    }
    for (int i = gi; i < BATCH * 128 + BATCH * 64 * 64; i += gs) {
        if (i < BATCH * 128) g_sumsq[i] = 0.f;
        else                 g_gram[i - BATCH * 128] = 0.f;
    }
}

// ---------------- A-resident tensor-core gemm1 --------------------------------
// t = w_in @ x, bf16-split K=192. A (256x192 bf16) staged ONCE per CTA (100KB);
// CTA grid-strides over 64-px tiles: cp.async raw x (16KB) double-buffered,
// in-kernel convert -> B, 12 ksteps mma. 512 threads = 16 warps = 8(m) x 2(n),
// warp tile 32 outs x 32 px. grid (37, 1, BATCH) = 148 CTAs, 1 CTA/SM.
#define GA_RB     400                          // A/B row stride (conflict-free)
#define GA_A_ARR  (256 * GA_RB)                // 102400
#define GA_B_ARR  (64 * GA_RB)                 // 25600
#define GA_X_RB   272                          // raw x row stride (256B data)
#define GA_X_ARR  (64 * GA_X_RB)               // 17408
#define GA_B_OFF  GA_A_ARR
#define GA_X_OFF  (GA_A_ARR + 2 * GA_B_ARR)
#define GA_SMEM   (GA_A_ARR + 2 * GA_B_ARR + 2 * GA_X_ARR)   // 188416
#define GA_NTILE  1024                         // NPIX / 64 per batch
#define GA_GRIDX  37
__global__ __launch_bounds__(512, 1) void gemm1_res(const float* __restrict__ x) {
    extern __shared__ char sm[];
    const int tid = threadIdx.x, wid = tid >> 5, lane = tid & 31;
    const int b = blockIdx.z;
    const int wm = wid & 7, wn = wid >> 3;

    const uint32_t smem_base = smem_to_u32(sm);
    const char*  Agl = (const char*)g_a2;                 // [256][384B]
    const float* xb  = x + (size_t)b * 64 * NPIX;

    // stage A once: 256 rows x 24 slabs of 16B
#pragma unroll
    for (int e = 0; e < 6144; e += 512) {
        int u = e + tid;
        int r = u / 24, sl = u % 24;
        cp16(smem_base + r * GA_RB + sl * 16, Agl + r * 384 + sl * 16);
    }

    auto prefetch_x = [&](int t, int s) {
        uint32_t xbs = smem_base + GA_X_OFF + s * GA_X_ARR;
        const float* src = xb + t * 64;
#pragma unroll
        for (int e = 0; e < 1024; e += 512) {
            int u = e + tid;
            int ch = u >> 4, sl = u & 15;
            cp16(xbs + ch * GA_X_RB + sl * 16, src + (size_t)ch * NPIX + sl * 4);
        }
    };

    const int lrow = lane & 15;
    const int lkh  = (lane >> 4) * 8;
    const int g = lane >> 2, T = lane & 3;
    const int cp_p  = tid & 63;      // convert: pixel
    const int cp_g  = tid >> 6;      // convert: channel-pair group (0..7)

    int t = blockIdx.x;
    int s = 0;
    prefetch_x(t, 0);
    CP_COMMIT();

    while (t < GA_NTILE) {
        const int nt = t + GA_GRIDX;
        CP_WAIT(0);
        __syncthreads();

        // convert raw x[s] -> B[s]: per thread 4 channel-pairs of one pixel
        {
            const float* xs = (const float*)(sm + GA_X_OFF + s * GA_X_ARR);
            uint32_t* brow = (uint32_t*)(sm + GA_B_OFF + s * GA_B_ARR + cp_p * GA_RB) + cp_g * 12;
            uint32_t w[12];
#pragma unroll
            for (int i = 0; i < 4; ++i) {
                int cpi = cp_g * 4 + i;
                float x0 = xs[(2 * cpi) * 68 + cp_p];
                float x1 = xs[(2 * cpi + 1) * 68 + cp_p];
                float h0 = __bfloat162float(__float2bfloat16(x0));
                float h1 = __bfloat162float(__float2bfloat16(x1));
                float l0 = x0 - h0, l1 = x1 - h1;
                w[i * 3 + 0] = bfpair(h0, l0);   // k=6cp   : xhi(c0), xlo(c0)
                w[i * 3 + 1] = bfpair(h0, h1);   // k=6cp+2 : xhi(c0), xhi(c1)
                w[i * 3 + 2] = bfpair(l1, h1);   // k=6cp+4 : xlo(c1), xhi(c1)
            }
#pragma unroll
            for (int i = 0; i < 3; ++i)
                *(uint4*)(brow + i * 4) = make_uint4(w[i*4], w[i*4+1], w[i*4+2], w[i*4+3]);
        }
        __syncthreads();

        if (nt < GA_NTILE) { prefetch_x(nt, s ^ 1); CP_COMMIT(); }

        // mma: warp = 32 outs x 32 px, K=192 in 12 steps
        float acc[2][4][4];
#pragma unroll
        for (int mi = 0; mi < 2; ++mi)
#pragma unroll
            for (int ni = 0; ni < 4; ++ni)
#pragma unroll
                for (int r = 0; r < 4; ++r) acc[mi][ni][r] = 0.f;

        uint32_t bb = smem_base + GA_B_OFF + s * GA_B_ARR;
#pragma unroll
        for (int ks = 0; ks < 12; ++ks) {
            uint32_t a[2][4];
#pragma unroll
            for (int mi = 0; mi < 2; ++mi) {
                uint32_t addr = smem_base + (wm * 32 + mi * 16 + lrow) * GA_RB + ks * 32 + lkh * 2;
                ldsm_x4(a[mi][0], a[mi][1], a[mi][2], a[mi][3], addr);
            }
            uint32_t bf[4][2];
#pragma unroll
            for (int nq = 0; nq < 2; ++nq) {
                uint32_t r0, r1, r2, r3;
                uint32_t addr = bb + (wn * 32 + nq * 16 + lrow) * GA_RB + ks * 32 + lkh * 2;
                ldsm_x4(r0, r1, r2, r3, addr);
                bf[2 * nq][0] = r0;     bf[2 * nq][1] = r2;
                bf[2 * nq + 1][0] = r1; bf[2 * nq + 1][1] = r3;
            }
#pragma unroll
            for (int mi = 0; mi < 2; ++mi)
#pragma unroll
                for (int ni = 0; ni < 4; ++ni)
                    mma_bf16(acc[mi][ni], a[mi], bf[ni]);
        }

        // epilogue: t tile pbase = t*64
#pragma unroll
        for (int mi = 0; mi < 2; ++mi) {
            int m = wm * 32 + mi * 16 + g;
            float* rowp = g_t + ((size_t)b * 256 + m) * NPIX + t * 64 + wn * 32 + T * 2;
#pragma unroll
            for (int ni = 0; ni < 4; ++ni) {
                *(u64*)(rowp + ni * 8) = pack2(acc[mi][ni][0], acc[mi][ni][1]);
                *(u64*)(rowp + ni * 8 + (size_t)8 * NPIX) = pack2(acc[mi][ni][2], acc[mi][ni][3]);
            }
        }
        t = nt;
        s ^= 1;
    }
}

// ---------------- depthwise 3x3 conv + gate, float4 (round-9 exact) ----------
__global__ __launch_bounds__(256) void conv_mul(const float* __restrict__ w_dw)
{
    __shared__ float st[34][264];
    const int tid = threadIdx.x;
    const int jj = blockIdx.y, b = blockIdx.z, r0 = blockIdx.x * 32;

    const float* t1 = g_t + ((size_t)b * 256 + jj) * NPIX;
    const float* t2 = g_t + ((size_t)b * 256 + 128 + jj) * NPIX;
    float* outp = g_qv + ((size_t)b * 128 + jj) * NPIX;

    float wd[9];
#pragma unroll
    for (int i = 0; i < 9; ++i) wd[i] = w_dw[jj * 9 + i];

#pragma unroll
    for (int e = 0; e < 2176; e += 256) {
        int u = e + tid;
        if (u < 2176) {
            int rr = u >> 6, q4 = u & 63;
            int row = r0 - 1 + rr;
            float4 v = make_float4(0.f, 0.f, 0.f, 0.f);
            if (row >= 0 && row < 256)
                v = *(const float4*)(t1 + row * 256 + q4 * 4);
            *(float4*)&st[rr][4 + q4 * 4] = v;
        }
    }
    if (tid < 34) { st[tid][3] = 0.f; st[tid][260] = 0.f; }
    __syncthreads();

    const int ty = tid >> 6, tc = tid & 63;
    const int c0 = tc * 4;
#pragma unroll
    for (int r = ty * 8; r < ty * 8 + 8; ++r) {
        float s0 = 0.f, s1 = 0.f, s2 = 0.f, s3 = 0.f;
#pragma unroll
        for (int ky = 0; ky < 3; ++ky) {
            const float* rowp = &st[r + ky][4 + c0];
            float4 m = *(const float4*)rowp;
            float left = rowp[-1], right = rowp[4];
            float w0 = wd[ky * 3 + 0], w1 = wd[ky * 3 + 1], w2 = wd[ky * 3 + 2];
            s0 += w0 * left + w1 * m.x + w2 * m.y;
            s1 += w0 * m.x  + w1 * m.y + w2 * m.z;
            s2 += w0 * m.y  + w1 * m.z + w2 * m.w;
            s3 += w0 * m.z  + w1 * m.w + w2 * right;
        }
        int p = (r0 + r) * 256 + c0;
        float4 g4 = *(const float4*)(t2 + p);
        float4 o = make_float4(s0 * g4.x, s1 * g4.y, s2 * g4.z, s3 * g4.w);
        *(float4*)(outp + p) = o;
    }
}

// ---------------- tensor-core gram + sumsq (round-11 exact) -------------------
#define GR_RB     208
#define GR_XRB    144
#define GR_A_OFF  0
#define GR_B_OFF  13312
#define GR_Q_OFF  26624
#define GR_V_OFF  35840
#define GR_STAGE  45056
#define GR_SMEM   (2 * GR_STAGE)
#define GR_NCHUNK 2048
__global__ __launch_bounds__(256, 2) void gram_mma()
{
    extern __shared__ char sm[];
    const int tid = threadIdx.x, wid = tid >> 5, lane = tid & 31;
    const int b = blockIdx.y;
    const int warpM = wid & 3, warpN = wid >> 2;

    const uint32_t smem_base = smem_to_u32(sm);
    const float* qsrc = g_qv + (size_t)b * 128 * NPIX;
    const float* vsrc = qsrc + (size_t)64 * NPIX;

    auto prefetch = [&](int ci, int s) {
        int pbase = ci * 32;
        uint32_t qb = smem_base + s * GR_STAGE + GR_Q_OFF;
        uint32_t vb = smem_base + s * GR_STAGE + GR_V_OFF;
#pragma unroll
        for (int e = 0; e < 512; e += 256) {
            int u = e + tid;
            int ch = u >> 3, sl = u & 7;
            cp16(qb + ch * GR_XRB + sl * 16, qsrc + (size_t)ch * NPIX + pbase + sl * 4);
        }
#pragma unroll
        for (int e = 0; e < 512; e += 256) {
            int u = e + tid;
            int ch = u >> 3, sl = u & 7;
            cp16(vb + ch * GR_XRB + sl * 16, vsrc + (size_t)ch * NPIX + pbase + sl * 4);
        }
    };

    const int lrow = lane & 15;
    const int lkh  = (lane >> 4) * 8;

    float acc[4][4];
#pragma unroll
    for (int ni = 0; ni < 4; ++ni)
#pragma unroll
        for (int r = 0; r < 4; ++r) acc[ni][r] = 0.f;
    float ssq = 0.f, ssv = 0.f;

    const int cch = tid >> 2;
    const int ppr = (tid & 3) * 4;

    int ci = blockIdx.x;
    int s = 0;
    prefetch(ci, 0);
    CP_COMMIT();

    while (ci < GR_NCHUNK) {
        const int nci = ci + gridDim.x;
        const bool more = nci < GR_NCHUNK;
        if (more) { prefetch(nci, s ^ 1); CP_COMMIT(); CP_WAIT(1); }
        else      { CP_WAIT(0); }
        __syncthreads();

        {
            const float* rq = (const float*)(sm + s * GR_STAGE + GR_Q_OFF) + cch * 36;
            const float* rv = (const float*)(sm + s * GR_STAGE + GR_V_OFF) + cch * 36;
            uint32_t* aq = (uint32_t*)(sm + s * GR_STAGE + GR_A_OFF + cch * GR_RB) + ppr * 3;
            uint32_t* bv = (uint32_t*)(sm + s * GR_STAGE + GR_B_OFF + cch * GR_RB) + ppr * 3;
#pragma unroll
            for (int pr = 0; pr < 4; ++pr) {
                float q0 = rq[ppr * 2 + pr * 2], q1 = rq[ppr * 2 + pr * 2 + 1];
                float v0 = rv[ppr * 2 + pr * 2], v1 = rv[ppr * 2 + pr * 2 + 1];
                ssq += q0 * q0 + q1 * q1;
                ssv += v0 * v0 + v1 * v1;
                float qh0 = __bfloat162float(__float2bfloat16(q0));
                float qh1 = __bfloat162float(__float2bfloat16(q1));
                float vh0 = __bfloat162float(__float2bfloat16(v0));
                float vh1 = __bfloat162float(__float2bfloat16(v1));
                float ql0 = q0 - qh0, ql1 = q1 - qh1;
                float vl0 = v0 - vh0, vl1 = v1 - vh1;
                aq[pr * 3 + 0] = bfpair(qh0, qh0);
                aq[pr * 3 + 1] = bfpair(ql0, qh1);
                aq[pr * 3 + 2] = bfpair(qh1, ql1);
                bv[pr * 3 + 0] = bfpair(vh0, vl0);
                bv[pr * 3 + 1] = bfpair(vh0, vh1);
                bv[pr * 3 + 2] = bfpair(vl1, vh1);
            }
        }
        __syncthreads();

        uint32_t ab = smem_base + s * GR_STAGE + GR_A_OFF;
        uint32_t bb = smem_base + s * GR_STAGE + GR_B_OFF;
#pragma unroll
        for (int ks = 0; ks < 6; ++ks) {
            uint32_t a[4];
            {
                uint32_t addr = ab + (warpM * 16 + lrow) * GR_RB + ks * 32 + lkh * 2;
                ldsm_x4(a[0], a[1], a[2], a[3], addr);
            }
            uint32_t bf[4][2];
#pragma unroll
            for (int nq = 0; nq < 2; ++nq) {
                uint32_t r0, r1, r2, r3;
                uint32_t addr = bb + (warpN * 32 + nq * 16 + lrow) * GR_RB + ks * 32 + lkh * 2;
                ldsm_x4(r0, r1, r2, r3, addr);
                bf[2 * nq][0] = r0;     bf[2 * nq][1] = r2;
                bf[2 * nq + 1][0] = r1; bf[2 * nq + 1][1] = r3;
            }
#pragma unroll
            for (int ni = 0; ni < 4; ++ni)
                mma_bf16(acc[ni], a, bf[ni]);
        }
        __syncthreads();
        ci = nci;
        s ^= 1;
    }

    atomicAdd(&g_sumsq[b * 128 + cch], ssq);
    atomicAdd(&g_sumsq[b * 128 + 64 + cch], ssv);

    const int g = lane >> 2, T = lane & 3;
    float* Gb = g_gram + b * 4096;
#pragma unroll
    for (int ni = 0; ni < 4; ++ni) {
        int n = warpN * 32 + ni * 8 + T * 2;
        int m = warpM * 16 + g;
        atomicAdd(&Gb[m * 64 + n],           acc[ni][0]);
        atomicAdd(&Gb[m * 64 + n + 1],       acc[ni][1]);
        atomicAdd(&Gb[(m + 8) * 64 + n],     acc[ni][2]);
        atomicAdd(&Gb[(m + 8) * 64 + n + 1], acc[ni][3]);
    }
}

// ---------------- norms + softmax + M = w_out @ attn (writes split M) --------
__global__ __launch_bounds__(256) void attn_kernel(
    const float* __restrict__ w_out, const float* __restrict__ temp_p)
{
    __shared__ float attn_s[64 * 65];
    __shared__ float wo_s[64 * 65];
    __shared__ float nrm[128];
    const int tid = threadIdx.x, b = blockIdx.x;

    if (tid < 128) nrm[tid] = fmaxf(sqrtf(g_sumsq[b * 128 + tid]), 1e-12f);
    for (int e = tid; e < 4096; e += 256) {
        int o = e >> 6, c = e & 63;
        wo_s[c * 65 + o] = w_out[e];
    }
    __syncthreads();

    const float temp = *temp_p;
    if (tid < 64) {
        int c = tid;
        float inq = temp / nrm[c];
        float mx = -1e30f;
        for (int d = 0; d < 64; ++d) {
            float l = g_gram[b * 4096 + c * 64 + d] * (inq / nrm[64 + d]);
            attn_s[c * 65 + d] = l;
            mx = fmaxf(mx, l);
        }
        float sum = 0.f;
        for (int d = 0; d < 64; ++d) {
            float e_ = expf(attn_s[c * 65 + d] - mx);
            attn_s[c * 65 + d] = e_;
            sum += e_;
        }
        float inv = 1.f / sum;
        for (int d = 0; d < 64; ++d) attn_s[c * 65 + d] *= inv;
    }
    __syncthreads();

    const int o = tid & 63, dg = tid >> 6;
    for (int d = dg * 16; d < dg * 16 + 16; ++d) {
        float m = 0.f;
#pragma unroll 8
        for (int c2 = 0; c2 < 64; ++c2) m += wo_s[c2 * 65 + o] * attn_s[c2 * 65 + d];
        __nv_bfloat16 hi = __float2bfloat16(m);
        __nv_bfloat16 lo = __float2bfloat16(m - __bfloat162float(hi));
        __nv_bfloat16* dst = g_M2 + ((size_t)b * 64 + o) * 192 + 3 * d;
        dst[0] = hi; dst[1] = hi; dst[2] = lo;
    }
}

// ---------------- tensor-core gemm2: out = M @ v (round-10 exact) -------------
#define G2_A_RB   400
#define G2_A_ARR  (64 * G2_A_RB)
#define G2_B_RB   112
#define G2_B_ARR  (128 * G2_B_RB)
#define G2_X_RB   528
#define G2_X_ARR  (16 * G2_X_RB)
#define G2_STAGE  (G2_B_ARR + G2_X_ARR)
#define G2_SMEM   (G2_A_ARR + 2 * G2_STAGE)
__global__ __launch_bounds__(256, 2) void gemm2_mma(float* __restrict__ out)
{
    extern __shared__ char sm[];
    const int tid = threadIdx.x, wid = tid >> 5, lane = tid & 31;
    const int pbase = blockIdx.x * 128;
    const int b = blockIdx.y;
    const int warpM = wid & 1, warpN = wid >> 1;

    const uint32_t smem_base = smem_to_u32(sm);
    const char*  Agl = (const char*)(g_M2 + (size_t)b * 64 * 192);
    const float* vb  = g_qv + (size_t)b * 128 * NPIX + (size_t)64 * NPIX + pbase;

    auto b_base = [&](int s) { return smem_base + G2_A_ARR + s * G2_STAGE; };
    auto x_base = [&](int s) { return smem_base + G2_A_ARR + s * G2_STAGE + G2_B_ARR; };

#pragma unroll
    for (int e = 0; e < 1536; e += 256) {
        int u = e + tid;
        int r = u / 24, sl = u % 24;
        cp16(smem_base + r * G2_A_RB + sl * 16, Agl + r * 384 + sl * 16);
    }
    auto prefetch = [&](int chunk, int s) {
        uint32_t xbs = x_base(s);
#pragma unroll
        for (int e = 0; e < 512; e += 256) {
            int u = e + tid;
            int ch = u >> 5, sl = u & 31;
            cp16(xbs + ch * G2_X_RB + sl * 16,
                 vb + (size_t)(chunk * 16 + ch) * NPIX + sl * 4);
        }
    };
    prefetch(0, 0);
    CP_COMMIT();

    const int lrow = lane & 15;
    const int lkh  = (lane >> 4) * 8;

    float acc[2][4][4];
#pragma unroll
    for (int mi = 0; mi < 2; ++mi)
#pragma unroll
        for (int ni = 0; ni < 4; ++ni)
#pragma unroll
            for (int r = 0; r < 4; ++r) acc[mi][ni][r] = 0.f;

#pragma unroll
    for (int c = 0; c < 4; ++c) {
        const int s = c & 1;
        if (c < 3) { prefetch(c + 1, s ^ 1); CP_COMMIT(); }
        if (c < 3) CP_WAIT(1); else CP_WAIT(0);
        __syncthreads();

        {
            const float* xs = (const float*)(sm + G2_A_ARR + s * G2_STAGE + G2_B_ARR);
            char* Bs = sm + G2_A_ARR + s * G2_STAGE;
#pragma unroll
            for (int e = 0; e < 1024; e += 256) {
                int u = e + tid;
                int p = u & 127, cp = u >> 7;
                float x0 = xs[(2 * cp) * 132 + p];
                float x1 = xs[(2 * cp + 1) * 132 + p];
                float h0 = __bfloat162float(__float2bfloat16(x0));
                float h1 = __bfloat162float(__float2bfloat16(x1));
                float l0 = x0 - h0, l1 = x1 - h1;
                uint32_t* row = (uint32_t*)(Bs + p * G2_B_RB + cp * 12);
                row[0] = bfpair(h0, l0);
                row[1] = bfpair(h0, h1);
                row[2] = bfpair(l1, h1);
            }
        }
        __syncthreads();

        uint32_t bb = b_base(s);
#pragma unroll
        for (int ksl = 0; ksl < 3; ++ksl) {
            uint32_t a[2][4];
#pragma unroll
            for (int mi = 0; mi < 2; ++mi) {
                uint32_t addr = smem_base + (warpM * 32 + mi * 16 + lrow) * G2_A_RB
                              + c * 96 + ksl * 32 + lkh * 2;
                ldsm_x4(a[mi][0], a[mi][1], a[mi][2], a[mi][3], addr);
            }
            uint32_t bf[4][2];
#pragma unroll
            for (int nq = 0; nq < 2; ++nq) {
                uint32_t r0, r1, r2, r3;
                uint32_t addr = bb + (warpN * 32 + nq * 16 + lrow) * G2_B_RB + ksl * 32 + lkh * 2;
                ldsm_x4(r0, r1, r2, r3, addr);
                bf[2 * nq][0] = r0;     bf[2 * nq][1] = r2;
                bf[2 * nq + 1][0] = r1; bf[2 * nq + 1][1] = r3;
            }
#pragma unroll
            for (int mi = 0; mi < 2; ++mi)
#pragma unroll
                for (int ni = 0; ni < 4; ++ni)
                    mma_bf16(acc[mi][ni], a[mi], bf[ni]);
        }
        __syncthreads();
    }

    const int g = lane >> 2, T = lane & 3;
#pragma unroll
    for (int mi = 0; mi < 2; ++mi) {
        int o = warpM * 32 + mi * 16 + g;
        float* rowp = out + ((size_t)b * 64 + o) * NPIX + pbase + warpN * 32 + T * 2;
#pragma unroll
        for (int ni = 0; ni < 4; ++ni) {
            *(u64*)(rowp + ni * 8) = pack2(acc[mi][ni][0], acc[mi][ni][1]);
            *(u64*)(rowp + ni * 8 + (size_t)8 * NPIX) = pack2(acc[mi][ni][2], acc[mi][ni][3]);
        }
    }
}

// ---------------- launch ------------------------------------------------------
extern "C" void kernel_launch(void* const* d_in, const int* in_sizes, int n_in,
                              void* d_out, int out_size)
{
    const float* x      = (const float*)d_in[0];
    const float* w_in   = (const float*)d_in[1];
    const float* w_dw   = (const float*)d_in[2];
    const float* w_out  = (const float*)d_in[3];
    const float* temp   = (const float*)d_in[4];
    float* out = (float*)d_out;

    cudaFuncSetAttribute(gemm1_res, cudaFuncAttributeMaxDynamicSharedMemorySize, GA_SMEM);
    cudaFuncSetAttribute(gram_mma,  cudaFuncAttributeMaxDynamicSharedMemorySize, GR_SMEM);
    cudaFuncSetAttribute(gemm2_mma, cudaFuncAttributeMaxDynamicSharedMemorySize, G2_SMEM);

    // weight split + stat zeroing (merged)
    wsplit<<<64, 256>>>(w_in);

    // t = w_in @ x  (tensor cores, A-resident, fused bf16-split)
    gemm1_res<<<dim3(GA_GRIDX, 1, BATCH), 512, GA_SMEM>>>(x);

    // depthwise conv + gate -> qv (float4)
    conv_mul<<<dim3(8, 128, BATCH), 256>>>(w_dw);

    // gram + sumsq (tensor cores, grid-stride)
    gram_mma<<<dim3(148, BATCH), 256, GR_SMEM>>>();

    // norms, softmax, M = w_out @ attn (+ bf16-split M)
    attn_kernel<<<BATCH, 256>>>(w_out, temp);

    // out = M @ v (tensor cores, fused split)
    gemm2_mma<<<dim3(NPIX / 128, BATCH), 256, G2_SMEM>>>(out);
}

// round 13
// speedup vs baseline: 1.8674x; 1.0558x over previous
#include <cuda_runtime.h>
#include <cuda_bf16.h>
#include <math.h>
#include <stdint.h>

typedef unsigned long long u64;

#define NPIX  65536   // 256*256
#define BATCH 4

// ---------------- scratch (device globals: allocation is forbidden) -----------
__device__ float g_t[(size_t)BATCH * 256 * NPIX];     // 256 MB : t = w_in @ x
__device__ float g_qv[(size_t)BATCH * 128 * NPIX];    // 128 MB : q, v
__device__ __nv_bfloat16 g_a2[256 * 192];             // bf16-split w_in, [o][192]
__device__ __nv_bfloat16 g_M2[BATCH * 64 * 192];      // bf16-split M = w_out@attn
__device__ float g_sumsq[BATCH * 128];
__device__ float g_gram[BATCH * 64 * 64];

// ---------------- helpers -----------------------------------------------------
__device__ __forceinline__ u64 pack2(float x, float y) {
    u64 d;
    asm("mov.b64 %0, {%1, %2};" : "=l"(d) : "f"(x), "f"(y));
    return d;
}
__device__ __forceinline__ uint32_t smem_to_u32(const void* p) {
    uint32_t a;
    asm("{ .reg .u64 t; cvta.to.shared.u64 t, %1; cvt.u32.u64 %0, t; }" : "=r"(a) : "l"(p));
    return a;
}
__device__ __forceinline__ void ldsm_x4(uint32_t& r0, uint32_t& r1, uint32_t& r2, uint32_t& r3,
                                        uint32_t addr) {
    asm volatile("ldmatrix.sync.aligned.m8n8.x4.shared.b16 {%0,%1,%2,%3}, [%4];"
        : "=r"(r0), "=r"(r1), "=r"(r2), "=r"(r3) : "r"(addr));
}
__device__ __forceinline__ void mma_bf16(float* d, const uint32_t* a, const uint32_t* b) {
    asm volatile("mma.sync.aligned.m16n8k16.row.col.f32.bf16.bf16.f32 "
        "{%0,%1,%2,%3}, {%4,%5,%6,%7}, {%8,%9}, {%0,%1,%2,%3};"
        : "+f"(d[0]), "+f"(d[1]), "+f"(d[2]), "+f"(d[3])
        : "r"(a[0]), "r"(a[1]), "r"(a[2]), "r"(a[3]), "r"(b[0]), "r"(b[1]));
}
__device__ __forceinline__ void cp16(uint32_t smem_addr, const void* gptr) {
    asm volatile("cp.async.cg.shared.global [%0], [%1], 16;" :: "r"(smem_addr), "l"(gptr));
}
#define CP_COMMIT() asm volatile("cp.async.commit_group;" ::: "memory")
#define CP_WAIT(n)  asm volatile("cp.async.wait_group %0;" :: "n"(n) : "memory")

__device__ __forceinline__ unsigned short bfbits(float v) {
    __nv_bfloat16 h = __float2bfloat16(v);
    return *(unsigned short*)&h;
}
__device__ __forceinline__ uint32_t bfpair(float a, float b) {
    return (uint32_t)bfbits(a) | ((uint32_t)bfbits(b) << 16);
}

// ---------------- weight split + zero stats (merged) --------------------------
__global__ void wsplit(const float* __restrict__ w_in) {
    const int gi = threadIdx.x + blockIdx.x * blockDim.x;
    const int gs = blockDim.x * gridDim.x;
    for (int i = gi; i < 256 * 192; i += gs) {
        int o = i / 192, k = i % 192;
        int c = k / 3, j = k % 3;
        float w = w_in[o * 64 + c];
        __nv_bfloat16 hi = __float2bfloat16(w);
        if (j == 2) g_a2[i] = __float2bfloat16(w - __bfloat162float(hi));
        else        g_a2[i] = hi;
    }
    for (int i = gi; i < BATCH * 128 + BATCH * 64 * 64; i += gs) {
        if (i < BATCH * 128) g_sumsq[i] = 0.f;
        else                 g_gram[i - BATCH * 128] = 0.f;
    }
}

// ---------------- A-resident tensor-core gemm1 (round-12 exact) ---------------
#define GA_RB     400
#define GA_A_ARR  (256 * GA_RB)
#define GA_B_ARR  (64 * GA_RB)
#define GA_X_RB   272
#define GA_X_ARR  (64 * GA_X_RB)
#define GA_B_OFF  GA_A_ARR
#define GA_X_OFF  (GA_A_ARR + 2 * GA_B_ARR)
#define GA_SMEM   (GA_A_ARR + 2 * GA_B_ARR + 2 * GA_X_ARR)
#define GA_NTILE  1024
#define GA_GRIDX  37
__global__ __launch_bounds__(512, 1) void gemm1_res(const float* __restrict__ x) {
    extern __shared__ char sm[];
    const int tid = threadIdx.x, wid = tid >> 5, lane = tid & 31;
    const int b = blockIdx.z;
    const int wm = wid & 7, wn = wid >> 3;

    const uint32_t smem_base = smem_to_u32(sm);
    const char*  Agl = (const char*)g_a2;
    const float* xb  = x + (size_t)b * 64 * NPIX;

#pragma unroll
    for (int e = 0; e < 6144; e += 512) {
        int u = e + tid;
        int r = u / 24, sl = u % 24;
        cp16(smem_base + r * GA_RB + sl * 16, Agl + r * 384 + sl * 16);
    }

    auto prefetch_x = [&](int t, int s) {
        uint32_t xbs = smem_base + GA_X_OFF + s * GA_X_ARR;
        const float* src = xb + t * 64;
#pragma unroll
        for (int e = 0; e < 1024; e += 512) {
            int u = e + tid;
            int ch = u >> 4, sl = u & 15;
            cp16(xbs + ch * GA_X_RB + sl * 16, src + (size_t)ch * NPIX + sl * 4);
        }
    };

    const int lrow = lane & 15;
    const int lkh  = (lane >> 4) * 8;
    const int g = lane >> 2, T = lane & 3;
    const int cp_p  = tid & 63;
    const int cp_g  = tid >> 6;

    int t = blockIdx.x;
    int s = 0;
    prefetch_x(t, 0);
    CP_COMMIT();

    while (t < GA_NTILE) {
        const int nt = t + GA_GRIDX;
        CP_WAIT(0);
        __syncthreads();

        {
            const float* xs = (const float*)(sm + GA_X_OFF + s * GA_X_ARR);
            uint32_t* brow = (uint32_t*)(sm + GA_B_OFF + s * GA_B_ARR + cp_p * GA_RB) + cp_g * 12;
            uint32_t w[12];
#pragma unroll
            for (int i = 0; i < 4; ++i) {
                int cpi = cp_g * 4 + i;
                float x0 = xs[(2 * cpi) * 68 + cp_p];
                float x1 = xs[(2 * cpi + 1) * 68 + cp_p];
                float h0 = __bfloat162float(__float2bfloat16(x0));
                float h1 = __bfloat162float(__float2bfloat16(x1));
                float l0 = x0 - h0, l1 = x1 - h1;
                w[i * 3 + 0] = bfpair(h0, l0);
                w[i * 3 + 1] = bfpair(h0, h1);
                w[i * 3 + 2] = bfpair(l1, h1);
            }
#pragma unroll
            for (int i = 0; i < 3; ++i)
                *(uint4*)(brow + i * 4) = make_uint4(w[i*4], w[i*4+1], w[i*4+2], w[i*4+3]);
        }
        __syncthreads();

        if (nt < GA_NTILE) { prefetch_x(nt, s ^ 1); CP_COMMIT(); }

        float acc[2][4][4];
#pragma unroll
        for (int mi = 0; mi < 2; ++mi)
#pragma unroll
            for (int ni = 0; ni < 4; ++ni)
#pragma unroll
                for (int r = 0; r < 4; ++r) acc[mi][ni][r] = 0.f;

        uint32_t bb = smem_base + GA_B_OFF + s * GA_B_ARR;
#pragma unroll
        for (int ks = 0; ks < 12; ++ks) {
            uint32_t a[2][4];
#pragma unroll
            for (int mi = 0; mi < 2; ++mi) {
                uint32_t addr = smem_base + (wm * 32 + mi * 16 + lrow) * GA_RB + ks * 32 + lkh * 2;
                ldsm_x4(a[mi][0], a[mi][1], a[mi][2], a[mi][3], addr);
            }
            uint32_t bf[4][2];
#pragma unroll
            for (int nq = 0; nq < 2; ++nq) {
                uint32_t r0, r1, r2, r3;
                uint32_t addr = bb + (wn * 32 + nq * 16 + lrow) * GA_RB + ks * 32 + lkh * 2;
                ldsm_x4(r0, r1, r2, r3, addr);
                bf[2 * nq][0] = r0;     bf[2 * nq][1] = r2;
                bf[2 * nq + 1][0] = r1; bf[2 * nq + 1][1] = r3;
            }
#pragma unroll
            for (int mi = 0; mi < 2; ++mi)
#pragma unroll
                for (int ni = 0; ni < 4; ++ni)
                    mma_bf16(acc[mi][ni], a[mi], bf[ni]);
        }

#pragma unroll
        for (int mi = 0; mi < 2; ++mi) {
            int m = wm * 32 + mi * 16 + g;
            float* rowp = g_t + ((size_t)b * 256 + m) * NPIX + t * 64 + wn * 32 + T * 2;
#pragma unroll
            for (int ni = 0; ni < 4; ++ni) {
                *(u64*)(rowp + ni * 8) = pack2(acc[mi][ni][0], acc[mi][ni][1]);
                *(u64*)(rowp + ni * 8 + (size_t)8 * NPIX) = pack2(acc[mi][ni][2], acc[mi][ni][3]);
            }
        }
        t = nt;
        s ^= 1;
    }
}

// ---------------- depthwise 3x3 conv + gate, float4 (round-9 exact) ----------
__global__ __launch_bounds__(256) void conv_mul(const float* __restrict__ w_dw)
{
    __shared__ float st[34][264];
    const int tid = threadIdx.x;
    const int jj = blockIdx.y, b = blockIdx.z, r0 = blockIdx.x * 32;

    const float* t1 = g_t + ((size_t)b * 256 + jj) * NPIX;
    const float* t2 = g_t + ((size_t)b * 256 + 128 + jj) * NPIX;
    float* outp = g_qv + ((size_t)b * 128 + jj) * NPIX;

    float wd[9];
#pragma unroll
    for (int i = 0; i < 9; ++i) wd[i] = w_dw[jj * 9 + i];

#pragma unroll
    for (int e = 0; e < 2176; e += 256) {
        int u = e + tid;
        if (u < 2176) {
            int rr = u >> 6, q4 = u & 63;
            int row = r0 - 1 + rr;
            float4 v = make_float4(0.f, 0.f, 0.f, 0.f);
            if (row >= 0 && row < 256)
                v = *(const float4*)(t1 + row * 256 + q4 * 4);
            *(float4*)&st[rr][4 + q4 * 4] = v;
        }
    }
    if (tid < 34) { st[tid][3] = 0.f; st[tid][260] = 0.f; }
    __syncthreads();

    const int ty = tid >> 6, tc = tid & 63;
    const int c0 = tc * 4;
#pragma unroll
    for (int r = ty * 8; r < ty * 8 + 8; ++r) {
        float s0 = 0.f, s1 = 0.f, s2 = 0.f, s3 = 0.f;
#pragma unroll
        for (int ky = 0; ky < 3; ++ky) {
            const float* rowp = &st[r + ky][4 + c0];
            float4 m = *(const float4*)rowp;
            float left = rowp[-1], right = rowp[4];
            float w0 = wd[ky * 3 + 0], w1 = wd[ky * 3 + 1], w2 = wd[ky * 3 + 2];
            s0 += w0 * left + w1 * m.x + w2 * m.y;
            s1 += w0 * m.x  + w1 * m.y + w2 * m.z;
            s2 += w0 * m.y  + w1 * m.z + w2 * m.w;
            s3 += w0 * m.z  + w1 * m.w + w2 * right;
        }
        int p = (r0 + r) * 256 + c0;
        float4 g4 = *(const float4*)(t2 + p);
        float4 o = make_float4(s0 * g4.x, s1 * g4.y, s2 * g4.z, s3 * g4.w);
        *(float4*)(outp + p) = o;
    }
}

// ---------------- tensor-core gram + sumsq (vectorized convert) ---------------
#define GR_RB     208
#define GR_XRB    144
#define GR_A_OFF  0
#define GR_B_OFF  13312
#define GR_Q_OFF  26624
#define GR_V_OFF  35840
#define GR_STAGE  45056
#define GR_SMEM   (2 * GR_STAGE)
#define GR_NCHUNK 2048
__global__ __launch_bounds__(256, 2) void gram_mma()
{
    extern __shared__ char sm[];
    const int tid = threadIdx.x, wid = tid >> 5, lane = tid & 31;
    const int b = blockIdx.y;
    const int warpM = wid & 3, warpN = wid >> 2;

    const uint32_t smem_base = smem_to_u32(sm);
    const float* qsrc = g_qv + (size_t)b * 128 * NPIX;
    const float* vsrc = qsrc + (size_t)64 * NPIX;

    auto prefetch = [&](int ci, int s) {
        int pbase = ci * 32;
        uint32_t qb = smem_base + s * GR_STAGE + GR_Q_OFF;
        uint32_t vb = smem_base + s * GR_STAGE + GR_V_OFF;
#pragma unroll
        for (int e = 0; e < 512; e += 256) {
            int u = e + tid;
            int ch = u >> 3, sl = u & 7;
            cp16(qb + ch * GR_XRB + sl * 16, qsrc + (size_t)ch * NPIX + pbase + sl * 4);
        }
#pragma unroll
        for (int e = 0; e < 512; e += 256) {
            int u = e + tid;
            int ch = u >> 3, sl = u & 7;
            cp16(vb + ch * GR_XRB + sl * 16, vsrc + (size_t)ch * NPIX + pbase + sl * 4);
        }
    };

    const int lrow = lane & 15;
    const int lkh  = (lane >> 4) * 8;

    float acc[4][4];
#pragma unroll
    for (int ni = 0; ni < 4; ++ni)
#pragma unroll
        for (int r = 0; r < 4; ++r) acc[ni][r] = 0.f;
    float ssq = 0.f, ssv = 0.f;

    const int cch = tid >> 2;
    const int ppr = (tid & 3) * 4;

    int ci = blockIdx.x;
    int s = 0;
    prefetch(ci, 0);
    CP_COMMIT();

    while (ci < GR_NCHUNK) {
        const int nci = ci + gridDim.x;
        const bool more = nci < GR_NCHUNK;
        if (more) { prefetch(nci, s ^ 1); CP_COMMIT(); CP_WAIT(1); }
        else      { CP_WAIT(0); }
        __syncthreads();

        // convert raw -> Aq / Bv (vectorized: 4x LDS.128 in, 6x STS.128 out)
        {
            const float* rq = (const float*)(sm + s * GR_STAGE + GR_Q_OFF) + cch * 36 + ppr * 2;
            const float* rv = (const float*)(sm + s * GR_STAGE + GR_V_OFF) + cch * 36 + ppr * 2;
            float4 qa = *(const float4*)rq, qb4 = *(const float4*)(rq + 4);
            float4 va = *(const float4*)rv, vb4 = *(const float4*)(rv + 4);
            float qq[8] = {qa.x, qa.y, qa.z, qa.w, qb4.x, qb4.y, qb4.z, qb4.w};
            float vv[8] = {va.x, va.y, va.z, va.w, vb4.x, vb4.y, vb4.z, vb4.w};
            uint32_t wq[12], wv[12];
#pragma unroll
            for (int pr = 0; pr < 4; ++pr) {
                float q0 = qq[2 * pr], q1 = qq[2 * pr + 1];
                float v0 = vv[2 * pr], v1 = vv[2 * pr + 1];
                ssq += q0 * q0 + q1 * q1;
                ssv += v0 * v0 + v1 * v1;
                float qh0 = __bfloat162float(__float2bfloat16(q0));
                float qh1 = __bfloat162float(__float2bfloat16(q1));
                float vh0 = __bfloat162float(__float2bfloat16(v0));
                float vh1 = __bfloat162float(__float2bfloat16(v1));
                float ql0 = q0 - qh0, ql1 = q1 - qh1;
                float vl0 = v0 - vh0, vl1 = v1 - vh1;
                wq[pr * 3 + 0] = bfpair(qh0, qh0);
                wq[pr * 3 + 1] = bfpair(ql0, qh1);
                wq[pr * 3 + 2] = bfpair(qh1, ql1);
                wv[pr * 3 + 0] = bfpair(vh0, vl0);
                wv[pr * 3 + 1] = bfpair(vh0, vh1);
                wv[pr * 3 + 2] = bfpair(vl1, vh1);
            }
            uint32_t* aq = (uint32_t*)(sm + s * GR_STAGE + GR_A_OFF + cch * GR_RB) + ppr * 3;
            uint32_t* bv = (uint32_t*)(sm + s * GR_STAGE + GR_B_OFF + cch * GR_RB) + ppr * 3;
#pragma unroll
            for (int i = 0; i < 3; ++i) {
                *(uint4*)(aq + i * 4) = make_uint4(wq[i*4], wq[i*4+1], wq[i*4+2], wq[i*4+3]);
                *(uint4*)(bv + i * 4) = make_uint4(wv[i*4], wv[i*4+1], wv[i*4+2], wv[i*4+3]);
            }
        }
        __syncthreads();

        uint32_t ab = smem_base + s * GR_STAGE + GR_A_OFF;
        uint32_t bb = smem_base + s * GR_STAGE + GR_B_OFF;
#pragma unroll
        for (int ks = 0; ks < 6; ++ks) {
            uint32_t a[4];
            {
                uint32_t addr = ab + (warpM * 16 + lrow) * GR_RB + ks * 32 + lkh * 2;
                ldsm_x4(a[0], a[1], a[2], a[3], addr);
            }
            uint32_t bf[4][2];
#pragma unroll
            for (int nq = 0; nq < 2; ++nq) {
                uint32_t r0, r1, r2, r3;
                uint32_t addr = bb + (warpN * 32 + nq * 16 + lrow) * GR_RB + ks * 32 + lkh * 2;
                ldsm_x4(r0, r1, r2, r3, addr);
                bf[2 * nq][0] = r0;     bf[2 * nq][1] = r2;
                bf[2 * nq + 1][0] = r1; bf[2 * nq + 1][1] = r3;
            }
#pragma unroll
            for (int ni = 0; ni < 4; ++ni)
                mma_bf16(acc[ni], a, bf[ni]);
        }
        __syncthreads();
        ci = nci;
        s ^= 1;
    }

    atomicAdd(&g_sumsq[b * 128 + cch], ssq);
    atomicAdd(&g_sumsq[b * 128 + 64 + cch], ssv);

    const int g = lane >> 2, T = lane & 3;
    float* Gb = g_gram + b * 4096;
#pragma unroll
    for (int ni = 0; ni < 4; ++ni) {
        int n = warpN * 32 + ni * 8 + T * 2;
        int m = warpM * 16 + g;
        atomicAdd(&Gb[m * 64 + n],           acc[ni][0]);
        atomicAdd(&Gb[m * 64 + n + 1],       acc[ni][1]);
        atomicAdd(&Gb[(m + 8) * 64 + n],     acc[ni][2]);
        atomicAdd(&Gb[(m + 8) * 64 + n + 1], acc[ni][3]);
    }
}

// ---------------- norms + softmax + M = w_out @ attn (writes split M) --------
__global__ __launch_bounds__(256) void attn_kernel(
    const float* __restrict__ w_out, const float* __restrict__ temp_p)
{
    __shared__ float attn_s[64 * 65];
    __shared__ float wo_s[64 * 65];
    __shared__ float nrm[128];
    const int tid = threadIdx.x, b = blockIdx.x;

    if (tid < 128) nrm[tid] = fmaxf(sqrtf(g_sumsq[b * 128 + tid]), 1e-12f);
    for (int e = tid; e < 4096; e += 256) {
        int o = e >> 6, c = e & 63;
        wo_s[c * 65 + o] = w_out[e];
    }
    __syncthreads();

    const float temp = *temp_p;
    if (tid < 64) {
        int c = tid;
        float inq = temp / nrm[c];
        float mx = -1e30f;
        for (int d = 0; d < 64; ++d) {
            float l = g_gram[b * 4096 + c * 64 + d] * (inq / nrm[64 + d]);
            attn_s[c * 65 + d] = l;
            mx = fmaxf(mx, l);
        }
        float sum = 0.f;
        for (int d = 0; d < 64; ++d) {
            float e_ = expf(attn_s[c * 65 + d] - mx);
            attn_s[c * 65 + d] = e_;
            sum += e_;
        }
        float inv = 1.f / sum;
        for (int d = 0; d < 64; ++d) attn_s[c * 65 + d] *= inv;
    }
    __syncthreads();

    const int o = tid & 63, dg = tid >> 6;
    for (int d = dg * 16; d < dg * 16 + 16; ++d) {
        float m = 0.f;
#pragma unroll 8
        for (int c2 = 0; c2 < 64; ++c2) m += wo_s[c2 * 65 + o] * attn_s[c2 * 65 + d];
        __nv_bfloat16 hi = __float2bfloat16(m);
        __nv_bfloat16 lo = __float2bfloat16(m - __bfloat162float(hi));
        __nv_bfloat16* dst = g_M2 + ((size_t)b * 64 + o) * 192 + 3 * d;
        dst[0] = hi; dst[1] = hi; dst[2] = lo;
    }
}

// ---------------- tensor-core gemm2: out = M @ v (vectorized convert) --------
#define G2_A_RB   400
#define G2_A_ARR  (64 * G2_A_RB)
#define G2_B_RB   112
#define G2_B_ARR  (128 * G2_B_RB)
#define G2_X_RB   528
#define G2_X_ARR  (16 * G2_X_RB)
#define G2_STAGE  (G2_B_ARR + G2_X_ARR)
#define G2_SMEM   (G2_A_ARR + 2 * G2_STAGE)
__global__ __launch_bounds__(256, 2) void gemm2_mma(float* __restrict__ out)
{
    extern __shared__ char sm[];
    const int tid = threadIdx.x, wid = tid >> 5, lane = tid & 31;
    const int pbase = blockIdx.x * 128;
    const int b = blockIdx.y;
    const int warpM = wid & 1, warpN = wid >> 1;

    const uint32_t smem_base = smem_to_u32(sm);
    const char*  Agl = (const char*)(g_M2 + (size_t)b * 64 * 192);
    const float* vb  = g_qv + (size_t)b * 128 * NPIX + (size_t)64 * NPIX + pbase;

    auto b_base = [&](int s) { return smem_base + G2_A_ARR + s * G2_STAGE; };
    auto x_base = [&](int s) { return smem_base + G2_A_ARR + s * G2_STAGE + G2_B_ARR; };

#pragma unroll
    for (int e = 0; e < 1536; e += 256) {
        int u = e + tid;
        int r = u / 24, sl = u % 24;
        cp16(smem_base + r * G2_A_RB + sl * 16, Agl + r * 384 + sl * 16);
    }
    auto prefetch = [&](int chunk, int s) {
        uint32_t xbs = x_base(s);
#pragma unroll
        for (int e = 0; e < 512; e += 256) {
            int u = e + tid;
            int ch = u >> 5, sl = u & 31;
            cp16(xbs + ch * G2_X_RB + sl * 16,
                 vb + (size_t)(chunk * 16 + ch) * NPIX + sl * 4);
        }
    };
    prefetch(0, 0);
    CP_COMMIT();

    const int lrow = lane & 15;
    const int lkh  = (lane >> 4) * 8;
    const int cv_p = tid & 127;      // convert: pixel
    const int cv_g = tid >> 7;       // convert: channel-pair group (0..1), 4 cps each

    float acc[2][4][4];
#pragma unroll
    for (int mi = 0; mi < 2; ++mi)
#pragma unroll
        for (int ni = 0; ni < 4; ++ni)
#pragma unroll
            for (int r = 0; r < 4; ++r) acc[mi][ni][r] = 0.f;

#pragma unroll
    for (int c = 0; c < 4; ++c) {
        const int s = c & 1;
        if (c < 3) { prefetch(c + 1, s ^ 1); CP_COMMIT(); }
        if (c < 3) CP_WAIT(1); else CP_WAIT(0);
        __syncthreads();

        // convert raw v -> B slots (vectorized stores: 3x STS.128 per thread)
        {
            const float* xs = (const float*)(sm + G2_A_ARR + s * G2_STAGE + G2_B_ARR);
            char* Bs = sm + G2_A_ARR + s * G2_STAGE;
            uint32_t w[12];
#pragma unroll
            for (int i = 0; i < 4; ++i) {
                int cpi = cv_g * 4 + i;
                float x0 = xs[(2 * cpi) * 132 + cv_p];
                float x1 = xs[(2 * cpi + 1) * 132 + cv_p];
                float h0 = __bfloat162float(__float2bfloat16(x0));
                float h1 = __bfloat162float(__float2bfloat16(x1));
                float l0 = x0 - h0, l1 = x1 - h1;
                w[i * 3 + 0] = bfpair(h0, l0);
                w[i * 3 + 1] = bfpair(h0, h1);
                w[i * 3 + 2] = bfpair(l1, h1);
            }
            uint32_t* brow = (uint32_t*)(Bs + cv_p * G2_B_RB) + cv_g * 12;
#pragma unroll
            for (int i = 0; i < 3; ++i)
                *(uint4*)(brow + i * 4) = make_uint4(w[i*4], w[i*4+1], w[i*4+2], w[i*4+3]);
        }
        __syncthreads();

        uint32_t bb = b_base(s);
#pragma unroll
        for (int ksl = 0; ksl < 3; ++ksl) {
            uint32_t a[2][4];
#pragma unroll
            for (int mi = 0; mi < 2; ++mi) {
                uint32_t addr = smem_base + (warpM * 32 + mi * 16 + lrow) * G2_A_RB
                              + c * 96 + ksl * 32 + lkh * 2;
                ldsm_x4(a[mi][0], a[mi][1], a[mi][2], a[mi][3], addr);
            }
            uint32_t bf[4][2];
#pragma unroll
            for (int nq = 0; nq < 2; ++nq) {
                uint32_t r0, r1, r2, r3;
                uint32_t addr = bb + (warpN * 32 + nq * 16 + lrow) * G2_B_RB + ksl * 32 + lkh * 2;
                ldsm_x4(r0, r1, r2, r3, addr);
                bf[2 * nq][0] = r0;     bf[2 * nq][1] = r2;
                bf[2 * nq + 1][0] = r1; bf[2 * nq + 1][1] = r3;
            }
#pragma unroll
            for (int mi = 0; mi < 2; ++mi)
#pragma unroll
                for (int ni = 0; ni < 4; ++ni)
                    mma_bf16(acc[mi][ni], a[mi], bf[ni]);
        }
        __syncthreads();
    }

    const int g = lane >> 2, T = lane & 3;
#pragma unroll
    for (int mi = 0; mi < 2; ++mi) {
        int o = warpM * 32 + mi * 16 + g;
        float* rowp = out + ((size_t)b * 64 + o) * NPIX + pbase + warpN * 32 + T * 2;
#pragma unroll
        for (int ni = 0; ni < 4; ++ni) {
            *(u64*)(rowp + ni * 8) = pack2(acc[mi][ni][0], acc[mi][ni][1]);
            *(u64*)(rowp + ni * 8 + (size_t)8 * NPIX) = pack2(acc[mi][ni][2], acc[mi][ni][3]);
        }
    }
}

// ---------------- launch ------------------------------------------------------
extern "C" void kernel_launch(void* const* d_in, const int* in_sizes, int n_in,
                              void* d_out, int out_size)
{
    const float* x      = (const float*)d_in[0];
    const float* w_in   = (const float*)d_in[1];
    const float* w_dw   = (const float*)d_in[2];
    const float* w_out  = (const float*)d_in[3];
    const float* temp   = (const float*)d_in[4];
    float* out = (float*)d_out;

    cudaFuncSetAttribute(gemm1_res, cudaFuncAttributeMaxDynamicSharedMemorySize, GA_SMEM);
    cudaFuncSetAttribute(gram_mma,  cudaFuncAttributeMaxDynamicSharedMemorySize, GR_SMEM);
    cudaFuncSetAttribute(gemm2_mma, cudaFuncAttributeMaxDynamicSharedMemorySize, G2_SMEM);

    // weight split + stat zeroing (merged)
    wsplit<<<64, 256>>>(w_in);

    // t = w_in @ x  (tensor cores, A-resident, fused bf16-split)
    gemm1_res<<<dim3(GA_GRIDX, 1, BATCH), 512, GA_SMEM>>>(x);

    // depthwise conv + gate -> qv (float4)
    conv_mul<<<dim3(8, 128, BATCH), 256>>>(w_dw);

    // gram + sumsq (tensor cores, grid-stride, vectorized convert)
    gram_mma<<<dim3(148, BATCH), 256, GR_SMEM>>>();

    // norms, softmax, M = w_out @ attn (+ bf16-split M)
    attn_kernel<<<BATCH, 256>>>(w_out, temp);

    // out = M @ v (tensor cores, fused split, vectorized convert)
    gemm2_mma<<<dim3(NPIX / 128, BATCH), 256, G2_SMEM>>>(out);
}

// round 14
// speedup vs baseline: 1.8833x; 1.0085x over previous
#include <cuda_runtime.h>
#include <cuda_bf16.h>
#include <math.h>
#include <stdint.h>

typedef unsigned long long u64;

#define NPIX  65536   // 256*256
#define BATCH 4

// ---------------- scratch (device globals: allocation is forbidden) -----------
__device__ float g_t[(size_t)BATCH * 256 * NPIX];     // 256 MB : t = w_in @ x
__device__ float g_qv[(size_t)BATCH * 128 * NPIX];    // 128 MB : q, v
__device__ __nv_bfloat16 g_a2[256 * 192];             // bf16-split w_in, [o][192]
__device__ __nv_bfloat16 g_M2[BATCH * 64 * 192];      // bf16-split M = w_out@attn
__device__ float g_sumsq[BATCH * 128];
__device__ float g_gram[BATCH * 64 * 64];

// ---------------- helpers -----------------------------------------------------
__device__ __forceinline__ u64 pack2(float x, float y) {
    u64 d;
    asm("mov.b64 %0, {%1, %2};" : "=l"(d) : "f"(x), "f"(y));
    return d;
}
__device__ __forceinline__ uint32_t smem_to_u32(const void* p) {
    uint32_t a;
    asm("{ .reg .u64 t; cvta.to.shared.u64 t, %1; cvt.u32.u64 %0, t; }" : "=r"(a) : "l"(p));
    return a;
}
__device__ __forceinline__ void ldsm_x4(uint32_t& r0, uint32_t& r1, uint32_t& r2, uint32_t& r3,
                                        uint32_t addr) {
    asm volatile("ldmatrix.sync.aligned.m8n8.x4.shared.b16 {%0,%1,%2,%3}, [%4];"
        : "=r"(r0), "=r"(r1), "=r"(r2), "=r"(r3) : "r"(addr));
}
__device__ __forceinline__ void mma_bf16(float* d, const uint32_t* a, const uint32_t* b) {
    asm volatile("mma.sync.aligned.m16n8k16.row.col.f32.bf16.bf16.f32 "
        "{%0,%1,%2,%3}, {%4,%5,%6,%7}, {%8,%9}, {%0,%1,%2,%3};"
        : "+f"(d[0]), "+f"(d[1]), "+f"(d[2]), "+f"(d[3])
        : "r"(a[0]), "r"(a[1]), "r"(a[2]), "r"(a[3]), "r"(b[0]), "r"(b[1]));
}
__device__ __forceinline__ void cp16(uint32_t smem_addr, const void* gptr) {
    asm volatile("cp.async.cg.shared.global [%0], [%1], 16;" :: "r"(smem_addr), "l"(gptr));
}
#define CP_COMMIT() asm volatile("cp.async.commit_group;" ::: "memory")
#define CP_WAIT(n)  asm volatile("cp.async.wait_group %0;" :: "n"(n) : "memory")

__device__ __forceinline__ unsigned short bfbits(float v) {
    __nv_bfloat16 h = __float2bfloat16(v);
    return *(unsigned short*)&h;
}
__device__ __forceinline__ uint32_t bfpair(float a, float b) {
    return (uint32_t)bfbits(a) | ((uint32_t)bfbits(b) << 16);
}

// ---------------- weight split + zero stats (merged) --------------------------
__global__ void wsplit(const float* __restrict__ w_in) {
    const int gi = threadIdx.x + blockIdx.x * blockDim.x;
    const int gs = blockDim.x * gridDim.x;
    for (int i = gi; i < 256 * 192; i += gs) {
        int o = i / 192, k = i % 192;
        int c = k / 3, j = k % 3;
        float w = w_in[o * 64 + c];
        __nv_bfloat16 hi = __float2bfloat16(w);
        if (j == 2) g_a2[i] = __float2bfloat16(w - __bfloat162float(hi));
        else        g_a2[i] = hi;
    }
    for (int i = gi; i < BATCH * 128 + BATCH * 64 * 64; i += gs) {
        if (i < BATCH * 128) g_sumsq[i] = 0.f;
        else                 g_gram[i - BATCH * 128] = 0.f;
    }
}

// ---------------- A-resident tensor-core gemm1 (single B, 3-stage X ring) ----
#define GA_RB     400
#define GA_A_ARR  (256 * GA_RB)
#define GA_B_ARR  (64 * GA_RB)
#define GA_X_RB   272
#define GA_X_ARR  (64 * GA_X_RB)
#define GA_B_OFF  GA_A_ARR
#define GA_X_OFF  (GA_A_ARR + GA_B_ARR)
#define GA_SMEM   (GA_A_ARR + GA_B_ARR + 3 * GA_X_ARR)   // 180224
#define GA_NTILE  1024
#define GA_GRIDX  37
__global__ __launch_bounds__(512, 1) void gemm1_res(const float* __restrict__ x) {
    extern __shared__ char sm[];
    const int tid = threadIdx.x, wid = tid >> 5, lane = tid & 31;
    const int b = blockIdx.z;
    const int wm = wid & 7, wn = wid >> 3;

    const uint32_t smem_base = smem_to_u32(sm);
    const char*  Agl = (const char*)g_a2;
    const float* xb  = x + (size_t)b * 64 * NPIX;

#pragma unroll
    for (int e = 0; e < 6144; e += 512) {
        int u = e + tid;
        int r = u / 24, sl = u % 24;
        cp16(smem_base + r * GA_RB + sl * 16, Agl + r * 384 + sl * 16);
    }

    auto prefetch_x = [&](int t, int s) {
        uint32_t xbs = smem_base + GA_X_OFF + s * GA_X_ARR;
        const float* src = xb + t * 64;
#pragma unroll
        for (int e = 0; e < 1024; e += 512) {
            int u = e + tid;
            int ch = u >> 4, sl = u & 15;
            cp16(xbs + ch * GA_X_RB + sl * 16, src + (size_t)ch * NPIX + sl * 4);
        }
    };

    const int lrow = lane & 15;
    const int lkh  = (lane >> 4) * 8;
    const int g = lane >> 2, T = lane & 3;
    const int cp_p  = tid & 63;
    const int cp_g  = tid >> 6;

    int t = blockIdx.x;
    int si = 0;
    prefetch_x(t, 0);
    CP_COMMIT();
    if (t + GA_GRIDX < GA_NTILE) { prefetch_x(t + GA_GRIDX, 1); CP_COMMIT(); }

    while (t < GA_NTILE) {
        const int nt = t + GA_GRIDX;
        const int t2 = t + 2 * GA_GRIDX;
        if (nt < GA_NTILE) CP_WAIT(1); else CP_WAIT(0);
        __syncthreads();

        // convert raw x[si] -> B (single buffer; loop-top sync protects reuse)
        {
            const float* xs = (const float*)(sm + GA_X_OFF + si * GA_X_ARR);
            uint32_t* brow = (uint32_t*)(sm + GA_B_OFF + cp_p * GA_RB) + cp_g * 12;
            uint32_t w[12];
#pragma unroll
            for (int i = 0; i < 4; ++i) {
                int cpi = cp_g * 4 + i;
                float x0 = xs[(2 * cpi) * 68 + cp_p];
                float x1 = xs[(2 * cpi + 1) * 68 + cp_p];
                float h0 = __bfloat162float(__float2bfloat16(x0));
                float h1 = __bfloat162float(__float2bfloat16(x1));
                float l0 = x0 - h0, l1 = x1 - h1;
                w[i * 3 + 0] = bfpair(h0, l0);
                w[i * 3 + 1] = bfpair(h0, h1);
                w[i * 3 + 2] = bfpair(l1, h1);
            }
#pragma unroll
            for (int i = 0; i < 3; ++i)
                *(uint4*)(brow + i * 4) = make_uint4(w[i*4], w[i*4+1], w[i*4+2], w[i*4+3]);
        }
        __syncthreads();

        if (t2 < GA_NTILE) {
            int s2 = si + 2; if (s2 >= 3) s2 -= 3;
            prefetch_x(t2, s2); CP_COMMIT();
        }

        float acc[2][4][4];
#pragma unroll
        for (int mi = 0; mi < 2; ++mi)
#pragma unroll
            for (int ni = 0; ni < 4; ++ni)
#pragma unroll
                for (int r = 0; r < 4; ++r) acc[mi][ni][r] = 0.f;

        uint32_t bb = smem_base + GA_B_OFF;
#pragma unroll
        for (int ks = 0; ks < 12; ++ks) {
            uint32_t a[2][4];
#pragma unroll
            for (int mi = 0; mi < 2; ++mi) {
                uint32_t addr = smem_base + (wm * 32 + mi * 16 + lrow) * GA_RB + ks * 32 + lkh * 2;
                ldsm_x4(a[mi][0], a[mi][1], a[mi][2], a[mi][3], addr);
            }
            uint32_t bf[4][2];
#pragma unroll
            for (int nq = 0; nq < 2; ++nq) {
                uint32_t r0, r1, r2, r3;
                uint32_t addr = bb + (wn * 32 + nq * 16 + lrow) * GA_RB + ks * 32 + lkh * 2;
                ldsm_x4(r0, r1, r2, r3, addr);
                bf[2 * nq][0] = r0;     bf[2 * nq][1] = r2;
                bf[2 * nq + 1][0] = r1; bf[2 * nq + 1][1] = r3;
            }
#pragma unroll
            for (int mi = 0; mi < 2; ++mi)
#pragma unroll
                for (int ni = 0; ni < 4; ++ni)
                    mma_bf16(acc[mi][ni], a[mi], bf[ni]);
        }

#pragma unroll
        for (int mi = 0; mi < 2; ++mi) {
            int m = wm * 32 + mi * 16 + g;
            float* rowp = g_t + ((size_t)b * 256 + m) * NPIX + t * 64 + wn * 32 + T * 2;
#pragma unroll
            for (int ni = 0; ni < 4; ++ni) {
                *(u64*)(rowp + ni * 8) = pack2(acc[mi][ni][0], acc[mi][ni][1]);
                *(u64*)(rowp + ni * 8 + (size_t)8 * NPIX) = pack2(acc[mi][ni][2], acc[mi][ni][3]);
            }
        }
        t = nt;
        si = si + 1; if (si >= 3) si = 0;
    }
}

// ---------------- depthwise 3x3 conv + gate, float4 (round-9 exact) ----------
__global__ __launch_bounds__(256) void conv_mul(const float* __restrict__ w_dw)
{
    __shared__ float st[34][264];
    const int tid = threadIdx.x;
    const int jj = blockIdx.y, b = blockIdx.z, r0 = blockIdx.x * 32;

    const float* t1 = g_t + ((size_t)b * 256 + jj) * NPIX;
    const float* t2 = g_t + ((size_t)b * 256 + 128 + jj) * NPIX;
    float* outp = g_qv + ((size_t)b * 128 + jj) * NPIX;

    float wd[9];
#pragma unroll
    for (int i = 0; i < 9; ++i) wd[i] = w_dw[jj * 9 + i];

#pragma unroll
    for (int e = 0; e < 2176; e += 256) {
        int u = e + tid;
        if (u < 2176) {
            int rr = u >> 6, q4 = u & 63;
            int row = r0 - 1 + rr;
            float4 v = make_float4(0.f, 0.f, 0.f, 0.f);
            if (row >= 0 && row < 256)
                v = *(const float4*)(t1 + row * 256 + q4 * 4);
            *(float4*)&st[rr][4 + q4 * 4] = v;
        }
    }
    if (tid < 34) { st[tid][3] = 0.f; st[tid][260] = 0.f; }
    __syncthreads();

    const int ty = tid >> 6, tc = tid & 63;
    const int c0 = tc * 4;
#pragma unroll
    for (int r = ty * 8; r < ty * 8 + 8; ++r) {
        float s0 = 0.f, s1 = 0.f, s2 = 0.f, s3 = 0.f;
#pragma unroll
        for (int ky = 0; ky < 3; ++ky) {
            const float* rowp = &st[r + ky][4 + c0];
            float4 m = *(const float4*)rowp;
            float left = rowp[-1], right = rowp[4];
            float w0 = wd[ky * 3 + 0], w1 = wd[ky * 3 + 1], w2 = wd[ky * 3 + 2];
            s0 += w0 * left + w1 * m.x + w2 * m.y;
            s1 += w0 * m.x  + w1 * m.y + w2 * m.z;
            s2 += w0 * m.y  + w1 * m.z + w2 * m.w;
            s3 += w0 * m.z  + w1 * m.w + w2 * right;
        }
        int p = (r0 + r) * 256 + c0;
        float4 g4 = *(const float4*)(t2 + p);
        float4 o = make_float4(s0 * g4.x, s1 * g4.y, s2 * g4.z, s3 * g4.w);
        *(float4*)(outp + p) = o;
    }
}

// ---------------- tensor-core gram + sumsq (K-split warps) --------------------
// 8 warps = 2(m:32) x 2(n:32) x 2(k-half: 3 of 6 ksteps). ldsm/chunk 144->96.
// K-halves combined via smem reduction at end (atomics unchanged).
#define GR_RB     208
#define GR_XRB    144
#define GR_A_OFF  0
#define GR_B_OFF  13312
#define GR_Q_OFF  26624
#define GR_V_OFF  35840
#define GR_STAGE  45056
#define GR_SMEM   (2 * GR_STAGE)
#define GR_NCHUNK 2048
__global__ __launch_bounds__(256, 2) void gram_mma()
{
    extern __shared__ char sm[];
    const int tid = threadIdx.x, wid = tid >> 5, lane = tid & 31;
    const int b = blockIdx.y;
    const int wk = wid >> 2;               // k-half
    const int warpM = wid & 1, warpN = (wid >> 1) & 1;

    const uint32_t smem_base = smem_to_u32(sm);
    const float* qsrc = g_qv + (size_t)b * 128 * NPIX;
    const float* vsrc = qsrc + (size_t)64 * NPIX;

    auto prefetch = [&](int ci, int s) {
        int pbase = ci * 32;
        uint32_t qb = smem_base + s * GR_STAGE + GR_Q_OFF;
        uint32_t vb = smem_base + s * GR_STAGE + GR_V_OFF;
#pragma unroll
        for (int e = 0; e < 512; e += 256) {
            int u = e + tid;
            int ch = u >> 3, sl = u & 7;
            cp16(qb + ch * GR_XRB + sl * 16, qsrc + (size_t)ch * NPIX + pbase + sl * 4);
        }
#pragma unroll
        for (int e = 0; e < 512; e += 256) {
            int u = e + tid;
            int ch = u >> 3, sl = u & 7;
            cp16(vb + ch * GR_XRB + sl * 16, vsrc + (size_t)ch * NPIX + pbase + sl * 4);
        }
    };

    const int lrow = lane & 15;
    const int lkh  = (lane >> 4) * 8;

    float acc[2][4][4];
#pragma unroll
    for (int mi = 0; mi < 2; ++mi)
#pragma unroll
        for (int ni = 0; ni < 4; ++ni)
#pragma unroll
            for (int r = 0; r < 4; ++r) acc[mi][ni][r] = 0.f;
    float ssq = 0.f, ssv = 0.f;

    const int cch = tid >> 2;
    const int ppr = (tid & 3) * 4;

    int ci = blockIdx.x;
    int s = 0;
    prefetch(ci, 0);
    CP_COMMIT();

    while (ci < GR_NCHUNK) {
        const int nci = ci + gridDim.x;
        const bool more = nci < GR_NCHUNK;
        if (more) { prefetch(nci, s ^ 1); CP_COMMIT(); CP_WAIT(1); }
        else      { CP_WAIT(0); }
        __syncthreads();

        // convert raw -> Aq / Bv (vectorized)
        {
            const float* rq = (const float*)(sm + s * GR_STAGE + GR_Q_OFF) + cch * 36 + ppr * 2;
            const float* rv = (const float*)(sm + s * GR_STAGE + GR_V_OFF) + cch * 36 + ppr * 2;
            float4 qa = *(const float4*)rq, qb4 = *(const float4*)(rq + 4);
            float4 va = *(const float4*)rv, vb4 = *(const float4*)(rv + 4);
            float qq[8] = {qa.x, qa.y, qa.z, qa.w, qb4.x, qb4.y, qb4.z, qb4.w};
            float vv[8] = {va.x, va.y, va.z, va.w, vb4.x, vb4.y, vb4.z, vb4.w};
            uint32_t wq[12], wv[12];
#pragma unroll
            for (int pr = 0; pr < 4; ++pr) {
                float q0 = qq[2 * pr], q1 = qq[2 * pr + 1];
                float v0 = vv[2 * pr], v1 = vv[2 * pr + 1];
                ssq += q0 * q0 + q1 * q1;
                ssv += v0 * v0 + v1 * v1;
                float qh0 = __bfloat162float(__float2bfloat16(q0));
                float qh1 = __bfloat162float(__float2bfloat16(q1));
                float vh0 = __bfloat162float(__float2bfloat16(v0));
                float vh1 = __bfloat162float(__float2bfloat16(v1));
                float ql0 = q0 - qh0, ql1 = q1 - qh1;
                float vl0 = v0 - vh0, vl1 = v1 - vh1;
                wq[pr * 3 + 0] = bfpair(qh0, qh0);
                wq[pr * 3 + 1] = bfpair(ql0, qh1);
                wq[pr * 3 + 2] = bfpair(qh1, ql1);
                wv[pr * 3 + 0] = bfpair(vh0, vl0);
                wv[pr * 3 + 1] = bfpair(vh0, vh1);
                wv[pr * 3 + 2] = bfpair(vl1, vh1);
            }
            uint32_t* aq = (uint32_t*)(sm + s * GR_STAGE + GR_A_OFF + cch * GR_RB) + ppr * 3;
            uint32_t* bv = (uint32_t*)(sm + s * GR_STAGE + GR_B_OFF + cch * GR_RB) + ppr * 3;
#pragma unroll
            for (int i = 0; i < 3; ++i) {
                *(uint4*)(aq + i * 4) = make_uint4(wq[i*4], wq[i*4+1], wq[i*4+2], wq[i*4+3]);
                *(uint4*)(bv + i * 4) = make_uint4(wv[i*4], wv[i*4+1], wv[i*4+2], wv[i*4+3]);
            }
        }
        __syncthreads();

        uint32_t ab = smem_base + s * GR_STAGE + GR_A_OFF;
        uint32_t bb = smem_base + s * GR_STAGE + GR_B_OFF;
#pragma unroll
        for (int ks3 = 0; ks3 < 3; ++ks3) {
            const int ks = wk * 3 + ks3;
            uint32_t a[2][4];
#pragma unroll
            for (int mi = 0; mi < 2; ++mi) {
                uint32_t addr = ab + (warpM * 32 + mi * 16 + lrow) * GR_RB + ks * 32 + lkh * 2;
                ldsm_x4(a[mi][0], a[mi][1], a[mi][2], a[mi][3], addr);
            }
            uint32_t bf[4][2];
#pragma unroll
            for (int nq = 0; nq < 2; ++nq) {
                uint32_t r0, r1, r2, r3;
                uint32_t addr = bb + (warpN * 32 + nq * 16 + lrow) * GR_RB + ks * 32 + lkh * 2;
                ldsm_x4(r0, r1, r2, r3, addr);
                bf[2 * nq][0] = r0;     bf[2 * nq][1] = r2;
                bf[2 * nq + 1][0] = r1; bf[2 * nq + 1][1] = r3;
            }
#pragma unroll
            for (int mi = 0; mi < 2; ++mi)
#pragma unroll
                for (int ni = 0; ni < 4; ++ni)
                    mma_bf16(acc[mi][ni], a[mi], bf[ni]);
        }
        __syncthreads();
        ci = nci;
        s ^= 1;
    }

    atomicAdd(&g_sumsq[b * 128 + cch], ssq);
    atomicAdd(&g_sumsq[b * 128 + 64 + cch], ssv);

    // combine k-halves via smem (stage area is free now), then atomics
    __syncthreads();
    float* red = (float*)sm + (warpM * 2 + warpN) * 1024;
    if (wk == 1) {
#pragma unroll
        for (int mi = 0; mi < 2; ++mi)
#pragma unroll
            for (int ni = 0; ni < 4; ++ni)
#pragma unroll
                for (int r = 0; r < 4; ++r)
                    red[(mi * 16 + ni * 4 + r) * 32 + lane] = acc[mi][ni][r];
    }
    __syncthreads();
    if (wk == 0) {
        const int g = lane >> 2, T = lane & 3;
        float* Gb = g_gram + b * 4096;
#pragma unroll
        for (int mi = 0; mi < 2; ++mi)
#pragma unroll
            for (int ni = 0; ni < 4; ++ni) {
                float r0 = acc[mi][ni][0] + red[(mi * 16 + ni * 4 + 0) * 32 + lane];
                float r1 = acc[mi][ni][1] + red[(mi * 16 + ni * 4 + 1) * 32 + lane];
                float r2 = acc[mi][ni][2] + red[(mi * 16 + ni * 4 + 2) * 32 + lane];
                float r3 = acc[mi][ni][3] + red[(mi * 16 + ni * 4 + 3) * 32 + lane];
                int m = warpM * 32 + mi * 16 + g;
                int n = warpN * 32 + ni * 8 + T * 2;
                atomicAdd(&Gb[m * 64 + n],           r0);
                atomicAdd(&Gb[m * 64 + n + 1],       r1);
                atomicAdd(&Gb[(m + 8) * 64 + n],     r2);
                atomicAdd(&Gb[(m + 8) * 64 + n + 1], r3);
            }
    }
}

// ---------------- norms + softmax + M = w_out @ attn (writes split M) --------
__global__ __launch_bounds__(256) void attn_kernel(
    const float* __restrict__ w_out, const float* __restrict__ temp_p)
{
    __shared__ float attn_s[64 * 65];
    __shared__ float wo_s[64 * 65];
    __shared__ float nrm[128];
    const int tid = threadIdx.x, b = blockIdx.x;

    if (tid < 128) nrm[tid] = fmaxf(sqrtf(g_sumsq[b * 128 + tid]), 1e-12f);
    for (int e = tid; e < 4096; e += 256) {
        int o = e >> 6, c = e & 63;
        wo_s[c * 65 + o] = w_out[e];
    }
    __syncthreads();

    const float temp = *temp_p;
    if (tid < 64) {
        int c = tid;
        float inq = temp / nrm[c];
        float mx = -1e30f;
        for (int d = 0; d < 64; ++d) {
            float l = g_gram[b * 4096 + c * 64 + d] * (inq / nrm[64 + d]);
            attn_s[c * 65 + d] = l;
            mx = fmaxf(mx, l);
        }
        float sum = 0.f;
        for (int d = 0; d < 64; ++d) {
            float e_ = expf(attn_s[c * 65 + d] - mx);
            attn_s[c * 65 + d] = e_;
            sum += e_;
        }
        float inv = 1.f / sum;
        for (int d = 0; d < 64; ++d) attn_s[c * 65 + d] *= inv;
    }
    __syncthreads();

    const int o = tid & 63, dg = tid >> 6;
    for (int d = dg * 16; d < dg * 16 + 16; ++d) {
        float m = 0.f;
#pragma unroll 8
        for (int c2 = 0; c2 < 64; ++c2) m += wo_s[c2 * 65 + o] * attn_s[c2 * 65 + d];
        __nv_bfloat16 hi = __float2bfloat16(m);
        __nv_bfloat16 lo = __float2bfloat16(m - __bfloat162float(hi));
        __nv_bfloat16* dst = g_M2 + ((size_t)b * 64 + o) * 192 + 3 * d;
        dst[0] = hi; dst[1] = hi; dst[2] = lo;
    }
}

// ---------------- tensor-core gemm2: out = M @ v (round-13 exact) ------------
#define G2_A_RB   400
#define G2_A_ARR  (64 * G2_A_RB)
#define G2_B_RB   112
#define G2_B_ARR  (128 * G2_B_RB)
#define G2_X_RB   528
#define G2_X_ARR  (16 * G2_X_RB)
#define G2_STAGE  (G2_B_ARR + G2_X_ARR)
#define G2_SMEM   (G2_A_ARR + 2 * G2_STAGE)
__global__ __launch_bounds__(256, 2) void gemm2_mma(float* __restrict__ out)
{
    extern __shared__ char sm[];
    const int tid = threadIdx.x, wid = tid >> 5, lane = tid & 31;
    const int pbase = blockIdx.x * 128;
    const int b = blockIdx.y;
    const int warpM = wid & 1, warpN = wid >> 1;

    const uint32_t smem_base = smem_to_u32(sm);
    const char*  Agl = (const char*)(g_M2 + (size_t)b * 64 * 192);
    const float* vb  = g_qv + (size_t)b * 128 * NPIX + (size_t)64 * NPIX + pbase;

    auto b_base = [&](int s) { return smem_base + G2_A_ARR + s * G2_STAGE; };
    auto x_base = [&](int s) { return smem_base + G2_A_ARR + s * G2_STAGE + G2_B_ARR; };

#pragma unroll
    for (int e = 0; e < 1536; e += 256) {
        int u = e + tid;
        int r = u / 24, sl = u % 24;
        cp16(smem_base + r * G2_A_RB + sl * 16, Agl + r * 384 + sl * 16);
    }
    auto prefetch = [&](int chunk, int s) {
        uint32_t xbs = x_base(s);
#pragma unroll
        for (int e = 0; e < 512; e += 256) {
            int u = e + tid;
            int ch = u >> 5, sl = u & 31;
            cp16(xbs + ch * G2_X_RB + sl * 16,
                 vb + (size_t)(chunk * 16 + ch) * NPIX + sl * 4);
        }
    };
    prefetch(0, 0);
    CP_COMMIT();

    const int lrow = lane & 15;
    const int lkh  = (lane >> 4) * 8;
    const int cv_p = tid & 127;
    const int cv_g = tid >> 7;

    float acc[2][4][4];
#pragma unroll
    for (int mi = 0; mi < 2; ++mi)
#pragma unroll
        for (int ni = 0; ni < 4; ++ni)
#pragma unroll
            for (int r = 0; r < 4; ++r) acc[mi][ni][r] = 0.f;

#pragma unroll
    for (int c = 0; c < 4; ++c) {
        const int s = c & 1;
        if (c < 3) { prefetch(c + 1, s ^ 1); CP_COMMIT(); }
        if (c < 3) CP_WAIT(1); else CP_WAIT(0);
        __syncthreads();

        {
            const float* xs = (const float*)(sm + G2_A_ARR + s * G2_STAGE + G2_B_ARR);
            char* Bs = sm + G2_A_ARR + s * G2_STAGE;
            uint32_t w[12];
#pragma unroll
            for (int i = 0; i < 4; ++i) {
                int cpi = cv_g * 4 + i;
                float x0 = xs[(2 * cpi) * 132 + cv_p];
                float x1 = xs[(2 * cpi + 1) * 132 + cv_p];
                float h0 = __bfloat162float(__float2bfloat16(x0));
                float h1 = __bfloat162float(__float2bfloat16(x1));
                float l0 = x0 - h0, l1 = x1 - h1;
                w[i * 3 + 0] = bfpair(h0, l0);
                w[i * 3 + 1] = bfpair(h0, h1);
                w[i * 3 + 2] = bfpair(l1, h1);
            }
            uint32_t* brow = (uint32_t*)(Bs + cv_p * G2_B_RB) + cv_g * 12;
#pragma unroll
            for (int i = 0; i < 3; ++i)
                *(uint4*)(brow + i * 4) = make_uint4(w[i*4], w[i*4+1], w[i*4+2], w[i*4+3]);
        }
        __syncthreads();

        uint32_t bb = b_base(s);
#pragma unroll
        for (int ksl = 0; ksl < 3; ++ksl) {
            uint32_t a[2][4];
#pragma unroll
            for (int mi = 0; mi < 2; ++mi) {
                uint32_t addr = smem_base + (warpM * 32 + mi * 16 + lrow) * G2_A_RB
                              + c * 96 + ksl * 32 + lkh * 2;
                ldsm_x4(a[mi][0], a[mi][1], a[mi][2], a[mi][3], addr);
            }
            uint32_t bf[4][2];
#pragma unroll
            for (int nq = 0; nq < 2; ++nq) {
                uint32_t r0, r1, r2, r3;
                uint32_t addr = bb + (warpN * 32 + nq * 16 + lrow) * G2_B_RB + ksl * 32 + lkh * 2;
                ldsm_x4(r0, r1, r2, r3, addr);
                bf[2 * nq][0] = r0;     bf[2 * nq][1] = r2;
                bf[2 * nq + 1][0] = r1; bf[2 * nq + 1][1] = r3;
            }
#pragma unroll
            for (int mi = 0; mi < 2; ++mi)
#pragma unroll
                for (int ni = 0; ni < 4; ++ni)
                    mma_bf16(acc[mi][ni], a[mi], bf[ni]);
        }
        __syncthreads();
    }

    const int g = lane >> 2, T = lane & 3;
#pragma unroll
    for (int mi = 0; mi < 2; ++mi) {
        int o = warpM * 32 + mi * 16 + g;
        float* rowp = out + ((size_t)b * 64 + o) * NPIX + pbase + warpN * 32 + T * 2;
#pragma unroll
        for (int ni = 0; ni < 4; ++ni) {
            *(u64*)(rowp + ni * 8) = pack2(acc[mi][ni][0], acc[mi][ni][1]);
            *(u64*)(rowp + ni * 8 + (size_t)8 * NPIX) = pack2(acc[mi][ni][2], acc[mi][ni][3]);
        }
    }
}

// ---------------- launch ------------------------------------------------------
extern "C" void kernel_launch(void* const* d_in, const int* in_sizes, int n_in,
                              void* d_out, int out_size)
{
    const float* x      = (const float*)d_in[0];
    const float* w_in   = (const float*)d_in[1];
    const float* w_dw   = (const float*)d_in[2];
    const float* w_out  = (const float*)d_in[3];
    const float* temp   = (const float*)d_in[4];
    float* out = (float*)d_out;

    cudaFuncSetAttribute(gemm1_res, cudaFuncAttributeMaxDynamicSharedMemorySize, GA_SMEM);
    cudaFuncSetAttribute(gram_mma,  cudaFuncAttributeMaxDynamicSharedMemorySize, GR_SMEM);
    cudaFuncSetAttribute(gemm2_mma, cudaFuncAttributeMaxDynamicSharedMemorySize, G2_SMEM);

    // weight split + stat zeroing (merged)
    wsplit<<<64, 256>>>(w_in);

    // t = w_in @ x  (tensor cores, A-resident, 3-stage X ring)
    gemm1_res<<<dim3(GA_GRIDX, 1, BATCH), 512, GA_SMEM>>>(x);

    // depthwise conv + gate -> qv (float4)
    conv_mul<<<dim3(8, 128, BATCH), 256>>>(w_dw);

    // gram + sumsq (tensor cores, K-split warps)
    gram_mma<<<dim3(148, BATCH), 256, GR_SMEM>>>();

    // norms, softmax, M = w_out @ attn (+ bf16-split M)
    attn_kernel<<<BATCH, 256>>>(w_out, temp);

    // out = M @ v (tensor cores, fused split)
    gemm2_mma<<<dim3(NPIX / 128, BATCH), 256, G2_SMEM>>>(out);
}